// round 11
// baseline (speedup 1.0000x reference)
#include <cuda_runtime.h>
#include <cuda_bf16.h>
#include <math_constants.h>
#include <cstdint>

#define TT 2048
#define HH 2048
#define NHEAD 16
#define HD 128
#define D2 256

// ======================= scratch (static device globals) =======================
__device__ __nv_bfloat16 g_nr[TT*HH];
__device__ __nv_bfloat16 g_ni[TT*HH];
__device__ float g_invs1[TT];
__device__ float g_invs2[TT];
__device__ float g_invs3[TT];
__device__ float g_invs4[TT];
__device__ __nv_bfloat16 g_wsp[16][HH*HH];
__device__ float g_pqr[TT*HH];
__device__ float g_pqi[TT*HH];
__device__ float g_pkr[TT*HH];
__device__ float g_pki[TT*HH];
__device__ float g_pvr[TT*HH];
__device__ float g_pvi[TT*HH];
__device__ float g_ar[TT*HH];
__device__ float g_ai[TT*HH];
__device__ float g_cos[TT*HD];
__device__ float g_sin[TT*HD];
__device__ __nv_bfloat16 g_qhi[NHEAD*TT*D2];
__device__ __nv_bfloat16 g_qlo[NHEAD*TT*D2];
__device__ __nv_bfloat16 g_khi[NHEAD*TT*D2];
__device__ __nv_bfloat16 g_klo[NHEAD*TT*D2];
__device__ __nv_bfloat16 g_vhi[NHEAD*TT*D2];
__device__ __nv_bfloat16 g_vlo[NHEAD*TT*D2];

// ======================= helpers =======================
__device__ __forceinline__ uint32_t smem_u32(const void* p) {
    uint32_t a;
    asm("{ .reg .u64 t; cvta.to.shared.u64 t, %1; cvt.u32.u64 %0, t; }" : "=r"(a) : "l"(p));
    return a;
}
#define SWZ128(b) ((b) ^ (((b) >> 3) & 0x70))
#define SWZ512(b) ((b) ^ (((b) >> 5) & 0x70))

__device__ __forceinline__ uint32_t packbf(float a, float b) {
    __nv_bfloat162 t = __floats2bfloat162_rn(a, b);
    return *(uint32_t*)&t;
}

// ======================= prep kernels (merged launches) =======================
struct QuantArgs {
    const float* x[2];
    __nv_bfloat16* q[2];
    float* invs[2];
};

__global__ void rowquant_bf16_kernel(QuantArgs a) {
    __shared__ float red[256];
    int sel = blockIdx.y;
    int row = blockIdx.x;
    const float* xr = a.x[sel] + row * HH;
    float m = 0.f;
    for (int c = threadIdx.x; c < HH; c += 256) m = fmaxf(m, fabsf(xr[c]));
    red[threadIdx.x] = m;
    __syncthreads();
    for (int s = 128; s > 0; s >>= 1) {
        if (threadIdx.x < s) red[threadIdx.x] = fmaxf(red[threadIdx.x], red[threadIdx.x + s]);
        __syncthreads();
    }
    float scale = 127.0f / fmaxf(red[0], 1e-5f);
    if (threadIdx.x == 0) a.invs[sel][row] = 1.0f / scale;
    __nv_bfloat16* q = a.q[sel];
    for (int c = threadIdx.x; c < HH; c += 256) {
        float v = rintf(xr[c] * scale);
        v = fminf(fmaxf(v, -128.f), 127.f);
        q[row * HH + c] = __float2bfloat16_rn(v);
    }
}

struct SplitArgs { const float* w[8]; __nv_bfloat16* base; };

__global__ void split_kernel(SplitArgs a) {
    int wsel = blockIdx.y;
    int i = (blockIdx.x * 256 + threadIdx.x) * 4;
    float4 v = *(const float4*)(a.w[wsel] + i);
    __nv_bfloat16* hi = a.base + (size_t)(2 * wsel) * HH * HH;
    __nv_bfloat16* lo = a.base + (size_t)(2 * wsel + 1) * HH * HH;
    __nv_bfloat16 h[4], l[4];
    float vv[4] = {v.x, v.y, v.z, v.w};
#pragma unroll
    for (int j = 0; j < 4; j++) {
        h[j] = __float2bfloat16_rn(vv[j]);
        l[j] = __float2bfloat16_rn(vv[j] - __bfloat162float(h[j]));
    }
    *(uint64_t*)(hi + i) = *(uint64_t*)h;
    *(uint64_t*)(lo + i) = *(uint64_t*)l;
}

// fp32 chain — matches XLA's fp32-rounded angle + cos/sin (proven; do NOT "improve")
__global__ void cossin_kernel(const int* __restrict__ pos) {
    int idx = blockIdx.x * 256 + threadIdx.x;
    if (idx >= TT * HD) return;
    int t = idx / HD, d = idx % HD;
    float invf = 1.0f / powf(10000.0f, (float)d / (float)HD);
    float f = (float)pos[t] * invf;
    g_cos[idx] = __bfloat162float(__float2bfloat16(cosf(f)));
    g_sin[idx] = __bfloat162float(__float2bfloat16(sinf(f)));
}

struct RSArgs {
    const float* xr[3];
    const float* xi[3];
    __nv_bfloat16* ghi[3];
    __nv_bfloat16* glo[3];
    int dorope[3];
};

__global__ void ropesplit_kernel(RSArgs a) {
    int sel = blockIdx.y;
    int idx = blockIdx.x * 256 + threadIdx.x;
    int t = idx >> 11;
    int colh = idx & 2047;
    int h = colh >> 7, d = colh & 127;
    float r = a.xr[sel][idx], im = a.xi[sel][idx];
    if (a.dorope[sel]) {
        float c = g_cos[t * HD + d], s = g_sin[t * HD + d];
        float rr = r * c - im * s;
        float ii = im * c + r * s;
        r = rr; im = ii;
    }
    size_t base = ((size_t)h * TT + t) * D2;
    __nv_bfloat16 rh = __float2bfloat16_rn(r);
    a.ghi[sel][base + d] = rh;
    a.glo[sel][base + d] = __float2bfloat16_rn(r - __bfloat162float(rh));
    __nv_bfloat16 ih = __float2bfloat16_rn(im);
    a.ghi[sel][base + 128 + d] = ih;
    a.glo[sel][base + 128 + d] = __float2bfloat16_rn(im - __bfloat162float(ih));
}

// ======================= mma.sync dual GEMM — occ-2: CTA 128x128, 3-stage, 96KB smem =======================
// C = invs1[m]*(A1 @ (B1hi+B1lo)^T) + sign*invs2[m]*(A2 @ (B2hi+B2lo)^T)
// 8 warps (2m x 4n), warp tile 64x32. K chunks of 64. 2 CTAs/SM -> 4 warps/SMSP.
#define STAGES 3
#define NCHUNK 128
#define STG_A  16384        // A: 128 rows x 128B
#define STG_SZ 32768        // A 16KB + B 16KB
#define GSM    (STAGES * STG_SZ)   // 98304

__device__ __forceinline__ void load_chunk(uint32_t st,
                                           const __nv_bfloat16* Aseg,
                                           const __nv_bfloat16* Bseg,
                                           int m0, int n0, int kc, int tid) {
    const char* ag = (const char*)(Aseg + (size_t)m0 * HH + kc * 64);
    const char* bg = (const char*)(Bseg + (size_t)n0 * HH + kc * 64);
    uint32_t sa = st, sb = st + STG_A;
#pragma unroll
    for (int i = 0; i < 4; i++) {   // A: 128 rows x 8 x 16B
        int idx = tid + i * 256;
        int r = idx >> 3, g = idx & 7;
        uint32_t so = sa + SWZ128(r * 128 + g * 16);
        asm volatile("cp.async.cg.shared.global [%0], [%1], 16;"
                     :: "r"(so), "l"(ag + (size_t)r * 4096 + g * 16));
    }
#pragma unroll
    for (int i = 0; i < 4; i++) {   // B: 128 rows x 8 x 16B
        int idx = tid + i * 256;
        int r = idx >> 3, g = idx & 7;
        uint32_t so = sb + SWZ128(r * 128 + g * 16);
        asm volatile("cp.async.cg.shared.global [%0], [%1], 16;"
                     :: "r"(so), "l"(bg + (size_t)r * 4096 + g * 16));
    }
}

// one K=64 chunk, warp tile 64x32: per ks 4 A-ldm + 2 B-ldm + 16 MMA
__device__ __forceinline__ void compute_chunk(uint32_t st,
                                              int warp_m, int warp_n, int lane,
                                              float (&acc)[4][4][4]) {
    uint32_t sa = st, sb = st + STG_A;
#pragma unroll
    for (int ks = 0; ks < 4; ks++) {
        uint32_t af[4][4];
#pragma unroll
        for (int mi = 0; mi < 4; mi++) {
            int r = warp_m * 64 + mi * 16 + (lane & 15);
            int cb = ks * 32 + (lane >> 4) * 16;
            uint32_t ad = sa + SWZ128(r * 128 + cb);
            asm volatile("ldmatrix.sync.aligned.m8n8.x4.shared.b16 {%0,%1,%2,%3}, [%4];"
                : "=r"(af[mi][0]), "=r"(af[mi][1]), "=r"(af[mi][2]), "=r"(af[mi][3])
                : "r"(ad));
        }
        uint32_t bf[4][2];
#pragma unroll
        for (int p = 0; p < 2; p++) {
            int nr = warp_n * 32 + p * 16 + (lane & 7) + ((lane >> 4) << 3);
            int cb = ks * 32 + ((lane >> 3) & 1) * 16;
            uint32_t bd = sb + SWZ128(nr * 128 + cb);
            asm volatile("ldmatrix.sync.aligned.m8n8.x4.shared.b16 {%0,%1,%2,%3}, [%4];"
                : "=r"(bf[2*p][0]), "=r"(bf[2*p][1]), "=r"(bf[2*p+1][0]), "=r"(bf[2*p+1][1])
                : "r"(bd));
        }
#pragma unroll
        for (int mi = 0; mi < 4; mi++)
#pragma unroll
            for (int nj = 0; nj < 4; nj++)
                asm volatile(
                    "mma.sync.aligned.m16n8k16.row.col.f32.bf16.bf16.f32 "
                    "{%0,%1,%2,%3}, {%4,%5,%6,%7}, {%8,%9}, {%0,%1,%2,%3};"
                    : "+f"(acc[mi][nj][0]), "+f"(acc[mi][nj][1]),
                      "+f"(acc[mi][nj][2]), "+f"(acc[mi][nj][3])
                    : "r"(af[mi][0]), "r"(af[mi][1]), "r"(af[mi][2]), "r"(af[mi][3]),
                      "r"(bf[nj][0]), "r"(bf[nj][1]));
    }
}

__global__ __launch_bounds__(256, 2) void gemm_dual_mma(
    const __nv_bfloat16* __restrict__ A1, const __nv_bfloat16* __restrict__ A2,
    const __nv_bfloat16* __restrict__ B1hi, const __nv_bfloat16* __restrict__ B1lo,
    const __nv_bfloat16* __restrict__ B2hi, const __nv_bfloat16* __restrict__ B2lo,
    const float* __restrict__ invs1, const float* __restrict__ invs2,
    float sign, float* __restrict__ C) {
    extern __shared__ char smem[];
    uint32_t sbase = smem_u32(smem);
    int tid = threadIdx.x;
    int wid = tid >> 5, lane = tid & 31;
    int warp_m = wid >> 2, warp_n = wid & 3;
    int m0 = blockIdx.y * 128, n0 = blockIdx.x * 128;
    int tq = lane >> 2, tr = lane & 3;

    float acc[4][4][4];
#pragma unroll
    for (int a = 0; a < 4; a++)
#pragma unroll
        for (int b = 0; b < 4; b++)
#pragma unroll
            for (int c = 0; c < 4; c++) acc[a][b][c] = 0.f;

    for (int c = 0; c < STAGES; c++) {
        load_chunk(sbase + c * STG_SZ, A1, B1hi, m0, n0, c, tid);
        asm volatile("cp.async.commit_group;");
    }

    int stage = 0;
    for (int c = 0; c < NCHUNK; c++) {
        uint32_t st = sbase + stage * STG_SZ;
        int rem = NCHUNK - 1 - c;
        if (rem >= 2)      asm volatile("cp.async.wait_group 2;");
        else if (rem == 1) asm volatile("cp.async.wait_group 1;");
        else               asm volatile("cp.async.wait_group 0;");
        __syncthreads();

        compute_chunk(st, warp_m, warp_n, lane, acc);

        if (c == 63) {
            // acc holds A1@(B1hi+B1lo); rescale so epilogue scale is sign*invs2[row]
#pragma unroll
            for (int mi = 0; mi < 4; mi++)
#pragma unroll
                for (int h = 0; h < 2; h++) {
                    int row = m0 + warp_m * 64 + mi * 16 + tq + h * 8;
                    float ratio = sign * invs1[row] / invs2[row];
#pragma unroll
                    for (int nj = 0; nj < 4; nj++) {
                        acc[mi][nj][2*h]     *= ratio;
                        acc[mi][nj][2*h + 1] *= ratio;
                    }
                }
        }
        __syncthreads();

        int cn = c + STAGES;
        if (cn < NCHUNK) {
            int sel = cn >> 5;
            const __nv_bfloat16* Bseg = (sel == 0) ? B1hi : (sel == 1) ? B1lo
                                       : (sel == 2) ? B2hi : B2lo;
            const __nv_bfloat16* Aseg = (cn >= 64) ? A2 : A1;
            load_chunk(st, Aseg, Bseg, m0, n0, cn & 31, tid);
            asm volatile("cp.async.commit_group;");
        }
        stage = (stage == STAGES - 1) ? 0 : stage + 1;
    }

    // epilogue: C = sign*invs2[row] * acc
#pragma unroll
    for (int mi = 0; mi < 4; mi++) {
#pragma unroll
        for (int h = 0; h < 2; h++) {
            int row = m0 + warp_m * 64 + mi * 16 + tq + h * 8;
            float fs = sign * invs2[row];
            float* crow = C + (size_t)row * HH + n0 + warp_n * 32;
#pragma unroll
            for (int nj = 0; nj < 4; nj++) {
                float2 o;
                o.x = fs * acc[mi][nj][2*h];
                o.y = fs * acc[mi][nj][2*h + 1];
                *(float2*)(crow + nj * 8 + 2 * tr) = o;
            }
        }
    }
}

// ======================= HMMA flash attention — 8 warps, pair-split (R10-proven) =======================
#define SB_OFF   196608
#define SB_HALF  576
#define SB_PAIR  1152
#define FSMEM    (196608 + 4 * SB_PAIR * 4)   // 215040

__global__ __launch_bounds__(256, 1) void flash_mma(
    const __nv_bfloat16* __restrict__ qhi, const __nv_bfloat16* __restrict__ qlo,
    const __nv_bfloat16* __restrict__ khi, const __nv_bfloat16* __restrict__ klo,
    const __nv_bfloat16* __restrict__ vhi, const __nv_bfloat16* __restrict__ vlo,
    float* __restrict__ outr, float* __restrict__ outi) {
    extern __shared__ char sm[];
    uint32_t sb = smem_u32(sm);
    float* Sbuf = (float*)(sm + SB_OFF);
    int head = blockIdx.y;
    int qi = (int)gridDim.x - 1 - (int)blockIdx.x;
    int tid = threadIdx.x;
    int warp = tid >> 5, lane = tid & 31;
    int pair = warp >> 1, half = warp & 1;
    int tq = lane >> 2, tr = lane & 3;
    size_t hbase = (size_t)head * TT * D2;

    {
        const char* s0 = (const char*)(qhi + hbase + (size_t)qi * 64 * D2);
        const char* s1 = (const char*)(qlo + hbase + (size_t)qi * 64 * D2);
#pragma unroll
        for (int i = 0; i < 16; i++) {
            int idx = tid + i * 256;
            int mat = idx >> 11, r = (idx >> 5) & 63, g = idx & 31;
            const char* src = (mat == 0 ? s0 : s1) + (size_t)r * 512 + g * 16;
            uint32_t dst = sb + mat * 32768 + SWZ512(r * 512 + g * 16);
            asm volatile("cp.async.cg.shared.global [%0], [%1], 16;" :: "r"(dst), "l"(src));
        }
    }

    int nkb = 2 * (qi + 1);
    const char* kvsrc[4] = {(const char*)(khi + hbase), (const char*)(klo + hbase),
                            (const char*)(vhi + hbase), (const char*)(vlo + hbase)};
    auto loadKV = [&](int kb, int buf) {
        uint32_t base = sb + 65536 + buf * 65536;
#pragma unroll
        for (int i = 0; i < 16; i++) {
            int idx = tid + i * 256;
            int mat = idx >> 10, r = (idx >> 5) & 31, g = idx & 31;
            const char* src = kvsrc[mat] + (size_t)(kb * 32 + r) * 512 + g * 16;
            uint32_t dst = base + mat * 16384 + SWZ512(r * 512 + g * 16);
            asm volatile("cp.async.cg.shared.global [%0], [%1], 16;" :: "r"(dst), "l"(src));
        }
    };
    loadKV(0, 0);
    asm volatile("cp.async.commit_group;");

    float oAcc[16][4];
#pragma unroll
    for (int j = 0; j < 16; j++)
#pragma unroll
        for (int c = 0; c < 4; c++) oAcc[j][c] = 0.f;
    float m0 = -CUDART_INF_F, m1 = -CUDART_INF_F, l0 = 0.f, l1 = 0.f;
    int rowg0 = qi * 64 + pair * 16 + tq;

    for (int kb = 0; kb < nkb; kb++) {
        if (kb + 1 < nkb) {
            loadKV(kb + 1, (kb + 1) & 1);
            asm volatile("cp.async.commit_group;");
            asm volatile("cp.async.wait_group 1;");
        } else {
            asm volatile("cp.async.wait_group 0;");
        }
        __syncthreads();
        uint32_t kv = sb + 65536 + (kb & 1) * 65536;

        float sAcc[4][4];
#pragma unroll
        for (int j = 0; j < 4; j++)
#pragma unroll
            for (int c = 0; c < 4; c++) sAcc[j][c] = 0.f;
#pragma unroll
        for (int pass = 0; pass < 3; pass++) {
            uint32_t qb_ = sb + (pass == 2 ? 32768 : 0);
            uint32_t kb_ = kv + (pass == 1 ? 16384 : 0);
#pragma unroll
            for (int ks0 = 0; ks0 < 8; ks0++) {
                int ks = half * 8 + ks0;
                uint32_t qa[4];
                uint32_t qaddr = qb_ + SWZ512((pair * 16 + (lane & 15)) * 512
                                              + ks * 32 + (lane >> 4) * 16);
                asm volatile("ldmatrix.sync.aligned.m8n8.x4.shared.b16 {%0,%1,%2,%3}, [%4];"
                    : "=r"(qa[0]), "=r"(qa[1]), "=r"(qa[2]), "=r"(qa[3]) : "r"(qaddr));
                uint32_t bfr[4][2];
#pragma unroll
                for (int p = 0; p < 2; p++) {
                    int nr = p * 16 + (lane & 7) + ((lane >> 4) << 3);
                    uint32_t kaddr = kb_ + SWZ512(nr * 512 + ks * 32 + ((lane >> 3) & 1) * 16);
                    asm volatile("ldmatrix.sync.aligned.m8n8.x4.shared.b16 {%0,%1,%2,%3}, [%4];"
                        : "=r"(bfr[2*p][0]), "=r"(bfr[2*p][1]),
                          "=r"(bfr[2*p+1][0]), "=r"(bfr[2*p+1][1]) : "r"(kaddr));
                }
#pragma unroll
                for (int nj = 0; nj < 4; nj++)
                    asm volatile(
                        "mma.sync.aligned.m16n8k16.row.col.f32.bf16.bf16.f32 "
                        "{%0,%1,%2,%3}, {%4,%5,%6,%7}, {%8,%9}, {%0,%1,%2,%3};"
                        : "+f"(sAcc[nj][0]), "+f"(sAcc[nj][1]),
                          "+f"(sAcc[nj][2]), "+f"(sAcc[nj][3])
                        : "r"(qa[0]), "r"(qa[1]), "r"(qa[2]), "r"(qa[3]),
                          "r"(bfr[nj][0]), "r"(bfr[nj][1]));
            }
        }

        {
            float* my = Sbuf + pair * SB_PAIR + half * SB_HALF;
#pragma unroll
            for (int nj = 0; nj < 4; nj++)
#pragma unroll
                for (int c = 0; c < 4; c++)
                    my[(tq + (c >> 1) * 8) * 36 + nj * 8 + tr * 2 + (c & 1)] = sAcc[nj][c];
        }
        __syncthreads();
        {
            const float* b0 = Sbuf + pair * SB_PAIR;
            const float* b1 = b0 + SB_HALF;
#pragma unroll
            for (int nj = 0; nj < 4; nj++)
#pragma unroll
                for (int c = 0; c < 4; c++) {
                    int ix = (tq + (c >> 1) * 8) * 36 + nj * 8 + tr * 2 + (c & 1);
                    sAcc[nj][c] = b0[ix] + b1[ix];
                }
        }

        float mloc0 = -CUDART_INF_F, mloc1 = -CUDART_INF_F;
#pragma unroll
        for (int nj = 0; nj < 4; nj++)
#pragma unroll
            for (int c = 0; c < 4; c++) {
                float sv = sAcc[nj][c] * 0.0625f;
                int col = kb * 32 + nj * 8 + tr * 2 + (c & 1);
                int rg = rowg0 + ((c >> 1) << 3);
                if (col > rg) sv = -1e9f;
                sAcc[nj][c] = sv;
                if (c < 2) mloc0 = fmaxf(mloc0, sv);
                else       mloc1 = fmaxf(mloc1, sv);
            }
        mloc0 = fmaxf(mloc0, __shfl_xor_sync(0xffffffffu, mloc0, 1));
        mloc0 = fmaxf(mloc0, __shfl_xor_sync(0xffffffffu, mloc0, 2));
        mloc1 = fmaxf(mloc1, __shfl_xor_sync(0xffffffffu, mloc1, 1));
        mloc1 = fmaxf(mloc1, __shfl_xor_sync(0xffffffffu, mloc1, 2));
        float mn0 = fmaxf(m0, mloc0), mn1 = fmaxf(m1, mloc1);
        float f0 = __expf(m0 - mn0), f1 = __expf(m1 - mn1);
        m0 = mn0; m1 = mn1;
        float rs0 = 0.f, rs1 = 0.f;
#pragma unroll
        for (int nj = 0; nj < 4; nj++)
#pragma unroll
            for (int c = 0; c < 4; c++) {
                float p = __expf(sAcc[nj][c] - (c < 2 ? mn0 : mn1));
                sAcc[nj][c] = p;
                if (c < 2) rs0 += p; else rs1 += p;
            }
        rs0 += __shfl_xor_sync(0xffffffffu, rs0, 1);
        rs0 += __shfl_xor_sync(0xffffffffu, rs0, 2);
        rs1 += __shfl_xor_sync(0xffffffffu, rs1, 1);
        rs1 += __shfl_xor_sync(0xffffffffu, rs1, 2);
        l0 = l0 * f0 + rs0;
        l1 = l1 * f1 + rs1;
#pragma unroll
        for (int j = 0; j < 16; j++) {
            oAcc[j][0] *= f0; oAcc[j][1] *= f0;
            oAcc[j][2] *= f1; oAcc[j][3] *= f1;
        }

        uint32_t phi[2][4], plo[2][4];
#pragma unroll
        for (int ks2 = 0; ks2 < 2; ks2++) {
            int nb = ks2 * 2;
#pragma unroll
            for (int q = 0; q < 2; q++) {
                float a0 = sAcc[nb][2*q], a1 = sAcc[nb][2*q+1];
                float b0 = sAcc[nb+1][2*q], b1 = sAcc[nb+1][2*q+1];
                phi[ks2][q]     = packbf(a0, a1);
                phi[ks2][q + 2] = packbf(b0, b1);
                float a0h = __bfloat162float(__float2bfloat16_rn(a0));
                float a1h = __bfloat162float(__float2bfloat16_rn(a1));
                float b0h = __bfloat162float(__float2bfloat16_rn(b0));
                float b1h = __bfloat162float(__float2bfloat16_rn(b1));
                plo[ks2][q]     = packbf(a0 - a0h, a1 - a1h);
                plo[ks2][q + 2] = packbf(b0 - b0h, b1 - b1h);
            }
        }

        uint32_t vbh = kv + 32768, vbl = kv + 49152;
#pragma unroll
        for (int ks2 = 0; ks2 < 2; ks2++) {
#pragma unroll
            for (int j = 0; j < 16; j++) {
                int nj = half * 16 + j;
                uint32_t off = SWZ512((ks2 * 16 + (lane & 15)) * 512 + nj * 16);
                uint32_t vh0, vh1, vl0, vl1;
                asm volatile("ldmatrix.sync.aligned.m8n8.x2.trans.shared.b16 {%0,%1}, [%2];"
                    : "=r"(vh0), "=r"(vh1) : "r"(vbh + off));
                asm volatile("ldmatrix.sync.aligned.m8n8.x2.trans.shared.b16 {%0,%1}, [%2];"
                    : "=r"(vl0), "=r"(vl1) : "r"(vbl + off));
                asm volatile(
                    "mma.sync.aligned.m16n8k16.row.col.f32.bf16.bf16.f32 "
                    "{%0,%1,%2,%3}, {%4,%5,%6,%7}, {%8,%9}, {%0,%1,%2,%3};"
                    : "+f"(oAcc[j][0]), "+f"(oAcc[j][1]), "+f"(oAcc[j][2]), "+f"(oAcc[j][3])
                    : "r"(phi[ks2][0]), "r"(phi[ks2][1]), "r"(phi[ks2][2]), "r"(phi[ks2][3]),
                      "r"(vh0), "r"(vh1));
                asm volatile(
                    "mma.sync.aligned.m16n8k16.row.col.f32.bf16.bf16.f32 "
                    "{%0,%1,%2,%3}, {%4,%5,%6,%7}, {%8,%9}, {%0,%1,%2,%3};"
                    : "+f"(oAcc[j][0]), "+f"(oAcc[j][1]), "+f"(oAcc[j][2]), "+f"(oAcc[j][3])
                    : "r"(plo[ks2][0]), "r"(plo[ks2][1]), "r"(plo[ks2][2]), "r"(plo[ks2][3]),
                      "r"(vh0), "r"(vh1));
                asm volatile(
                    "mma.sync.aligned.m16n8k16.row.col.f32.bf16.bf16.f32 "
                    "{%0,%1,%2,%3}, {%4,%5,%6,%7}, {%8,%9}, {%0,%1,%2,%3};"
                    : "+f"(oAcc[j][0]), "+f"(oAcc[j][1]), "+f"(oAcc[j][2]), "+f"(oAcc[j][3])
                    : "r"(phi[ks2][0]), "r"(phi[ks2][1]), "r"(phi[ks2][2]), "r"(phi[ks2][3]),
                      "r"(vl0), "r"(vl1));
            }
        }
        __syncthreads();
    }

    float il0 = 1.0f / l0, il1 = 1.0f / l1;
    int hoff = head * HD;
    int r0 = qi * 64 + pair * 16 + tq;
    float* outp = (half == 0) ? outr : outi;
#pragma unroll
    for (int j = 0; j < 16; j++) {
        int col = j * 8 + tr * 2;
        float2 a = make_float2(oAcc[j][0] * il0, oAcc[j][1] * il0);
        float2 b = make_float2(oAcc[j][2] * il1, oAcc[j][3] * il1);
        *(float2*)(outp + (size_t)r0 * HH + hoff + col) = a;
        *(float2*)(outp + (size_t)(r0 + 8) * HH + hoff + col) = b;
    }
}

// ======================= launch =======================
extern "C" void kernel_launch(void* const* d_in, const int* in_sizes, int n_in,
                              void* d_out, int out_size) {
    const float* hr   = (const float*)d_in[0];
    const float* hi   = (const float*)d_in[1];
    const int*   pos  = (const int*)d_in[2];
    float* out = (float*)d_out;

    __nv_bfloat16 *nr, *ni, *wsp, *qhi, *qlo, *khi, *klo, *vhi, *vlo;
    float *is1, *is2, *is3, *is4, *pqr, *pqi, *pkr, *pki, *pvr, *pvi, *ar, *ai;
    cudaGetSymbolAddress((void**)&nr,  g_nr);
    cudaGetSymbolAddress((void**)&ni,  g_ni);
    cudaGetSymbolAddress((void**)&is1, g_invs1);
    cudaGetSymbolAddress((void**)&is2, g_invs2);
    cudaGetSymbolAddress((void**)&is3, g_invs3);
    cudaGetSymbolAddress((void**)&is4, g_invs4);
    cudaGetSymbolAddress((void**)&wsp, g_wsp);
    cudaGetSymbolAddress((void**)&pqr, g_pqr);
    cudaGetSymbolAddress((void**)&pqi, g_pqi);
    cudaGetSymbolAddress((void**)&pkr, g_pkr);
    cudaGetSymbolAddress((void**)&pki, g_pki);
    cudaGetSymbolAddress((void**)&pvr, g_pvr);
    cudaGetSymbolAddress((void**)&pvi, g_pvi);
    cudaGetSymbolAddress((void**)&ar,  g_ar);
    cudaGetSymbolAddress((void**)&ai,  g_ai);
    cudaGetSymbolAddress((void**)&qhi, g_qhi);
    cudaGetSymbolAddress((void**)&qlo, g_qlo);
    cudaGetSymbolAddress((void**)&khi, g_khi);
    cudaGetSymbolAddress((void**)&klo, g_klo);
    cudaGetSymbolAddress((void**)&vhi, g_vhi);
    cudaGetSymbolAddress((void**)&vlo, g_vlo);
    __nv_bfloat16* ws[16];
    for (int i = 0; i < 16; i++) ws[i] = wsp + (size_t)i * HH * HH;

    // ---- prep (merged launches)
    QuantArgs qa;
    qa.x[0] = hr; qa.x[1] = hi;
    qa.q[0] = nr; qa.q[1] = ni;
    qa.invs[0] = is1; qa.invs[1] = is2;
    rowquant_bf16_kernel<<<dim3(TT, 2), 256>>>(qa);

    cossin_kernel<<<(TT * HD) / 256, 256>>>(pos);

    SplitArgs sa;
    for (int w = 0; w < 8; w++) sa.w[w] = (const float*)d_in[3 + w];
    sa.base = wsp;
    split_kernel<<<dim3((HH * HH) / 1024, 8), 256>>>(sa);

    // ---- projections: separate launches (L2 weight residency), occ-2 GEMM
    cudaFuncSetAttribute(gemm_dual_mma, cudaFuncAttributeMaxDynamicSharedMemorySize, GSM);
    dim3 gg(HH / 128, TT / 128);
    gemm_dual_mma<<<gg, 256, GSM>>>(nr, ni, ws[0], ws[1], ws[2], ws[3], is1, is2,  1.f, pqr);
    gemm_dual_mma<<<gg, 256, GSM>>>(nr, ni, ws[2], ws[3], ws[0], ws[1], is1, is2, -1.f, pqi);
    gemm_dual_mma<<<gg, 256, GSM>>>(nr, ni, ws[4], ws[5], ws[6], ws[7], is1, is2,  1.f, pkr);
    gemm_dual_mma<<<gg, 256, GSM>>>(nr, ni, ws[6], ws[7], ws[4], ws[5], is1, is2, -1.f, pki);
    gemm_dual_mma<<<gg, 256, GSM>>>(nr, ni, ws[8], ws[9], ws[10], ws[11], is1, is2,  1.f, pvr);
    gemm_dual_mma<<<gg, 256, GSM>>>(nr, ni, ws[10], ws[11], ws[8], ws[9], is1, is2, -1.f, pvi);

    // ---- rope + hi/lo split (3 tasks)
    RSArgs ra;
    ra.xr[0] = pqr; ra.xi[0] = pqi; ra.ghi[0] = qhi; ra.glo[0] = qlo; ra.dorope[0] = 1;
    ra.xr[1] = pkr; ra.xi[1] = pki; ra.ghi[1] = khi; ra.glo[1] = klo; ra.dorope[1] = 1;
    ra.xr[2] = pvr; ra.xi[2] = pvi; ra.ghi[2] = vhi; ra.glo[2] = vlo; ra.dorope[2] = 0;
    ropesplit_kernel<<<dim3((TT * HH) / 256, 3), 256>>>(ra);

    // ---- flash attention (8 warps)
    cudaFuncSetAttribute(flash_mma, cudaFuncAttributeMaxDynamicSharedMemorySize, FSMEM);
    flash_mma<<<dim3(TT / 64, NHEAD), 256, FSMEM>>>(qhi, qlo, khi, klo, vhi, vlo, ar, ai);

    // ---- output projection
    QuantArgs qb;
    qb.x[0] = ar; qb.x[1] = ai;
    qb.q[0] = nr; qb.q[1] = ni;
    qb.invs[0] = is3; qb.invs[1] = is4;
    rowquant_bf16_kernel<<<dim3(TT, 2), 256>>>(qb);

    gemm_dual_mma<<<gg, 256, GSM>>>(nr, ni, ws[12], ws[13], ws[14], ws[15], is3, is4,  1.f, out);
    gemm_dual_mma<<<gg, 256, GSM>>>(nr, ni, ws[14], ws[15], ws[12], ws[13], is3, is4, -1.f, out + (size_t)TT * HH);
}

// round 12
// speedup vs baseline: 1.0152x; 1.0152x over previous
#include <cuda_runtime.h>
#include <cuda_bf16.h>
#include <math_constants.h>
#include <cstdint>

#define TT 2048
#define HH 2048
#define NHEAD 16
#define HD 128
#define D2 256

// ======================= scratch (static device globals) =======================
__device__ __nv_bfloat16 g_nr[TT*HH];
__device__ __nv_bfloat16 g_ni[TT*HH];
__device__ float g_invs1[TT];
__device__ float g_invs2[TT];
__device__ float g_invs3[TT];
__device__ float g_invs4[TT];
__device__ __nv_bfloat16 g_wsp[16][HH*HH];
__device__ float g_pqr[TT*HH];
__device__ float g_pqi[TT*HH];
__device__ float g_pkr[TT*HH];
__device__ float g_pki[TT*HH];
__device__ float g_pvr[TT*HH];
__device__ float g_pvi[TT*HH];
__device__ float g_ar[TT*HH];
__device__ float g_ai[TT*HH];
__device__ float g_cos[TT*HD];
__device__ float g_sin[TT*HD];
__device__ __nv_bfloat16 g_qhi[NHEAD*TT*D2];
__device__ __nv_bfloat16 g_qlo[NHEAD*TT*D2];
__device__ __nv_bfloat16 g_khi[NHEAD*TT*D2];
__device__ __nv_bfloat16 g_klo[NHEAD*TT*D2];
__device__ __nv_bfloat16 g_vhi[NHEAD*TT*D2];
__device__ __nv_bfloat16 g_vlo[NHEAD*TT*D2];

// ======================= helpers =======================
__device__ __forceinline__ uint32_t smem_u32(const void* p) {
    uint32_t a;
    asm("{ .reg .u64 t; cvta.to.shared.u64 t, %1; cvt.u32.u64 %0, t; }" : "=r"(a) : "l"(p));
    return a;
}
#define SWZ128(b) ((b) ^ (((b) >> 3) & 0x70))
#define SWZ512(b) ((b) ^ (((b) >> 5) & 0x70))

__device__ __forceinline__ uint32_t packbf(float a, float b) {
    __nv_bfloat162 t = __floats2bfloat162_rn(a, b);
    return *(uint32_t*)&t;
}

// ======================= prep kernels (merged launches) =======================
struct QuantArgs {
    const float* x[2];
    __nv_bfloat16* q[2];
    float* invs[2];
};

__global__ void rowquant_bf16_kernel(QuantArgs a) {
    __shared__ float red[256];
    int sel = blockIdx.y;
    int row = blockIdx.x;
    const float* xr = a.x[sel] + row * HH;
    float m = 0.f;
    for (int c = threadIdx.x; c < HH; c += 256) m = fmaxf(m, fabsf(xr[c]));
    red[threadIdx.x] = m;
    __syncthreads();
    for (int s = 128; s > 0; s >>= 1) {
        if (threadIdx.x < s) red[threadIdx.x] = fmaxf(red[threadIdx.x], red[threadIdx.x + s]);
        __syncthreads();
    }
    float scale = 127.0f / fmaxf(red[0], 1e-5f);
    if (threadIdx.x == 0) a.invs[sel][row] = 1.0f / scale;
    __nv_bfloat16* q = a.q[sel];
    for (int c = threadIdx.x; c < HH; c += 256) {
        float v = rintf(xr[c] * scale);
        v = fminf(fmaxf(v, -128.f), 127.f);
        q[row * HH + c] = __float2bfloat16_rn(v);
    }
}

struct SplitArgs { const float* w[8]; __nv_bfloat16* base; };

__global__ void split_kernel(SplitArgs a) {
    int wsel = blockIdx.y;
    int i = (blockIdx.x * 256 + threadIdx.x) * 4;
    float4 v = *(const float4*)(a.w[wsel] + i);
    __nv_bfloat16* hi = a.base + (size_t)(2 * wsel) * HH * HH;
    __nv_bfloat16* lo = a.base + (size_t)(2 * wsel + 1) * HH * HH;
    __nv_bfloat16 h[4], l[4];
    float vv[4] = {v.x, v.y, v.z, v.w};
#pragma unroll
    for (int j = 0; j < 4; j++) {
        h[j] = __float2bfloat16_rn(vv[j]);
        l[j] = __float2bfloat16_rn(vv[j] - __bfloat162float(h[j]));
    }
    *(uint64_t*)(hi + i) = *(uint64_t*)h;
    *(uint64_t*)(lo + i) = *(uint64_t*)l;
}

// fp32 chain — matches XLA's fp32-rounded angle + cos/sin (proven; do NOT "improve")
__global__ void cossin_kernel(const int* __restrict__ pos) {
    int idx = blockIdx.x * 256 + threadIdx.x;
    if (idx >= TT * HD) return;
    int t = idx / HD, d = idx % HD;
    float invf = 1.0f / powf(10000.0f, (float)d / (float)HD);
    float f = (float)pos[t] * invf;
    g_cos[idx] = __bfloat162float(__float2bfloat16(cosf(f)));
    g_sin[idx] = __bfloat162float(__float2bfloat16(sinf(f)));
}

struct RSArgs {
    const float* xr[3];
    const float* xi[3];
    __nv_bfloat16* ghi[3];
    __nv_bfloat16* glo[3];
    int dorope[3];
};

__global__ void ropesplit_kernel(RSArgs a) {
    int sel = blockIdx.y;
    int idx = blockIdx.x * 256 + threadIdx.x;
    int t = idx >> 11;
    int colh = idx & 2047;
    int h = colh >> 7, d = colh & 127;
    float r = a.xr[sel][idx], im = a.xi[sel][idx];
    if (a.dorope[sel]) {
        float c = g_cos[t * HD + d], s = g_sin[t * HD + d];
        float rr = r * c - im * s;
        float ii = im * c + r * s;
        r = rr; im = ii;
    }
    size_t base = ((size_t)h * TT + t) * D2;
    __nv_bfloat16 rh = __float2bfloat16_rn(r);
    a.ghi[sel][base + d] = rh;
    a.glo[sel][base + d] = __float2bfloat16_rn(r - __bfloat162float(rh));
    __nv_bfloat16 ih = __float2bfloat16_rn(im);
    a.ghi[sel][base + 128 + d] = ih;
    a.glo[sel][base + 128 + d] = __float2bfloat16_rn(im - __bfloat162float(ih));
}

// ======================= mma.sync dual GEMM (R10-proven loop; z-batched tasks) =======================
// task z: C = invs1[m]*(A1 @ (B1hi+B1lo)^T) + sign*invs2[m]*(A2 @ (B2hi+B2lo)^T)
// CTA 128x256, 8 warps (2m x 4n), warp tile 64x64. K chunks of 64, 4-stage cp.async ring.
#define STAGES 4
#define NCHUNK 128
#define STG_A  16384
#define STG_SZ 49152
#define GSM    (STAGES * STG_SZ)   // 196608

struct DualTask {
    const __nv_bfloat16 *B1hi, *B1lo, *B2hi, *B2lo;
    const float *invs1, *invs2;
    float sign;
    float* C;
};
struct DualTasks { DualTask t[6]; };

__device__ __forceinline__ void load_chunk(uint32_t st,
                                           const __nv_bfloat16* Aseg,
                                           const __nv_bfloat16* Bseg,
                                           int m0, int n0, int kc, int tid) {
    const char* ag = (const char*)(Aseg + (size_t)m0 * HH + kc * 64);
    const char* bg = (const char*)(Bseg + (size_t)n0 * HH + kc * 64);
    uint32_t sa = st, sb = st + STG_A;
#pragma unroll
    for (int i = 0; i < 4; i++) {
        int idx = tid + i * 256;
        int r = idx >> 3, g = idx & 7;
        uint32_t so = sa + SWZ128(r * 128 + g * 16);
        asm volatile("cp.async.cg.shared.global [%0], [%1], 16;"
                     :: "r"(so), "l"(ag + (size_t)r * 4096 + g * 16));
    }
#pragma unroll
    for (int i = 0; i < 8; i++) {
        int idx = tid + i * 256;
        int r = idx >> 3, g = idx & 7;
        uint32_t so = sb + SWZ128(r * 128 + g * 16);
        asm volatile("cp.async.cg.shared.global [%0], [%1], 16;"
                     :: "r"(so), "l"(bg + (size_t)r * 4096 + g * 16));
    }
}

__device__ __forceinline__ void compute_chunk(uint32_t st,
                                              int warp_m, int warp_n, int lane,
                                              float (&acc)[4][8][4]) {
    uint32_t sa = st, sb = st + STG_A;
#pragma unroll
    for (int ks = 0; ks < 4; ks++) {
        uint32_t af[4][4];
#pragma unroll
        for (int mi = 0; mi < 4; mi++) {
            int r = warp_m * 64 + mi * 16 + (lane & 15);
            int cb = ks * 32 + (lane >> 4) * 16;
            uint32_t ad = sa + SWZ128(r * 128 + cb);
            asm volatile("ldmatrix.sync.aligned.m8n8.x4.shared.b16 {%0,%1,%2,%3}, [%4];"
                : "=r"(af[mi][0]), "=r"(af[mi][1]), "=r"(af[mi][2]), "=r"(af[mi][3])
                : "r"(ad));
        }
        uint32_t bf[8][2];
#pragma unroll
        for (int p = 0; p < 4; p++) {
            int nr = warp_n * 64 + p * 16 + (lane & 7) + ((lane >> 4) << 3);
            int cb = ks * 32 + ((lane >> 3) & 1) * 16;
            uint32_t bd = sb + SWZ128(nr * 128 + cb);
            asm volatile("ldmatrix.sync.aligned.m8n8.x4.shared.b16 {%0,%1,%2,%3}, [%4];"
                : "=r"(bf[2*p][0]), "=r"(bf[2*p][1]), "=r"(bf[2*p+1][0]), "=r"(bf[2*p+1][1])
                : "r"(bd));
        }
#pragma unroll
        for (int mi = 0; mi < 4; mi++)
#pragma unroll
            for (int nj = 0; nj < 8; nj++)
                asm volatile(
                    "mma.sync.aligned.m16n8k16.row.col.f32.bf16.bf16.f32 "
                    "{%0,%1,%2,%3}, {%4,%5,%6,%7}, {%8,%9}, {%0,%1,%2,%3};"
                    : "+f"(acc[mi][nj][0]), "+f"(acc[mi][nj][1]),
                      "+f"(acc[mi][nj][2]), "+f"(acc[mi][nj][3])
                    : "r"(af[mi][0]), "r"(af[mi][1]), "r"(af[mi][2]), "r"(af[mi][3]),
                      "r"(bf[nj][0]), "r"(bf[nj][1]));
    }
}

__global__ __launch_bounds__(256, 1) void gemm_dual_mma(
    const __nv_bfloat16* __restrict__ A1, const __nv_bfloat16* __restrict__ A2,
    DualTasks tasks) {
    extern __shared__ char smem[];
    uint32_t sbase = smem_u32(smem);
    const DualTask tk = tasks.t[blockIdx.z];
    const __nv_bfloat16* B1hi = tk.B1hi;
    const __nv_bfloat16* B1lo = tk.B1lo;
    const __nv_bfloat16* B2hi = tk.B2hi;
    const __nv_bfloat16* B2lo = tk.B2lo;
    int tid = threadIdx.x;
    int wid = tid >> 5, lane = tid & 31;
    int warp_m = wid >> 2, warp_n = wid & 3;
    int m0 = blockIdx.y * 128, n0 = blockIdx.x * 256;
    int tq = lane >> 2, tr = lane & 3;

    float acc[4][8][4];
#pragma unroll
    for (int a = 0; a < 4; a++)
#pragma unroll
        for (int b = 0; b < 8; b++)
#pragma unroll
            for (int c = 0; c < 4; c++) acc[a][b][c] = 0.f;

    for (int c = 0; c < STAGES; c++) {
        load_chunk(sbase + c * STG_SZ, A1, B1hi, m0, n0, c, tid);
        asm volatile("cp.async.commit_group;");
    }

    for (int c = 0; c < NCHUNK; c++) {
        int stage = c & (STAGES - 1);
        uint32_t st = sbase + stage * STG_SZ;
        int rem = NCHUNK - 1 - c;
        if (rem >= 3)      asm volatile("cp.async.wait_group 3;");
        else if (rem == 2) asm volatile("cp.async.wait_group 2;");
        else if (rem == 1) asm volatile("cp.async.wait_group 1;");
        else               asm volatile("cp.async.wait_group 0;");
        __syncthreads();

        compute_chunk(st, warp_m, warp_n, lane, acc);

        if (c == 63) {
#pragma unroll
            for (int mi = 0; mi < 4; mi++)
#pragma unroll
                for (int h = 0; h < 2; h++) {
                    int row = m0 + warp_m * 64 + mi * 16 + tq + h * 8;
                    float ratio = tk.sign * tk.invs1[row] / tk.invs2[row];
#pragma unroll
                    for (int nj = 0; nj < 8; nj++) {
                        acc[mi][nj][2*h]     *= ratio;
                        acc[mi][nj][2*h + 1] *= ratio;
                    }
                }
        }
        __syncthreads();

        int cn = c + STAGES;
        if (cn < NCHUNK) {
            int sel = cn >> 5;
            const __nv_bfloat16* Bseg = (sel == 0) ? B1hi : (sel == 1) ? B1lo
                                       : (sel == 2) ? B2hi : B2lo;
            const __nv_bfloat16* Aseg = (cn >= 64) ? A2 : A1;
            load_chunk(st, Aseg, Bseg, m0, n0, cn & 31, tid);
            asm volatile("cp.async.commit_group;");
        }
    }

#pragma unroll
    for (int mi = 0; mi < 4; mi++) {
#pragma unroll
        for (int h = 0; h < 2; h++) {
            int row = m0 + warp_m * 64 + mi * 16 + tq + h * 8;
            float fs = tk.sign * tk.invs2[row];
            float* crow = tk.C + (size_t)row * HH + n0 + warp_n * 64;
#pragma unroll
            for (int nj = 0; nj < 8; nj++) {
                float2 o;
                o.x = fs * acc[mi][nj][2*h];
                o.y = fs * acc[mi][nj][2*h + 1];
                *(float2*)(crow + nj * 8 + 2 * tr) = o;
            }
        }
    }
}

// ======================= HMMA flash attention — 8 warps, pair-split (R10-proven) =======================
#define SB_OFF   196608
#define SB_HALF  576
#define SB_PAIR  1152
#define FSMEM    (196608 + 4 * SB_PAIR * 4)   // 215040

__global__ __launch_bounds__(256, 1) void flash_mma(
    const __nv_bfloat16* __restrict__ qhi, const __nv_bfloat16* __restrict__ qlo,
    const __nv_bfloat16* __restrict__ khi, const __nv_bfloat16* __restrict__ klo,
    const __nv_bfloat16* __restrict__ vhi, const __nv_bfloat16* __restrict__ vlo,
    float* __restrict__ outr, float* __restrict__ outi) {
    extern __shared__ char sm[];
    uint32_t sb = smem_u32(sm);
    float* Sbuf = (float*)(sm + SB_OFF);
    int head = blockIdx.y;
    int qi = (int)gridDim.x - 1 - (int)blockIdx.x;
    int tid = threadIdx.x;
    int warp = tid >> 5, lane = tid & 31;
    int pair = warp >> 1, half = warp & 1;
    int tq = lane >> 2, tr = lane & 3;
    size_t hbase = (size_t)head * TT * D2;

    {
        const char* s0 = (const char*)(qhi + hbase + (size_t)qi * 64 * D2);
        const char* s1 = (const char*)(qlo + hbase + (size_t)qi * 64 * D2);
#pragma unroll
        for (int i = 0; i < 16; i++) {
            int idx = tid + i * 256;
            int mat = idx >> 11, r = (idx >> 5) & 63, g = idx & 31;
            const char* src = (mat == 0 ? s0 : s1) + (size_t)r * 512 + g * 16;
            uint32_t dst = sb + mat * 32768 + SWZ512(r * 512 + g * 16);
            asm volatile("cp.async.cg.shared.global [%0], [%1], 16;" :: "r"(dst), "l"(src));
        }
    }

    int nkb = 2 * (qi + 1);
    const char* kvsrc[4] = {(const char*)(khi + hbase), (const char*)(klo + hbase),
                            (const char*)(vhi + hbase), (const char*)(vlo + hbase)};
    auto loadKV = [&](int kb, int buf) {
        uint32_t base = sb + 65536 + buf * 65536;
#pragma unroll
        for (int i = 0; i < 16; i++) {
            int idx = tid + i * 256;
            int mat = idx >> 10, r = (idx >> 5) & 31, g = idx & 31;
            const char* src = kvsrc[mat] + (size_t)(kb * 32 + r) * 512 + g * 16;
            uint32_t dst = base + mat * 16384 + SWZ512(r * 512 + g * 16);
            asm volatile("cp.async.cg.shared.global [%0], [%1], 16;" :: "r"(dst), "l"(src));
        }
    };
    loadKV(0, 0);
    asm volatile("cp.async.commit_group;");

    float oAcc[16][4];
#pragma unroll
    for (int j = 0; j < 16; j++)
#pragma unroll
        for (int c = 0; c < 4; c++) oAcc[j][c] = 0.f;
    float m0 = -CUDART_INF_F, m1 = -CUDART_INF_F, l0 = 0.f, l1 = 0.f;
    int rowg0 = qi * 64 + pair * 16 + tq;

    for (int kb = 0; kb < nkb; kb++) {
        if (kb + 1 < nkb) {
            loadKV(kb + 1, (kb + 1) & 1);
            asm volatile("cp.async.commit_group;");
            asm volatile("cp.async.wait_group 1;");
        } else {
            asm volatile("cp.async.wait_group 0;");
        }
        __syncthreads();
        uint32_t kv = sb + 65536 + (kb & 1) * 65536;

        float sAcc[4][4];
#pragma unroll
        for (int j = 0; j < 4; j++)
#pragma unroll
            for (int c = 0; c < 4; c++) sAcc[j][c] = 0.f;
#pragma unroll
        for (int pass = 0; pass < 3; pass++) {
            uint32_t qb_ = sb + (pass == 2 ? 32768 : 0);
            uint32_t kb_ = kv + (pass == 1 ? 16384 : 0);
#pragma unroll
            for (int ks0 = 0; ks0 < 8; ks0++) {
                int ks = half * 8 + ks0;
                uint32_t qa[4];
                uint32_t qaddr = qb_ + SWZ512((pair * 16 + (lane & 15)) * 512
                                              + ks * 32 + (lane >> 4) * 16);
                asm volatile("ldmatrix.sync.aligned.m8n8.x4.shared.b16 {%0,%1,%2,%3}, [%4];"
                    : "=r"(qa[0]), "=r"(qa[1]), "=r"(qa[2]), "=r"(qa[3]) : "r"(qaddr));
                uint32_t bfr[4][2];
#pragma unroll
                for (int p = 0; p < 2; p++) {
                    int nr = p * 16 + (lane & 7) + ((lane >> 4) << 3);
                    uint32_t kaddr = kb_ + SWZ512(nr * 512 + ks * 32 + ((lane >> 3) & 1) * 16);
                    asm volatile("ldmatrix.sync.aligned.m8n8.x4.shared.b16 {%0,%1,%2,%3}, [%4];"
                        : "=r"(bfr[2*p][0]), "=r"(bfr[2*p][1]),
                          "=r"(bfr[2*p+1][0]), "=r"(bfr[2*p+1][1]) : "r"(kaddr));
                }
#pragma unroll
                for (int nj = 0; nj < 4; nj++)
                    asm volatile(
                        "mma.sync.aligned.m16n8k16.row.col.f32.bf16.bf16.f32 "
                        "{%0,%1,%2,%3}, {%4,%5,%6,%7}, {%8,%9}, {%0,%1,%2,%3};"
                        : "+f"(sAcc[nj][0]), "+f"(sAcc[nj][1]),
                          "+f"(sAcc[nj][2]), "+f"(sAcc[nj][3])
                        : "r"(qa[0]), "r"(qa[1]), "r"(qa[2]), "r"(qa[3]),
                          "r"(bfr[nj][0]), "r"(bfr[nj][1]));
            }
        }

        {
            float* my = Sbuf + pair * SB_PAIR + half * SB_HALF;
#pragma unroll
            for (int nj = 0; nj < 4; nj++)
#pragma unroll
                for (int c = 0; c < 4; c++)
                    my[(tq + (c >> 1) * 8) * 36 + nj * 8 + tr * 2 + (c & 1)] = sAcc[nj][c];
        }
        __syncthreads();
        {
            const float* b0 = Sbuf + pair * SB_PAIR;
            const float* b1 = b0 + SB_HALF;
#pragma unroll
            for (int nj = 0; nj < 4; nj++)
#pragma unroll
                for (int c = 0; c < 4; c++) {
                    int ix = (tq + (c >> 1) * 8) * 36 + nj * 8 + tr * 2 + (c & 1);
                    sAcc[nj][c] = b0[ix] + b1[ix];
                }
        }

        float mloc0 = -CUDART_INF_F, mloc1 = -CUDART_INF_F;
#pragma unroll
        for (int nj = 0; nj < 4; nj++)
#pragma unroll
            for (int c = 0; c < 4; c++) {
                float sv = sAcc[nj][c] * 0.0625f;
                int col = kb * 32 + nj * 8 + tr * 2 + (c & 1);
                int rg = rowg0 + ((c >> 1) << 3);
                if (col > rg) sv = -1e9f;
                sAcc[nj][c] = sv;
                if (c < 2) mloc0 = fmaxf(mloc0, sv);
                else       mloc1 = fmaxf(mloc1, sv);
            }
        mloc0 = fmaxf(mloc0, __shfl_xor_sync(0xffffffffu, mloc0, 1));
        mloc0 = fmaxf(mloc0, __shfl_xor_sync(0xffffffffu, mloc0, 2));
        mloc1 = fmaxf(mloc1, __shfl_xor_sync(0xffffffffu, mloc1, 1));
        mloc1 = fmaxf(mloc1, __shfl_xor_sync(0xffffffffu, mloc1, 2));
        float mn0 = fmaxf(m0, mloc0), mn1 = fmaxf(m1, mloc1);
        float f0 = __expf(m0 - mn0), f1 = __expf(m1 - mn1);
        m0 = mn0; m1 = mn1;
        float rs0 = 0.f, rs1 = 0.f;
#pragma unroll
        for (int nj = 0; nj < 4; nj++)
#pragma unroll
            for (int c = 0; c < 4; c++) {
                float p = __expf(sAcc[nj][c] - (c < 2 ? mn0 : mn1));
                sAcc[nj][c] = p;
                if (c < 2) rs0 += p; else rs1 += p;
            }
        rs0 += __shfl_xor_sync(0xffffffffu, rs0, 1);
        rs0 += __shfl_xor_sync(0xffffffffu, rs0, 2);
        rs1 += __shfl_xor_sync(0xffffffffu, rs1, 1);
        rs1 += __shfl_xor_sync(0xffffffffu, rs1, 2);
        l0 = l0 * f0 + rs0;
        l1 = l1 * f1 + rs1;
#pragma unroll
        for (int j = 0; j < 16; j++) {
            oAcc[j][0] *= f0; oAcc[j][1] *= f0;
            oAcc[j][2] *= f1; oAcc[j][3] *= f1;
        }

        uint32_t phi[2][4], plo[2][4];
#pragma unroll
        for (int ks2 = 0; ks2 < 2; ks2++) {
            int nb = ks2 * 2;
#pragma unroll
            for (int q = 0; q < 2; q++) {
                float a0 = sAcc[nb][2*q], a1 = sAcc[nb][2*q+1];
                float b0 = sAcc[nb+1][2*q], b1 = sAcc[nb+1][2*q+1];
                phi[ks2][q]     = packbf(a0, a1);
                phi[ks2][q + 2] = packbf(b0, b1);
                float a0h = __bfloat162float(__float2bfloat16_rn(a0));
                float a1h = __bfloat162float(__float2bfloat16_rn(a1));
                float b0h = __bfloat162float(__float2bfloat16_rn(b0));
                float b1h = __bfloat162float(__float2bfloat16_rn(b1));
                plo[ks2][q]     = packbf(a0 - a0h, a1 - a1h);
                plo[ks2][q + 2] = packbf(b0 - b0h, b1 - b1h);
            }
        }

        uint32_t vbh = kv + 32768, vbl = kv + 49152;
#pragma unroll
        for (int ks2 = 0; ks2 < 2; ks2++) {
#pragma unroll
            for (int j = 0; j < 16; j++) {
                int nj = half * 16 + j;
                uint32_t off = SWZ512((ks2 * 16 + (lane & 15)) * 512 + nj * 16);
                uint32_t vh0, vh1, vl0, vl1;
                asm volatile("ldmatrix.sync.aligned.m8n8.x2.trans.shared.b16 {%0,%1}, [%2];"
                    : "=r"(vh0), "=r"(vh1) : "r"(vbh + off));
                asm volatile("ldmatrix.sync.aligned.m8n8.x2.trans.shared.b16 {%0,%1}, [%2];"
                    : "=r"(vl0), "=r"(vl1) : "r"(vbl + off));
                asm volatile(
                    "mma.sync.aligned.m16n8k16.row.col.f32.bf16.bf16.f32 "
                    "{%0,%1,%2,%3}, {%4,%5,%6,%7}, {%8,%9}, {%0,%1,%2,%3};"
                    : "+f"(oAcc[j][0]), "+f"(oAcc[j][1]), "+f"(oAcc[j][2]), "+f"(oAcc[j][3])
                    : "r"(phi[ks2][0]), "r"(phi[ks2][1]), "r"(phi[ks2][2]), "r"(phi[ks2][3]),
                      "r"(vh0), "r"(vh1));
                asm volatile(
                    "mma.sync.aligned.m16n8k16.row.col.f32.bf16.bf16.f32 "
                    "{%0,%1,%2,%3}, {%4,%5,%6,%7}, {%8,%9}, {%0,%1,%2,%3};"
                    : "+f"(oAcc[j][0]), "+f"(oAcc[j][1]), "+f"(oAcc[j][2]), "+f"(oAcc[j][3])
                    : "r"(plo[ks2][0]), "r"(plo[ks2][1]), "r"(plo[ks2][2]), "r"(plo[ks2][3]),
                      "r"(vh0), "r"(vh1));
                asm volatile(
                    "mma.sync.aligned.m16n8k16.row.col.f32.bf16.bf16.f32 "
                    "{%0,%1,%2,%3}, {%4,%5,%6,%7}, {%8,%9}, {%0,%1,%2,%3};"
                    : "+f"(oAcc[j][0]), "+f"(oAcc[j][1]), "+f"(oAcc[j][2]), "+f"(oAcc[j][3])
                    : "r"(phi[ks2][0]), "r"(phi[ks2][1]), "r"(phi[ks2][2]), "r"(phi[ks2][3]),
                      "r"(vl0), "r"(vl1));
            }
        }
        __syncthreads();
    }

    float il0 = 1.0f / l0, il1 = 1.0f / l1;
    int hoff = head * HD;
    int r0 = qi * 64 + pair * 16 + tq;
    float* outp = (half == 0) ? outr : outi;
#pragma unroll
    for (int j = 0; j < 16; j++) {
        int col = j * 8 + tr * 2;
        float2 a = make_float2(oAcc[j][0] * il0, oAcc[j][1] * il0);
        float2 b = make_float2(oAcc[j][2] * il1, oAcc[j][3] * il1);
        *(float2*)(outp + (size_t)r0 * HH + hoff + col) = a;
        *(float2*)(outp + (size_t)(r0 + 8) * HH + hoff + col) = b;
    }
}

// ======================= launch =======================
extern "C" void kernel_launch(void* const* d_in, const int* in_sizes, int n_in,
                              void* d_out, int out_size) {
    const float* hr   = (const float*)d_in[0];
    const float* hi   = (const float*)d_in[1];
    const int*   pos  = (const int*)d_in[2];
    float* out = (float*)d_out;

    __nv_bfloat16 *nr, *ni, *wsp, *qhi, *qlo, *khi, *klo, *vhi, *vlo;
    float *is1, *is2, *is3, *is4, *pqr, *pqi, *pkr, *pki, *pvr, *pvi, *ar, *ai;
    cudaGetSymbolAddress((void**)&nr,  g_nr);
    cudaGetSymbolAddress((void**)&ni,  g_ni);
    cudaGetSymbolAddress((void**)&is1, g_invs1);
    cudaGetSymbolAddress((void**)&is2, g_invs2);
    cudaGetSymbolAddress((void**)&is3, g_invs3);
    cudaGetSymbolAddress((void**)&is4, g_invs4);
    cudaGetSymbolAddress((void**)&wsp, g_wsp);
    cudaGetSymbolAddress((void**)&pqr, g_pqr);
    cudaGetSymbolAddress((void**)&pqi, g_pqi);
    cudaGetSymbolAddress((void**)&pkr, g_pkr);
    cudaGetSymbolAddress((void**)&pki, g_pki);
    cudaGetSymbolAddress((void**)&pvr, g_pvr);
    cudaGetSymbolAddress((void**)&pvi, g_pvi);
    cudaGetSymbolAddress((void**)&ar,  g_ar);
    cudaGetSymbolAddress((void**)&ai,  g_ai);
    cudaGetSymbolAddress((void**)&qhi, g_qhi);
    cudaGetSymbolAddress((void**)&qlo, g_qlo);
    cudaGetSymbolAddress((void**)&khi, g_khi);
    cudaGetSymbolAddress((void**)&klo, g_klo);
    cudaGetSymbolAddress((void**)&vhi, g_vhi);
    cudaGetSymbolAddress((void**)&vlo, g_vlo);
    __nv_bfloat16* ws[16];
    for (int i = 0; i < 16; i++) ws[i] = wsp + (size_t)i * HH * HH;

    // ---- prep (merged launches)
    QuantArgs qa;
    qa.x[0] = hr; qa.x[1] = hi;
    qa.q[0] = nr; qa.q[1] = ni;
    qa.invs[0] = is1; qa.invs[1] = is2;
    rowquant_bf16_kernel<<<dim3(TT, 2), 256>>>(qa);

    cossin_kernel<<<(TT * HD) / 256, 256>>>(pos);

    SplitArgs sa;
    for (int w = 0; w < 8; w++) sa.w[w] = (const float*)d_in[3 + w];
    sa.base = wsp;
    split_kernel<<<dim3((HH * HH) / 1024, 8), 256>>>(sa);

    // ---- QKV projections: one z-batched launch (R10 loop, 768 CTAs)
    cudaFuncSetAttribute(gemm_dual_mma, cudaFuncAttributeMaxDynamicSharedMemorySize, GSM);
    DualTasks tq;
    tq.t[0] = {ws[0],  ws[1],  ws[2],  ws[3],  is1, is2,  1.f, pqr};
    tq.t[1] = {ws[2],  ws[3],  ws[0],  ws[1],  is1, is2, -1.f, pqi};
    tq.t[2] = {ws[4],  ws[5],  ws[6],  ws[7],  is1, is2,  1.f, pkr};
    tq.t[3] = {ws[6],  ws[7],  ws[4],  ws[5],  is1, is2, -1.f, pki};
    tq.t[4] = {ws[8],  ws[9],  ws[10], ws[11], is1, is2,  1.f, pvr};
    tq.t[5] = {ws[10], ws[11], ws[8],  ws[9],  is1, is2, -1.f, pvi};
    gemm_dual_mma<<<dim3(HH / 256, TT / 128, 6), 256, GSM>>>(nr, ni, tq);

    // ---- rope + hi/lo split (3 tasks)
    RSArgs ra;
    ra.xr[0] = pqr; ra.xi[0] = pqi; ra.ghi[0] = qhi; ra.glo[0] = qlo; ra.dorope[0] = 1;
    ra.xr[1] = pkr; ra.xi[1] = pki; ra.ghi[1] = khi; ra.glo[1] = klo; ra.dorope[1] = 1;
    ra.xr[2] = pvr; ra.xi[2] = pvi; ra.ghi[2] = vhi; ra.glo[2] = vlo; ra.dorope[2] = 0;
    ropesplit_kernel<<<dim3((TT * HH) / 256, 3), 256>>>(ra);

    // ---- flash attention (8 warps)
    cudaFuncSetAttribute(flash_mma, cudaFuncAttributeMaxDynamicSharedMemorySize, FSMEM);
    flash_mma<<<dim3(TT / 64, NHEAD), 256, FSMEM>>>(qhi, qlo, khi, klo, vhi, vlo, ar, ai);

    // ---- output projection: one z-batched launch (2 tasks)
    QuantArgs qb;
    qb.x[0] = ar; qb.x[1] = ai;
    qb.q[0] = nr; qb.q[1] = ni;
    qb.invs[0] = is3; qb.invs[1] = is4;
    rowquant_bf16_kernel<<<dim3(TT, 2), 256>>>(qb);

    DualTasks to;
    to.t[0] = {ws[12], ws[13], ws[14], ws[15], is3, is4,  1.f, out};
    to.t[1] = {ws[14], ws[15], ws[12], ws[13], is3, is4, -1.f, out + (size_t)TT * HH};
    gemm_dual_mma<<<dim3(HH / 256, TT / 128, 2), 256, GSM>>>(nr, ni, to);
}

// round 13
// speedup vs baseline: 1.0878x; 1.0715x over previous
#include <cuda_runtime.h>
#include <cuda_bf16.h>
#include <math_constants.h>
#include <cstdint>

#define TT 2048
#define HH 2048
#define NHEAD 16
#define HD 128
#define D2 256

// ======================= scratch (static device globals) =======================
__device__ __nv_bfloat16 g_nr[TT*HH];
__device__ __nv_bfloat16 g_ni[TT*HH];
__device__ float g_invs1[TT];
__device__ float g_invs2[TT];
__device__ float g_invs3[TT];
__device__ float g_invs4[TT];
__device__ __nv_bfloat16 g_wsp[16][HH*HH];
__device__ float g_ar[TT*HH];
__device__ float g_ai[TT*HH];
__device__ float g_cos[TT*HD];
__device__ float g_sin[TT*HD];
__device__ __nv_bfloat16 g_qhi[NHEAD*TT*D2];
__device__ __nv_bfloat16 g_qlo[NHEAD*TT*D2];
__device__ __nv_bfloat16 g_khi[NHEAD*TT*D2];
__device__ __nv_bfloat16 g_klo[NHEAD*TT*D2];
__device__ __nv_bfloat16 g_vhi[NHEAD*TT*D2];
__device__ __nv_bfloat16 g_vlo[NHEAD*TT*D2];

// ======================= helpers =======================
__device__ __forceinline__ uint32_t smem_u32(const void* p) {
    uint32_t a;
    asm("{ .reg .u64 t; cvta.to.shared.u64 t, %1; cvt.u32.u64 %0, t; }" : "=r"(a) : "l"(p));
    return a;
}
#define SWZ128(b) ((b) ^ (((b) >> 3) & 0x70))
#define SWZ512(b) ((b) ^ (((b) >> 5) & 0x70))

__device__ __forceinline__ uint32_t packbf(float a, float b) {
    __nv_bfloat162 t = __floats2bfloat162_rn(a, b);
    return *(uint32_t*)&t;
}

// ======================= prep kernels =======================
struct QuantArgs {
    const float* x[2];
    __nv_bfloat16* q[2];
    float* invs[2];
};

__global__ void rowquant_bf16_kernel(QuantArgs a) {
    __shared__ float red[256];
    int sel = blockIdx.y;
    int row = blockIdx.x;
    const float* xr = a.x[sel] + row * HH;
    float m = 0.f;
    for (int c = threadIdx.x; c < HH; c += 256) m = fmaxf(m, fabsf(xr[c]));
    red[threadIdx.x] = m;
    __syncthreads();
    for (int s = 128; s > 0; s >>= 1) {
        if (threadIdx.x < s) red[threadIdx.x] = fmaxf(red[threadIdx.x], red[threadIdx.x + s]);
        __syncthreads();
    }
    float scale = 127.0f / fmaxf(red[0], 1e-5f);
    if (threadIdx.x == 0) a.invs[sel][row] = 1.0f / scale;
    __nv_bfloat16* q = a.q[sel];
    for (int c = threadIdx.x; c < HH; c += 256) {
        float v = rintf(xr[c] * scale);
        v = fminf(fmaxf(v, -128.f), 127.f);
        q[row * HH + c] = __float2bfloat16_rn(v);
    }
}

struct SplitArgs { const float* w[8]; __nv_bfloat16* base; };

__global__ void split_kernel(SplitArgs a) {
    int wsel = blockIdx.y;
    int i = (blockIdx.x * 256 + threadIdx.x) * 4;
    float4 v = *(const float4*)(a.w[wsel] + i);
    __nv_bfloat16* hi = a.base + (size_t)(2 * wsel) * HH * HH;
    __nv_bfloat16* lo = a.base + (size_t)(2 * wsel + 1) * HH * HH;
    __nv_bfloat16 h[4], l[4];
    float vv[4] = {v.x, v.y, v.z, v.w};
#pragma unroll
    for (int j = 0; j < 4; j++) {
        h[j] = __float2bfloat16_rn(vv[j]);
        l[j] = __float2bfloat16_rn(vv[j] - __bfloat162float(h[j]));
    }
    *(uint64_t*)(hi + i) = *(uint64_t*)h;
    *(uint64_t*)(lo + i) = *(uint64_t*)l;
}

// fp32 chain — matches XLA's fp32-rounded angle + cos/sin (proven; do NOT "improve")
__global__ void cossin_kernel(const int* __restrict__ pos) {
    int idx = blockIdx.x * 256 + threadIdx.x;
    if (idx >= TT * HD) return;
    int t = idx / HD, d = idx % HD;
    float invf = 1.0f / powf(10000.0f, (float)d / (float)HD);
    float f = (float)pos[t] * invf;
    g_cos[idx] = __bfloat162float(__float2bfloat16(cosf(f)));
    g_sin[idx] = __bfloat162float(__float2bfloat16(sinf(f)));
}

// ======================= complex-paired dual-acc GEMM with fused rope/split epilogue =======================
// acc_r = nr@Wr^T + ni@Wi^T ; acc_i = nr@Wi^T - ni@Wr^T (sign via rescale trick per-acc)
// CTA 128x128, 8 warps (2m x 4n), warp tile 64x32, TWO accumulators.
// chunk: A(16K) + Br(16K) + Bi(16K) = 48K; for A=ni chunks Br/Bi sources swap.
// epilogue: mode 1 = rope+split, 0 = split, -1 = fp32 pair write.
#define STAGES 4
#define NCHUNK 128
#define STG_SZ 49152
#define GSM    (STAGES * STG_SZ)   // 196608

struct CTask {
    const __nv_bfloat16 *Wrhi, *Wrlo, *Wihi, *Wilo;
    const float *invs1, *invs2;
    __nv_bfloat16 *ghi, *glo;   // mode>=0: per-head hi/lo output
    float *fr, *fi;             // mode<0: fp32 outputs
    int mode;
};
struct CTasks { CTask t[3]; };

__device__ __forceinline__ void load_chunk3(uint32_t st,
                                            const __nv_bfloat16* Aseg,
                                            const __nv_bfloat16* Br,
                                            const __nv_bfloat16* Bi,
                                            int m0, int n0, int kc, int tid) {
    const char* ag = (const char*)(Aseg + (size_t)m0 * HH + kc * 64);
    const char* rg = (const char*)(Br + (size_t)n0 * HH + kc * 64);
    const char* ig = (const char*)(Bi + (size_t)n0 * HH + kc * 64);
#pragma unroll
    for (int i = 0; i < 4; i++) {
        int idx = tid + i * 256;
        int r = idx >> 3, g = idx & 7;
        uint32_t so = st + SWZ128(r * 128 + g * 16);
        asm volatile("cp.async.cg.shared.global [%0], [%1], 16;"
                     :: "r"(so), "l"(ag + (size_t)r * 4096 + g * 16));
    }
#pragma unroll
    for (int i = 0; i < 4; i++) {
        int idx = tid + i * 256;
        int r = idx >> 3, g = idx & 7;
        uint32_t so = st + 16384 + SWZ128(r * 128 + g * 16);
        asm volatile("cp.async.cg.shared.global [%0], [%1], 16;"
                     :: "r"(so), "l"(rg + (size_t)r * 4096 + g * 16));
    }
#pragma unroll
    for (int i = 0; i < 4; i++) {
        int idx = tid + i * 256;
        int r = idx >> 3, g = idx & 7;
        uint32_t so = st + 32768 + SWZ128(r * 128 + g * 16);
        asm volatile("cp.async.cg.shared.global [%0], [%1], 16;"
                     :: "r"(so), "l"(ig + (size_t)r * 4096 + g * 16));
    }
}

__device__ __forceinline__ void compute_chunk3(uint32_t st,
                                               int warp_m, int warp_n, int lane,
                                               float (&accr)[4][4][4], float (&acci)[4][4][4]) {
#pragma unroll
    for (int ks = 0; ks < 4; ks++) {
        uint32_t af[4][4];
#pragma unroll
        for (int mi = 0; mi < 4; mi++) {
            int r = warp_m * 64 + mi * 16 + (lane & 15);
            int cb = ks * 32 + (lane >> 4) * 16;
            uint32_t ad = st + SWZ128(r * 128 + cb);
            asm volatile("ldmatrix.sync.aligned.m8n8.x4.shared.b16 {%0,%1,%2,%3}, [%4];"
                : "=r"(af[mi][0]), "=r"(af[mi][1]), "=r"(af[mi][2]), "=r"(af[mi][3])
                : "r"(ad));
        }
        uint32_t br[4][2], bi[4][2];
#pragma unroll
        for (int p = 0; p < 2; p++) {
            int nr_ = warp_n * 32 + p * 16 + (lane & 7) + ((lane >> 4) << 3);
            int cb = ks * 32 + ((lane >> 3) & 1) * 16;
            uint32_t bd = st + 16384 + SWZ128(nr_ * 128 + cb);
            asm volatile("ldmatrix.sync.aligned.m8n8.x4.shared.b16 {%0,%1,%2,%3}, [%4];"
                : "=r"(br[2*p][0]), "=r"(br[2*p][1]), "=r"(br[2*p+1][0]), "=r"(br[2*p+1][1])
                : "r"(bd));
            uint32_t bd2 = st + 32768 + SWZ128(nr_ * 128 + cb);
            asm volatile("ldmatrix.sync.aligned.m8n8.x4.shared.b16 {%0,%1,%2,%3}, [%4];"
                : "=r"(bi[2*p][0]), "=r"(bi[2*p][1]), "=r"(bi[2*p+1][0]), "=r"(bi[2*p+1][1])
                : "r"(bd2));
        }
#pragma unroll
        for (int mi = 0; mi < 4; mi++)
#pragma unroll
            for (int nj = 0; nj < 4; nj++) {
                asm volatile(
                    "mma.sync.aligned.m16n8k16.row.col.f32.bf16.bf16.f32 "
                    "{%0,%1,%2,%3}, {%4,%5,%6,%7}, {%8,%9}, {%0,%1,%2,%3};"
                    : "+f"(accr[mi][nj][0]), "+f"(accr[mi][nj][1]),
                      "+f"(accr[mi][nj][2]), "+f"(accr[mi][nj][3])
                    : "r"(af[mi][0]), "r"(af[mi][1]), "r"(af[mi][2]), "r"(af[mi][3]),
                      "r"(br[nj][0]), "r"(br[nj][1]));
                asm volatile(
                    "mma.sync.aligned.m16n8k16.row.col.f32.bf16.bf16.f32 "
                    "{%0,%1,%2,%3}, {%4,%5,%6,%7}, {%8,%9}, {%0,%1,%2,%3};"
                    : "+f"(acci[mi][nj][0]), "+f"(acci[mi][nj][1]),
                      "+f"(acci[mi][nj][2]), "+f"(acci[mi][nj][3])
                    : "r"(af[mi][0]), "r"(af[mi][1]), "r"(af[mi][2]), "r"(af[mi][3]),
                      "r"(bi[nj][0]), "r"(bi[nj][1]));
            }
    }
}

__global__ __launch_bounds__(256, 1) void gemm_cplx(
    const __nv_bfloat16* __restrict__ A1, const __nv_bfloat16* __restrict__ A2,
    CTasks tasks) {
    extern __shared__ char smem[];
    uint32_t sbase = smem_u32(smem);
    const CTask tk = tasks.t[blockIdx.z];
    int tid = threadIdx.x;
    int wid = tid >> 5, lane = tid & 31;
    int warp_m = wid >> 2, warp_n = wid & 3;
    int m0 = blockIdx.y * 128, n0 = blockIdx.x * 128;
    int tq = lane >> 2, tr = lane & 3;

    float accr[4][4][4], acci[4][4][4];
#pragma unroll
    for (int a = 0; a < 4; a++)
#pragma unroll
        for (int b = 0; b < 4; b++)
#pragma unroll
            for (int c = 0; c < 4; c++) { accr[a][b][c] = 0.f; acci[a][b][c] = 0.f; }

    // chunk c: A = (c>=64 ? A2 : A1); lvl = (c>>5)&1; k = c&31.
    // region0 feeds acc_r: Wr for A1, Wi for A2. region1 feeds acc_i: Wi for A1, Wr for A2.
    auto segload = [&](int cn, uint32_t st) {
        int lvl = (cn >> 5) & 1;
        const __nv_bfloat16* Wr = lvl ? tk.Wrlo : tk.Wrhi;
        const __nv_bfloat16* Wi = lvl ? tk.Wilo : tk.Wihi;
        if (cn < 64) load_chunk3(st, A1, Wr, Wi, m0, n0, cn & 31, tid);
        else         load_chunk3(st, A2, Wi, Wr, m0, n0, cn & 31, tid);
        asm volatile("cp.async.commit_group;");
    };

    for (int c = 0; c < STAGES; c++) segload(c, sbase + c * STG_SZ);

    for (int c = 0; c < NCHUNK; c++) {
        int stage = c & (STAGES - 1);
        uint32_t st = sbase + stage * STG_SZ;
        int rem = NCHUNK - 1 - c;
        if (rem >= 3)      asm volatile("cp.async.wait_group 3;");
        else if (rem == 2) asm volatile("cp.async.wait_group 2;");
        else if (rem == 1) asm volatile("cp.async.wait_group 1;");
        else               asm volatile("cp.async.wait_group 0;");
        __syncthreads();

        compute_chunk3(st, warp_m, warp_n, lane, accr, acci);

        if (c == 63) {
            // acc_r = nr@Wr(hi+lo): *= +invs1/invs2 ; acc_i = nr@Wi(hi+lo): *= -invs1/invs2
#pragma unroll
            for (int mi = 0; mi < 4; mi++)
#pragma unroll
                for (int h = 0; h < 2; h++) {
                    int row = m0 + warp_m * 64 + mi * 16 + tq + h * 8;
                    float ratio = tk.invs1[row] / tk.invs2[row];
#pragma unroll
                    for (int nj = 0; nj < 4; nj++) {
                        accr[mi][nj][2*h]     *=  ratio;
                        accr[mi][nj][2*h + 1] *=  ratio;
                        acci[mi][nj][2*h]     *= -ratio;
                        acci[mi][nj][2*h + 1] *= -ratio;
                    }
                }
        }
        __syncthreads();

        int cn = c + STAGES;
        if (cn < NCHUNK) segload(cn, st);
    }

    // epilogue: r = invs2*acc_r ; i = -invs2*acc_i ; then rope/split or fp32 write
    int head = n0 >> 7;
#pragma unroll
    for (int mi = 0; mi < 4; mi++) {
#pragma unroll
        for (int h = 0; h < 2; h++) {
            int row = m0 + warp_m * 64 + mi * 16 + tq + h * 8;
            float fsr = tk.invs2[row];
            float fsi = -fsr;
            if (tk.mode < 0) {
                float* fr = tk.fr + (size_t)row * HH + n0 + warp_n * 32;
                float* fi = tk.fi + (size_t)row * HH + n0 + warp_n * 32;
#pragma unroll
                for (int nj = 0; nj < 4; nj++) {
                    float2 o1, o2;
                    o1.x = fsr * accr[mi][nj][2*h];
                    o1.y = fsr * accr[mi][nj][2*h + 1];
                    o2.x = fsi * acci[mi][nj][2*h];
                    o2.y = fsi * acci[mi][nj][2*h + 1];
                    *(float2*)(fr + nj * 8 + 2 * tr) = o1;
                    *(float2*)(fi + nj * 8 + 2 * tr) = o2;
                }
            } else {
                size_t base = ((size_t)head * TT + row) * D2;
#pragma unroll
                for (int nj = 0; nj < 4; nj++) {
                    int d = warp_n * 32 + nj * 8 + 2 * tr;
                    float rx = fsr * accr[mi][nj][2*h];
                    float ry = fsr * accr[mi][nj][2*h + 1];
                    float ix = fsi * acci[mi][nj][2*h];
                    float iy = fsi * acci[mi][nj][2*h + 1];
                    if (tk.mode == 1) {
                        float2 c2 = *(const float2*)&g_cos[row * HD + d];
                        float2 s2 = *(const float2*)&g_sin[row * HD + d];
                        float rr0 = rx * c2.x - ix * s2.x;
                        float ii0 = ix * c2.x + rx * s2.x;
                        float rr1 = ry * c2.y - iy * s2.y;
                        float ii1 = iy * c2.y + ry * s2.y;
                        rx = rr0; ry = rr1; ix = ii0; iy = ii1;
                    }
                    __nv_bfloat16 rh0 = __float2bfloat16_rn(rx);
                    __nv_bfloat16 rh1 = __float2bfloat16_rn(ry);
                    __nv_bfloat16 ih0 = __float2bfloat16_rn(ix);
                    __nv_bfloat16 ih1 = __float2bfloat16_rn(iy);
                    *(uint32_t*)(tk.ghi + base + d) =
                        (uint32_t)*(uint16_t*)&rh0 | ((uint32_t)*(uint16_t*)&rh1 << 16);
                    *(uint32_t*)(tk.glo + base + d) =
                        packbf(rx - __bfloat162float(rh0), ry - __bfloat162float(rh1));
                    *(uint32_t*)(tk.ghi + base + 128 + d) =
                        (uint32_t)*(uint16_t*)&ih0 | ((uint32_t)*(uint16_t*)&ih1 << 16);
                    *(uint32_t*)(tk.glo + base + 128 + d) =
                        packbf(ix - __bfloat162float(ih0), iy - __bfloat162float(ih1));
                }
            }
        }
    }
}

// ======================= HMMA flash attention — 8 warps, pair-split (R10-proven) =======================
#define SB_OFF   196608
#define SB_HALF  576
#define SB_PAIR  1152
#define FSMEM    (196608 + 4 * SB_PAIR * 4)   // 215040

__global__ __launch_bounds__(256, 1) void flash_mma(
    const __nv_bfloat16* __restrict__ qhi, const __nv_bfloat16* __restrict__ qlo,
    const __nv_bfloat16* __restrict__ khi, const __nv_bfloat16* __restrict__ klo,
    const __nv_bfloat16* __restrict__ vhi, const __nv_bfloat16* __restrict__ vlo,
    float* __restrict__ outr, float* __restrict__ outi) {
    extern __shared__ char sm[];
    uint32_t sb = smem_u32(sm);
    float* Sbuf = (float*)(sm + SB_OFF);
    int head = blockIdx.y;
    int qi = (int)gridDim.x - 1 - (int)blockIdx.x;
    int tid = threadIdx.x;
    int warp = tid >> 5, lane = tid & 31;
    int pair = warp >> 1, half = warp & 1;
    int tq = lane >> 2, tr = lane & 3;
    size_t hbase = (size_t)head * TT * D2;

    {
        const char* s0 = (const char*)(qhi + hbase + (size_t)qi * 64 * D2);
        const char* s1 = (const char*)(qlo + hbase + (size_t)qi * 64 * D2);
#pragma unroll
        for (int i = 0; i < 16; i++) {
            int idx = tid + i * 256;
            int mat = idx >> 11, r = (idx >> 5) & 63, g = idx & 31;
            const char* src = (mat == 0 ? s0 : s1) + (size_t)r * 512 + g * 16;
            uint32_t dst = sb + mat * 32768 + SWZ512(r * 512 + g * 16);
            asm volatile("cp.async.cg.shared.global [%0], [%1], 16;" :: "r"(dst), "l"(src));
        }
    }

    int nkb = 2 * (qi + 1);
    const char* kvsrc[4] = {(const char*)(khi + hbase), (const char*)(klo + hbase),
                            (const char*)(vhi + hbase), (const char*)(vlo + hbase)};
    auto loadKV = [&](int kb, int buf) {
        uint32_t base = sb + 65536 + buf * 65536;
#pragma unroll
        for (int i = 0; i < 16; i++) {
            int idx = tid + i * 256;
            int mat = idx >> 10, r = (idx >> 5) & 31, g = idx & 31;
            const char* src = kvsrc[mat] + (size_t)(kb * 32 + r) * 512 + g * 16;
            uint32_t dst = base + mat * 16384 + SWZ512(r * 512 + g * 16);
            asm volatile("cp.async.cg.shared.global [%0], [%1], 16;" :: "r"(dst), "l"(src));
        }
    };
    loadKV(0, 0);
    asm volatile("cp.async.commit_group;");

    float oAcc[16][4];
#pragma unroll
    for (int j = 0; j < 16; j++)
#pragma unroll
        for (int c = 0; c < 4; c++) oAcc[j][c] = 0.f;
    float m0 = -CUDART_INF_F, m1 = -CUDART_INF_F, l0 = 0.f, l1 = 0.f;
    int rowg0 = qi * 64 + pair * 16 + tq;

    for (int kb = 0; kb < nkb; kb++) {
        if (kb + 1 < nkb) {
            loadKV(kb + 1, (kb + 1) & 1);
            asm volatile("cp.async.commit_group;");
            asm volatile("cp.async.wait_group 1;");
        } else {
            asm volatile("cp.async.wait_group 0;");
        }
        __syncthreads();
        uint32_t kv = sb + 65536 + (kb & 1) * 65536;

        float sAcc[4][4];
#pragma unroll
        for (int j = 0; j < 4; j++)
#pragma unroll
            for (int c = 0; c < 4; c++) sAcc[j][c] = 0.f;
#pragma unroll
        for (int pass = 0; pass < 3; pass++) {
            uint32_t qb_ = sb + (pass == 2 ? 32768 : 0);
            uint32_t kb_ = kv + (pass == 1 ? 16384 : 0);
#pragma unroll
            for (int ks0 = 0; ks0 < 8; ks0++) {
                int ks = half * 8 + ks0;
                uint32_t qa[4];
                uint32_t qaddr = qb_ + SWZ512((pair * 16 + (lane & 15)) * 512
                                              + ks * 32 + (lane >> 4) * 16);
                asm volatile("ldmatrix.sync.aligned.m8n8.x4.shared.b16 {%0,%1,%2,%3}, [%4];"
                    : "=r"(qa[0]), "=r"(qa[1]), "=r"(qa[2]), "=r"(qa[3]) : "r"(qaddr));
                uint32_t bfr[4][2];
#pragma unroll
                for (int p = 0; p < 2; p++) {
                    int nr = p * 16 + (lane & 7) + ((lane >> 4) << 3);
                    uint32_t kaddr = kb_ + SWZ512(nr * 512 + ks * 32 + ((lane >> 3) & 1) * 16);
                    asm volatile("ldmatrix.sync.aligned.m8n8.x4.shared.b16 {%0,%1,%2,%3}, [%4];"
                        : "=r"(bfr[2*p][0]), "=r"(bfr[2*p][1]),
                          "=r"(bfr[2*p+1][0]), "=r"(bfr[2*p+1][1]) : "r"(kaddr));
                }
#pragma unroll
                for (int nj = 0; nj < 4; nj++)
                    asm volatile(
                        "mma.sync.aligned.m16n8k16.row.col.f32.bf16.bf16.f32 "
                        "{%0,%1,%2,%3}, {%4,%5,%6,%7}, {%8,%9}, {%0,%1,%2,%3};"
                        : "+f"(sAcc[nj][0]), "+f"(sAcc[nj][1]),
                          "+f"(sAcc[nj][2]), "+f"(sAcc[nj][3])
                        : "r"(qa[0]), "r"(qa[1]), "r"(qa[2]), "r"(qa[3]),
                          "r"(bfr[nj][0]), "r"(bfr[nj][1]));
            }
        }

        {
            float* my = Sbuf + pair * SB_PAIR + half * SB_HALF;
#pragma unroll
            for (int nj = 0; nj < 4; nj++)
#pragma unroll
                for (int c = 0; c < 4; c++)
                    my[(tq + (c >> 1) * 8) * 36 + nj * 8 + tr * 2 + (c & 1)] = sAcc[nj][c];
        }
        __syncthreads();
        {
            const float* b0 = Sbuf + pair * SB_PAIR;
            const float* b1 = b0 + SB_HALF;
#pragma unroll
            for (int nj = 0; nj < 4; nj++)
#pragma unroll
                for (int c = 0; c < 4; c++) {
                    int ix = (tq + (c >> 1) * 8) * 36 + nj * 8 + tr * 2 + (c & 1);
                    sAcc[nj][c] = b0[ix] + b1[ix];
                }
        }

        float mloc0 = -CUDART_INF_F, mloc1 = -CUDART_INF_F;
#pragma unroll
        for (int nj = 0; nj < 4; nj++)
#pragma unroll
            for (int c = 0; c < 4; c++) {
                float sv = sAcc[nj][c] * 0.0625f;
                int col = kb * 32 + nj * 8 + tr * 2 + (c & 1);
                int rg = rowg0 + ((c >> 1) << 3);
                if (col > rg) sv = -1e9f;
                sAcc[nj][c] = sv;
                if (c < 2) mloc0 = fmaxf(mloc0, sv);
                else       mloc1 = fmaxf(mloc1, sv);
            }
        mloc0 = fmaxf(mloc0, __shfl_xor_sync(0xffffffffu, mloc0, 1));
        mloc0 = fmaxf(mloc0, __shfl_xor_sync(0xffffffffu, mloc0, 2));
        mloc1 = fmaxf(mloc1, __shfl_xor_sync(0xffffffffu, mloc1, 1));
        mloc1 = fmaxf(mloc1, __shfl_xor_sync(0xffffffffu, mloc1, 2));
        float mn0 = fmaxf(m0, mloc0), mn1 = fmaxf(m1, mloc1);
        float f0 = __expf(m0 - mn0), f1 = __expf(m1 - mn1);
        m0 = mn0; m1 = mn1;
        float rs0 = 0.f, rs1 = 0.f;
#pragma unroll
        for (int nj = 0; nj < 4; nj++)
#pragma unroll
            for (int c = 0; c < 4; c++) {
                float p = __expf(sAcc[nj][c] - (c < 2 ? mn0 : mn1));
                sAcc[nj][c] = p;
                if (c < 2) rs0 += p; else rs1 += p;
            }
        rs0 += __shfl_xor_sync(0xffffffffu, rs0, 1);
        rs0 += __shfl_xor_sync(0xffffffffu, rs0, 2);
        rs1 += __shfl_xor_sync(0xffffffffu, rs1, 1);
        rs1 += __shfl_xor_sync(0xffffffffu, rs1, 2);
        l0 = l0 * f0 + rs0;
        l1 = l1 * f1 + rs1;
#pragma unroll
        for (int j = 0; j < 16; j++) {
            oAcc[j][0] *= f0; oAcc[j][1] *= f0;
            oAcc[j][2] *= f1; oAcc[j][3] *= f1;
        }

        uint32_t phi[2][4], plo[2][4];
#pragma unroll
        for (int ks2 = 0; ks2 < 2; ks2++) {
            int nb = ks2 * 2;
#pragma unroll
            for (int q = 0; q < 2; q++) {
                float a0 = sAcc[nb][2*q], a1 = sAcc[nb][2*q+1];
                float b0 = sAcc[nb+1][2*q], b1 = sAcc[nb+1][2*q+1];
                phi[ks2][q]     = packbf(a0, a1);
                phi[ks2][q + 2] = packbf(b0, b1);
                float a0h = __bfloat162float(__float2bfloat16_rn(a0));
                float a1h = __bfloat162float(__float2bfloat16_rn(a1));
                float b0h = __bfloat162float(__float2bfloat16_rn(b0));
                float b1h = __bfloat162float(__float2bfloat16_rn(b1));
                plo[ks2][q]     = packbf(a0 - a0h, a1 - a1h);
                plo[ks2][q + 2] = packbf(b0 - b0h, b1 - b1h);
            }
        }

        uint32_t vbh = kv + 32768, vbl = kv + 49152;
#pragma unroll
        for (int ks2 = 0; ks2 < 2; ks2++) {
#pragma unroll
            for (int j = 0; j < 16; j++) {
                int nj = half * 16 + j;
                uint32_t off = SWZ512((ks2 * 16 + (lane & 15)) * 512 + nj * 16);
                uint32_t vh0, vh1, vl0, vl1;
                asm volatile("ldmatrix.sync.aligned.m8n8.x2.trans.shared.b16 {%0,%1}, [%2];"
                    : "=r"(vh0), "=r"(vh1) : "r"(vbh + off));
                asm volatile("ldmatrix.sync.aligned.m8n8.x2.trans.shared.b16 {%0,%1}, [%2];"
                    : "=r"(vl0), "=r"(vl1) : "r"(vbl + off));
                asm volatile(
                    "mma.sync.aligned.m16n8k16.row.col.f32.bf16.bf16.f32 "
                    "{%0,%1,%2,%3}, {%4,%5,%6,%7}, {%8,%9}, {%0,%1,%2,%3};"
                    : "+f"(oAcc[j][0]), "+f"(oAcc[j][1]), "+f"(oAcc[j][2]), "+f"(oAcc[j][3])
                    : "r"(phi[ks2][0]), "r"(phi[ks2][1]), "r"(phi[ks2][2]), "r"(phi[ks2][3]),
                      "r"(vh0), "r"(vh1));
                asm volatile(
                    "mma.sync.aligned.m16n8k16.row.col.f32.bf16.bf16.f32 "
                    "{%0,%1,%2,%3}, {%4,%5,%6,%7}, {%8,%9}, {%0,%1,%2,%3};"
                    : "+f"(oAcc[j][0]), "+f"(oAcc[j][1]), "+f"(oAcc[j][2]), "+f"(oAcc[j][3])
                    : "r"(plo[ks2][0]), "r"(plo[ks2][1]), "r"(plo[ks2][2]), "r"(plo[ks2][3]),
                      "r"(vh0), "r"(vh1));
                asm volatile(
                    "mma.sync.aligned.m16n8k16.row.col.f32.bf16.bf16.f32 "
                    "{%0,%1,%2,%3}, {%4,%5,%6,%7}, {%8,%9}, {%0,%1,%2,%3};"
                    : "+f"(oAcc[j][0]), "+f"(oAcc[j][1]), "+f"(oAcc[j][2]), "+f"(oAcc[j][3])
                    : "r"(phi[ks2][0]), "r"(phi[ks2][1]), "r"(phi[ks2][2]), "r"(phi[ks2][3]),
                      "r"(vl0), "r"(vl1));
            }
        }
        __syncthreads();
    }

    float il0 = 1.0f / l0, il1 = 1.0f / l1;
    int hoff = head * HD;
    int r0 = qi * 64 + pair * 16 + tq;
    float* outp = (half == 0) ? outr : outi;
#pragma unroll
    for (int j = 0; j < 16; j++) {
        int col = j * 8 + tr * 2;
        float2 a = make_float2(oAcc[j][0] * il0, oAcc[j][1] * il0);
        float2 b = make_float2(oAcc[j][2] * il1, oAcc[j][3] * il1);
        *(float2*)(outp + (size_t)r0 * HH + hoff + col) = a;
        *(float2*)(outp + (size_t)(r0 + 8) * HH + hoff + col) = b;
    }
}

// ======================= launch =======================
extern "C" void kernel_launch(void* const* d_in, const int* in_sizes, int n_in,
                              void* d_out, int out_size) {
    const float* hr   = (const float*)d_in[0];
    const float* hi   = (const float*)d_in[1];
    const int*   pos  = (const int*)d_in[2];
    float* out = (float*)d_out;

    __nv_bfloat16 *nr, *ni, *wsp, *qhi, *qlo, *khi, *klo, *vhi, *vlo;
    float *is1, *is2, *is3, *is4, *ar, *ai;
    cudaGetSymbolAddress((void**)&nr,  g_nr);
    cudaGetSymbolAddress((void**)&ni,  g_ni);
    cudaGetSymbolAddress((void**)&is1, g_invs1);
    cudaGetSymbolAddress((void**)&is2, g_invs2);
    cudaGetSymbolAddress((void**)&is3, g_invs3);
    cudaGetSymbolAddress((void**)&is4, g_invs4);
    cudaGetSymbolAddress((void**)&wsp, g_wsp);
    cudaGetSymbolAddress((void**)&ar,  g_ar);
    cudaGetSymbolAddress((void**)&ai,  g_ai);
    cudaGetSymbolAddress((void**)&qhi, g_qhi);
    cudaGetSymbolAddress((void**)&qlo, g_qlo);
    cudaGetSymbolAddress((void**)&khi, g_khi);
    cudaGetSymbolAddress((void**)&klo, g_klo);
    cudaGetSymbolAddress((void**)&vhi, g_vhi);
    cudaGetSymbolAddress((void**)&vlo, g_vlo);
    __nv_bfloat16* ws[16];
    for (int i = 0; i < 16; i++) ws[i] = wsp + (size_t)i * HH * HH;

    // ---- prep
    QuantArgs qa;
    qa.x[0] = hr; qa.x[1] = hi;
    qa.q[0] = nr; qa.q[1] = ni;
    qa.invs[0] = is1; qa.invs[1] = is2;
    rowquant_bf16_kernel<<<dim3(TT, 2), 256>>>(qa);

    cossin_kernel<<<(TT * HD) / 256, 256>>>(pos);

    SplitArgs sa;
    for (int w = 0; w < 8; w++) sa.w[w] = (const float*)d_in[3 + w];
    sa.base = wsp;
    split_kernel<<<dim3((HH * HH) / 1024, 8), 256>>>(sa);

    // ---- QKV: 3 complex-paired tasks, fused rope+split epilogue
    cudaFuncSetAttribute(gemm_cplx, cudaFuncAttributeMaxDynamicSharedMemorySize, GSM);
    CTasks tq;
    // ws layout: [2w]=hi, [2w+1]=lo for w in {Wq_r, Wq_i, Wk_r, Wk_i, Wv_r, Wv_i, Wo_r, Wo_i}
    tq.t[0] = {ws[0], ws[1], ws[2],  ws[3],  is1, is2, qhi, qlo, nullptr, nullptr, 1};
    tq.t[1] = {ws[4], ws[5], ws[6],  ws[7],  is1, is2, khi, klo, nullptr, nullptr, 1};
    tq.t[2] = {ws[8], ws[9], ws[10], ws[11], is1, is2, vhi, vlo, nullptr, nullptr, 0};
    gemm_cplx<<<dim3(HH / 128, TT / 128, 3), 256, GSM>>>(nr, ni, tq);

    // ---- flash attention (8 warps)
    cudaFuncSetAttribute(flash_mma, cudaFuncAttributeMaxDynamicSharedMemorySize, FSMEM);
    flash_mma<<<dim3(TT / 64, NHEAD), 256, FSMEM>>>(qhi, qlo, khi, klo, vhi, vlo, ar, ai);

    // ---- output projection: one paired task, fp32 epilogue
    QuantArgs qb;
    qb.x[0] = ar; qb.x[1] = ai;
    qb.q[0] = nr; qb.q[1] = ni;
    qb.invs[0] = is3; qb.invs[1] = is4;
    rowquant_bf16_kernel<<<dim3(TT, 2), 256>>>(qb);

    CTasks to;
    to.t[0] = {ws[12], ws[13], ws[14], ws[15], is3, is4, nullptr, nullptr,
               out, out + (size_t)TT * HH, -1};
    to.t[1] = to.t[0];
    to.t[2] = to.t[0];
    gemm_cplx<<<dim3(HH / 128, TT / 128, 1), 256, GSM>>>(nr, ni, to);
}

// round 14
// speedup vs baseline: 1.1168x; 1.0267x over previous
#include <cuda_runtime.h>
#include <cuda_bf16.h>
#include <math_constants.h>
#include <cstdint>

#define TT 2048
#define HH 2048
#define NHEAD 16
#define HD 128
#define D2 256

// ======================= scratch (static device globals) =======================
__device__ __nv_bfloat16 g_nr[TT*HH];
__device__ __nv_bfloat16 g_ni[TT*HH];
__device__ float g_invs1[TT];
__device__ float g_invs2[TT];
__device__ float g_invs3[TT];
__device__ float g_invs4[TT];
__device__ __nv_bfloat16 g_wsp[16][HH*HH];
__device__ float g_ar[TT*HH];
__device__ float g_ai[TT*HH];
__device__ float g_cos[TT*HD];
__device__ float g_sin[TT*HD];
__device__ __nv_bfloat16 g_qhi[NHEAD*TT*D2];
__device__ __nv_bfloat16 g_qlo[NHEAD*TT*D2];
__device__ __nv_bfloat16 g_khi[NHEAD*TT*D2];
__device__ __nv_bfloat16 g_klo[NHEAD*TT*D2];
__device__ __nv_bfloat16 g_vhi[NHEAD*TT*D2];
__device__ __nv_bfloat16 g_vlo[NHEAD*TT*D2];

// ======================= helpers =======================
__device__ __forceinline__ uint32_t smem_u32(const void* p) {
    uint32_t a;
    asm("{ .reg .u64 t; cvta.to.shared.u64 t, %1; cvt.u32.u64 %0, t; }" : "=r"(a) : "l"(p));
    return a;
}
#define SWZ128(b) ((b) ^ (((b) >> 3) & 0x70))
#define SWZ512(b) ((b) ^ (((b) >> 5) & 0x70))

__device__ __forceinline__ uint32_t packbf(float a, float b) {
    __nv_bfloat162 t = __floats2bfloat162_rn(a, b);
    return *(uint32_t*)&t;
}

// ======================= prep kernels =======================
struct QuantArgs {
    const float* x[2];
    __nv_bfloat16* q[2];
    float* invs[2];
};

// one row per CTA; 8 elems/thread (2048 = 256*8): single pass, exact same per-element math
__global__ void rowquant_bf16_kernel(QuantArgs a) {
    __shared__ float red[256];
    int sel = blockIdx.y;
    int row = blockIdx.x;
    int tid = threadIdx.x;
    const float* xr = a.x[sel] + (size_t)row * HH + tid * 8;
    float4 v0 = *(const float4*)xr;
    float4 v1 = *(const float4*)(xr + 4);
    float e[8] = {v0.x, v0.y, v0.z, v0.w, v1.x, v1.y, v1.z, v1.w};
    float m = 0.f;
#pragma unroll
    for (int j = 0; j < 8; j++) m = fmaxf(m, fabsf(e[j]));
    red[tid] = m;
    __syncthreads();
    for (int s = 128; s > 0; s >>= 1) {
        if (tid < s) red[tid] = fmaxf(red[tid], red[tid + s]);
        __syncthreads();
    }
    float scale = 127.0f / fmaxf(red[0], 1e-5f);
    if (tid == 0) a.invs[sel][row] = 1.0f / scale;
    __nv_bfloat16 q[8];
#pragma unroll
    for (int j = 0; j < 8; j++) {
        float v = rintf(e[j] * scale);
        v = fminf(fmaxf(v, -128.f), 127.f);
        q[j] = __float2bfloat16_rn(v);
    }
    *(uint4*)(a.q[sel] + (size_t)row * HH + tid * 8) = *(uint4*)q;
}

struct SplitArgs { const float* w[8]; __nv_bfloat16* base; };

// 8 floats/thread: 2x float4 in, 16B hi + 16B lo out
__global__ void split_kernel(SplitArgs a) {
    int wsel = blockIdx.y;
    size_t i = ((size_t)blockIdx.x * 256 + threadIdx.x) * 8;
    const float* w = a.w[wsel] + i;
    float4 v0 = *(const float4*)w;
    float4 v1 = *(const float4*)(w + 4);
    float vv[8] = {v0.x, v0.y, v0.z, v0.w, v1.x, v1.y, v1.z, v1.w};
    __nv_bfloat16 h[8], l[8];
#pragma unroll
    for (int j = 0; j < 8; j++) {
        h[j] = __float2bfloat16_rn(vv[j]);
        l[j] = __float2bfloat16_rn(vv[j] - __bfloat162float(h[j]));
    }
    __nv_bfloat16* hi = a.base + (size_t)(2 * wsel) * HH * HH + i;
    __nv_bfloat16* lo = a.base + (size_t)(2 * wsel + 1) * HH * HH + i;
    *(uint4*)hi = *(uint4*)h;
    *(uint4*)lo = *(uint4*)l;
}

// fp32 chain — matches XLA's fp32-rounded angle + cos/sin (proven; do NOT "improve")
__global__ void cossin_kernel(const int* __restrict__ pos) {
    int idx = blockIdx.x * 256 + threadIdx.x;
    if (idx >= TT * HD) return;
    int t = idx / HD, d = idx % HD;
    float invf = 1.0f / powf(10000.0f, (float)d / (float)HD);
    float f = (float)pos[t] * invf;
    g_cos[idx] = __bfloat162float(__float2bfloat16(cosf(f)));
    g_sin[idx] = __bfloat162float(__float2bfloat16(sinf(f)));
}

// ======================= complex-paired dual-acc GEMM with fused rope/split epilogue =======================
// acc_r = nr@Wr^T + ni@Wi^T ; acc_i = nr@Wi^T - ni@Wr^T (sign via rescale trick per-acc)
// CTA 128x128, 8 warps (2m x 4n), warp tile 64x32, TWO accumulators.
#define STAGES 4
#define NCHUNK 128
#define STG_SZ 49152
#define GSM    (STAGES * STG_SZ)   // 196608

struct CTask {
    const __nv_bfloat16 *Wrhi, *Wrlo, *Wihi, *Wilo;
    const float *invs1, *invs2;
    __nv_bfloat16 *ghi, *glo;
    float *fr, *fi;
    int mode;   // 1 = rope+split, 0 = split, -1 = fp32 pair write
};
struct CTasks { CTask t[3]; };

__device__ __forceinline__ void load_chunk3(uint32_t st,
                                            const __nv_bfloat16* Aseg,
                                            const __nv_bfloat16* Br,
                                            const __nv_bfloat16* Bi,
                                            int m0, int n0, int kc, int tid) {
    const char* ag = (const char*)(Aseg + (size_t)m0 * HH + kc * 64);
    const char* rg = (const char*)(Br + (size_t)n0 * HH + kc * 64);
    const char* ig = (const char*)(Bi + (size_t)n0 * HH + kc * 64);
#pragma unroll
    for (int i = 0; i < 4; i++) {
        int idx = tid + i * 256;
        int r = idx >> 3, g = idx & 7;
        uint32_t so = st + SWZ128(r * 128 + g * 16);
        asm volatile("cp.async.cg.shared.global [%0], [%1], 16;"
                     :: "r"(so), "l"(ag + (size_t)r * 4096 + g * 16));
    }
#pragma unroll
    for (int i = 0; i < 4; i++) {
        int idx = tid + i * 256;
        int r = idx >> 3, g = idx & 7;
        uint32_t so = st + 16384 + SWZ128(r * 128 + g * 16);
        asm volatile("cp.async.cg.shared.global [%0], [%1], 16;"
                     :: "r"(so), "l"(rg + (size_t)r * 4096 + g * 16));
    }
#pragma unroll
    for (int i = 0; i < 4; i++) {
        int idx = tid + i * 256;
        int r = idx >> 3, g = idx & 7;
        uint32_t so = st + 32768 + SWZ128(r * 128 + g * 16);
        asm volatile("cp.async.cg.shared.global [%0], [%1], 16;"
                     :: "r"(so), "l"(ig + (size_t)r * 4096 + g * 16));
    }
}

__device__ __forceinline__ void compute_chunk3(uint32_t st,
                                               int warp_m, int warp_n, int lane,
                                               float (&accr)[4][4][4], float (&acci)[4][4][4]) {
#pragma unroll
    for (int ks = 0; ks < 4; ks++) {
        uint32_t af[4][4];
#pragma unroll
        for (int mi = 0; mi < 4; mi++) {
            int r = warp_m * 64 + mi * 16 + (lane & 15);
            int cb = ks * 32 + (lane >> 4) * 16;
            uint32_t ad = st + SWZ128(r * 128 + cb);
            asm volatile("ldmatrix.sync.aligned.m8n8.x4.shared.b16 {%0,%1,%2,%3}, [%4];"
                : "=r"(af[mi][0]), "=r"(af[mi][1]), "=r"(af[mi][2]), "=r"(af[mi][3])
                : "r"(ad));
        }
        uint32_t br[4][2], bi[4][2];
#pragma unroll
        for (int p = 0; p < 2; p++) {
            int nr_ = warp_n * 32 + p * 16 + (lane & 7) + ((lane >> 4) << 3);
            int cb = ks * 32 + ((lane >> 3) & 1) * 16;
            uint32_t bd = st + 16384 + SWZ128(nr_ * 128 + cb);
            asm volatile("ldmatrix.sync.aligned.m8n8.x4.shared.b16 {%0,%1,%2,%3}, [%4];"
                : "=r"(br[2*p][0]), "=r"(br[2*p][1]), "=r"(br[2*p+1][0]), "=r"(br[2*p+1][1])
                : "r"(bd));
            uint32_t bd2 = st + 32768 + SWZ128(nr_ * 128 + cb);
            asm volatile("ldmatrix.sync.aligned.m8n8.x4.shared.b16 {%0,%1,%2,%3}, [%4];"
                : "=r"(bi[2*p][0]), "=r"(bi[2*p][1]), "=r"(bi[2*p+1][0]), "=r"(bi[2*p+1][1])
                : "r"(bd2));
        }
#pragma unroll
        for (int mi = 0; mi < 4; mi++)
#pragma unroll
            for (int nj = 0; nj < 4; nj++) {
                asm volatile(
                    "mma.sync.aligned.m16n8k16.row.col.f32.bf16.bf16.f32 "
                    "{%0,%1,%2,%3}, {%4,%5,%6,%7}, {%8,%9}, {%0,%1,%2,%3};"
                    : "+f"(accr[mi][nj][0]), "+f"(accr[mi][nj][1]),
                      "+f"(accr[mi][nj][2]), "+f"(accr[mi][nj][3])
                    : "r"(af[mi][0]), "r"(af[mi][1]), "r"(af[mi][2]), "r"(af[mi][3]),
                      "r"(br[nj][0]), "r"(br[nj][1]));
                asm volatile(
                    "mma.sync.aligned.m16n8k16.row.col.f32.bf16.bf16.f32 "
                    "{%0,%1,%2,%3}, {%4,%5,%6,%7}, {%8,%9}, {%0,%1,%2,%3};"
                    : "+f"(acci[mi][nj][0]), "+f"(acci[mi][nj][1]),
                      "+f"(acci[mi][nj][2]), "+f"(acci[mi][nj][3])
                    : "r"(af[mi][0]), "r"(af[mi][1]), "r"(af[mi][2]), "r"(af[mi][3]),
                      "r"(bi[nj][0]), "r"(bi[nj][1]));
            }
    }
}

__global__ __launch_bounds__(256, 1) void gemm_cplx(
    const __nv_bfloat16* __restrict__ A1, const __nv_bfloat16* __restrict__ A2,
    CTasks tasks) {
    extern __shared__ char smem[];
    uint32_t sbase = smem_u32(smem);
    const CTask tk = tasks.t[blockIdx.z];
    int tid = threadIdx.x;
    int wid = tid >> 5, lane = tid & 31;
    int warp_m = wid >> 2, warp_n = wid & 3;
    int m0 = blockIdx.y * 128, n0 = blockIdx.x * 128;
    int tq = lane >> 2, tr = lane & 3;

    float accr[4][4][4], acci[4][4][4];
#pragma unroll
    for (int a = 0; a < 4; a++)
#pragma unroll
        for (int b = 0; b < 4; b++)
#pragma unroll
            for (int c = 0; c < 4; c++) { accr[a][b][c] = 0.f; acci[a][b][c] = 0.f; }

    auto segload = [&](int cn, uint32_t st) {
        int lvl = (cn >> 5) & 1;
        const __nv_bfloat16* Wr = lvl ? tk.Wrlo : tk.Wrhi;
        const __nv_bfloat16* Wi = lvl ? tk.Wilo : tk.Wihi;
        if (cn < 64) load_chunk3(st, A1, Wr, Wi, m0, n0, cn & 31, tid);
        else         load_chunk3(st, A2, Wi, Wr, m0, n0, cn & 31, tid);
        asm volatile("cp.async.commit_group;");
    };

    for (int c = 0; c < STAGES; c++) segload(c, sbase + c * STG_SZ);

    for (int c = 0; c < NCHUNK; c++) {
        int stage = c & (STAGES - 1);
        uint32_t st = sbase + stage * STG_SZ;
        int rem = NCHUNK - 1 - c;
        if (rem >= 3)      asm volatile("cp.async.wait_group 3;");
        else if (rem == 2) asm volatile("cp.async.wait_group 2;");
        else if (rem == 1) asm volatile("cp.async.wait_group 1;");
        else               asm volatile("cp.async.wait_group 0;");
        __syncthreads();

        compute_chunk3(st, warp_m, warp_n, lane, accr, acci);

        if (c == 63) {
#pragma unroll
            for (int mi = 0; mi < 4; mi++)
#pragma unroll
                for (int h = 0; h < 2; h++) {
                    int row = m0 + warp_m * 64 + mi * 16 + tq + h * 8;
                    float ratio = tk.invs1[row] / tk.invs2[row];
#pragma unroll
                    for (int nj = 0; nj < 4; nj++) {
                        accr[mi][nj][2*h]     *=  ratio;
                        accr[mi][nj][2*h + 1] *=  ratio;
                        acci[mi][nj][2*h]     *= -ratio;
                        acci[mi][nj][2*h + 1] *= -ratio;
                    }
                }
        }
        __syncthreads();

        int cn = c + STAGES;
        if (cn < NCHUNK) segload(cn, st);
    }

    int head = n0 >> 7;
#pragma unroll
    for (int mi = 0; mi < 4; mi++) {
#pragma unroll
        for (int h = 0; h < 2; h++) {
            int row = m0 + warp_m * 64 + mi * 16 + tq + h * 8;
            float fsr = tk.invs2[row];
            float fsi = -fsr;
            if (tk.mode < 0) {
                float* fr = tk.fr + (size_t)row * HH + n0 + warp_n * 32;
                float* fi = tk.fi + (size_t)row * HH + n0 + warp_n * 32;
#pragma unroll
                for (int nj = 0; nj < 4; nj++) {
                    float2 o1, o2;
                    o1.x = fsr * accr[mi][nj][2*h];
                    o1.y = fsr * accr[mi][nj][2*h + 1];
                    o2.x = fsi * acci[mi][nj][2*h];
                    o2.y = fsi * acci[mi][nj][2*h + 1];
                    *(float2*)(fr + nj * 8 + 2 * tr) = o1;
                    *(float2*)(fi + nj * 8 + 2 * tr) = o2;
                }
            } else {
                size_t base = ((size_t)head * TT + row) * D2;
#pragma unroll
                for (int nj = 0; nj < 4; nj++) {
                    int d = warp_n * 32 + nj * 8 + 2 * tr;
                    float rx = fsr * accr[mi][nj][2*h];
                    float ry = fsr * accr[mi][nj][2*h + 1];
                    float ix = fsi * acci[mi][nj][2*h];
                    float iy = fsi * acci[mi][nj][2*h + 1];
                    if (tk.mode == 1) {
                        float2 c2 = *(const float2*)&g_cos[row * HD + d];
                        float2 s2 = *(const float2*)&g_sin[row * HD + d];
                        float rr0 = rx * c2.x - ix * s2.x;
                        float ii0 = ix * c2.x + rx * s2.x;
                        float rr1 = ry * c2.y - iy * s2.y;
                        float ii1 = iy * c2.y + ry * s2.y;
                        rx = rr0; ry = rr1; ix = ii0; iy = ii1;
                    }
                    __nv_bfloat16 rh0 = __float2bfloat16_rn(rx);
                    __nv_bfloat16 rh1 = __float2bfloat16_rn(ry);
                    __nv_bfloat16 ih0 = __float2bfloat16_rn(ix);
                    __nv_bfloat16 ih1 = __float2bfloat16_rn(iy);
                    *(uint32_t*)(tk.ghi + base + d) =
                        (uint32_t)*(uint16_t*)&rh0 | ((uint32_t)*(uint16_t*)&rh1 << 16);
                    *(uint32_t*)(tk.glo + base + d) =
                        packbf(rx - __bfloat162float(rh0), ry - __bfloat162float(rh1));
                    *(uint32_t*)(tk.ghi + base + 128 + d) =
                        (uint32_t)*(uint16_t*)&ih0 | ((uint32_t)*(uint16_t*)&ih1 << 16);
                    *(uint32_t*)(tk.glo + base + 128 + d) =
                        packbf(ix - __bfloat162float(ih0), iy - __bfloat162float(ih1));
                }
            }
        }
    }
}

// ======================= HMMA flash attention — 8 warps, pair-split (R10-proven) =======================
#define SB_OFF   196608
#define SB_HALF  576
#define SB_PAIR  1152
#define FSMEM    (196608 + 4 * SB_PAIR * 4)   // 215040

__global__ __launch_bounds__(256, 1) void flash_mma(
    const __nv_bfloat16* __restrict__ qhi, const __nv_bfloat16* __restrict__ qlo,
    const __nv_bfloat16* __restrict__ khi, const __nv_bfloat16* __restrict__ klo,
    const __nv_bfloat16* __restrict__ vhi, const __nv_bfloat16* __restrict__ vlo,
    float* __restrict__ outr, float* __restrict__ outi) {
    extern __shared__ char sm[];
    uint32_t sb = smem_u32(sm);
    float* Sbuf = (float*)(sm + SB_OFF);
    int head = blockIdx.y;
    int qi = (int)gridDim.x - 1 - (int)blockIdx.x;
    int tid = threadIdx.x;
    int warp = tid >> 5, lane = tid & 31;
    int pair = warp >> 1, half = warp & 1;
    int tq = lane >> 2, tr = lane & 3;
    size_t hbase = (size_t)head * TT * D2;

    {
        const char* s0 = (const char*)(qhi + hbase + (size_t)qi * 64 * D2);
        const char* s1 = (const char*)(qlo + hbase + (size_t)qi * 64 * D2);
#pragma unroll
        for (int i = 0; i < 16; i++) {
            int idx = tid + i * 256;
            int mat = idx >> 11, r = (idx >> 5) & 63, g = idx & 31;
            const char* src = (mat == 0 ? s0 : s1) + (size_t)r * 512 + g * 16;
            uint32_t dst = sb + mat * 32768 + SWZ512(r * 512 + g * 16);
            asm volatile("cp.async.cg.shared.global [%0], [%1], 16;" :: "r"(dst), "l"(src));
        }
    }

    int nkb = 2 * (qi + 1);
    const char* kvsrc[4] = {(const char*)(khi + hbase), (const char*)(klo + hbase),
                            (const char*)(vhi + hbase), (const char*)(vlo + hbase)};
    auto loadKV = [&](int kb, int buf) {
        uint32_t base = sb + 65536 + buf * 65536;
#pragma unroll
        for (int i = 0; i < 16; i++) {
            int idx = tid + i * 256;
            int mat = idx >> 10, r = (idx >> 5) & 31, g = idx & 31;
            const char* src = kvsrc[mat] + (size_t)(kb * 32 + r) * 512 + g * 16;
            uint32_t dst = base + mat * 16384 + SWZ512(r * 512 + g * 16);
            asm volatile("cp.async.cg.shared.global [%0], [%1], 16;" :: "r"(dst), "l"(src));
        }
    };
    loadKV(0, 0);
    asm volatile("cp.async.commit_group;");

    float oAcc[16][4];
#pragma unroll
    for (int j = 0; j < 16; j++)
#pragma unroll
        for (int c = 0; c < 4; c++) oAcc[j][c] = 0.f;
    float m0 = -CUDART_INF_F, m1 = -CUDART_INF_F, l0 = 0.f, l1 = 0.f;
    int rowg0 = qi * 64 + pair * 16 + tq;

    for (int kb = 0; kb < nkb; kb++) {
        if (kb + 1 < nkb) {
            loadKV(kb + 1, (kb + 1) & 1);
            asm volatile("cp.async.commit_group;");
            asm volatile("cp.async.wait_group 1;");
        } else {
            asm volatile("cp.async.wait_group 0;");
        }
        __syncthreads();
        uint32_t kv = sb + 65536 + (kb & 1) * 65536;

        float sAcc[4][4];
#pragma unroll
        for (int j = 0; j < 4; j++)
#pragma unroll
            for (int c = 0; c < 4; c++) sAcc[j][c] = 0.f;
#pragma unroll
        for (int pass = 0; pass < 3; pass++) {
            uint32_t qb_ = sb + (pass == 2 ? 32768 : 0);
            uint32_t kb_ = kv + (pass == 1 ? 16384 : 0);
#pragma unroll
            for (int ks0 = 0; ks0 < 8; ks0++) {
                int ks = half * 8 + ks0;
                uint32_t qa[4];
                uint32_t qaddr = qb_ + SWZ512((pair * 16 + (lane & 15)) * 512
                                              + ks * 32 + (lane >> 4) * 16);
                asm volatile("ldmatrix.sync.aligned.m8n8.x4.shared.b16 {%0,%1,%2,%3}, [%4];"
                    : "=r"(qa[0]), "=r"(qa[1]), "=r"(qa[2]), "=r"(qa[3]) : "r"(qaddr));
                uint32_t bfr[4][2];
#pragma unroll
                for (int p = 0; p < 2; p++) {
                    int nr = p * 16 + (lane & 7) + ((lane >> 4) << 3);
                    uint32_t kaddr = kb_ + SWZ512(nr * 512 + ks * 32 + ((lane >> 3) & 1) * 16);
                    asm volatile("ldmatrix.sync.aligned.m8n8.x4.shared.b16 {%0,%1,%2,%3}, [%4];"
                        : "=r"(bfr[2*p][0]), "=r"(bfr[2*p][1]),
                          "=r"(bfr[2*p+1][0]), "=r"(bfr[2*p+1][1]) : "r"(kaddr));
                }
#pragma unroll
                for (int nj = 0; nj < 4; nj++)
                    asm volatile(
                        "mma.sync.aligned.m16n8k16.row.col.f32.bf16.bf16.f32 "
                        "{%0,%1,%2,%3}, {%4,%5,%6,%7}, {%8,%9}, {%0,%1,%2,%3};"
                        : "+f"(sAcc[nj][0]), "+f"(sAcc[nj][1]),
                          "+f"(sAcc[nj][2]), "+f"(sAcc[nj][3])
                        : "r"(qa[0]), "r"(qa[1]), "r"(qa[2]), "r"(qa[3]),
                          "r"(bfr[nj][0]), "r"(bfr[nj][1]));
            }
        }

        {
            float* my = Sbuf + pair * SB_PAIR + half * SB_HALF;
#pragma unroll
            for (int nj = 0; nj < 4; nj++)
#pragma unroll
                for (int c = 0; c < 4; c++)
                    my[(tq + (c >> 1) * 8) * 36 + nj * 8 + tr * 2 + (c & 1)] = sAcc[nj][c];
        }
        __syncthreads();
        {
            const float* b0 = Sbuf + pair * SB_PAIR;
            const float* b1 = b0 + SB_HALF;
#pragma unroll
            for (int nj = 0; nj < 4; nj++)
#pragma unroll
                for (int c = 0; c < 4; c++) {
                    int ix = (tq + (c >> 1) * 8) * 36 + nj * 8 + tr * 2 + (c & 1);
                    sAcc[nj][c] = b0[ix] + b1[ix];
                }
        }

        float mloc0 = -CUDART_INF_F, mloc1 = -CUDART_INF_F;
#pragma unroll
        for (int nj = 0; nj < 4; nj++)
#pragma unroll
            for (int c = 0; c < 4; c++) {
                float sv = sAcc[nj][c] * 0.0625f;
                int col = kb * 32 + nj * 8 + tr * 2 + (c & 1);
                int rg = rowg0 + ((c >> 1) << 3);
                if (col > rg) sv = -1e9f;
                sAcc[nj][c] = sv;
                if (c < 2) mloc0 = fmaxf(mloc0, sv);
                else       mloc1 = fmaxf(mloc1, sv);
            }
        mloc0 = fmaxf(mloc0, __shfl_xor_sync(0xffffffffu, mloc0, 1));
        mloc0 = fmaxf(mloc0, __shfl_xor_sync(0xffffffffu, mloc0, 2));
        mloc1 = fmaxf(mloc1, __shfl_xor_sync(0xffffffffu, mloc1, 1));
        mloc1 = fmaxf(mloc1, __shfl_xor_sync(0xffffffffu, mloc1, 2));
        float mn0 = fmaxf(m0, mloc0), mn1 = fmaxf(m1, mloc1);
        float f0 = __expf(m0 - mn0), f1 = __expf(m1 - mn1);
        m0 = mn0; m1 = mn1;
        float rs0 = 0.f, rs1 = 0.f;
#pragma unroll
        for (int nj = 0; nj < 4; nj++)
#pragma unroll
            for (int c = 0; c < 4; c++) {
                float p = __expf(sAcc[nj][c] - (c < 2 ? mn0 : mn1));
                sAcc[nj][c] = p;
                if (c < 2) rs0 += p; else rs1 += p;
            }
        rs0 += __shfl_xor_sync(0xffffffffu, rs0, 1);
        rs0 += __shfl_xor_sync(0xffffffffu, rs0, 2);
        rs1 += __shfl_xor_sync(0xffffffffu, rs1, 1);
        rs1 += __shfl_xor_sync(0xffffffffu, rs1, 2);
        l0 = l0 * f0 + rs0;
        l1 = l1 * f1 + rs1;
#pragma unroll
        for (int j = 0; j < 16; j++) {
            oAcc[j][0] *= f0; oAcc[j][1] *= f0;
            oAcc[j][2] *= f1; oAcc[j][3] *= f1;
        }

        uint32_t phi[2][4], plo[2][4];
#pragma unroll
        for (int ks2 = 0; ks2 < 2; ks2++) {
            int nb = ks2 * 2;
#pragma unroll
            for (int q = 0; q < 2; q++) {
                float a0 = sAcc[nb][2*q], a1 = sAcc[nb][2*q+1];
                float b0 = sAcc[nb+1][2*q], b1 = sAcc[nb+1][2*q+1];
                phi[ks2][q]     = packbf(a0, a1);
                phi[ks2][q + 2] = packbf(b0, b1);
                float a0h = __bfloat162float(__float2bfloat16_rn(a0));
                float a1h = __bfloat162float(__float2bfloat16_rn(a1));
                float b0h = __bfloat162float(__float2bfloat16_rn(b0));
                float b1h = __bfloat162float(__float2bfloat16_rn(b1));
                plo[ks2][q]     = packbf(a0 - a0h, a1 - a1h);
                plo[ks2][q + 2] = packbf(b0 - b0h, b1 - b1h);
            }
        }

        uint32_t vbh = kv + 32768, vbl = kv + 49152;
#pragma unroll
        for (int ks2 = 0; ks2 < 2; ks2++) {
#pragma unroll
            for (int j = 0; j < 16; j++) {
                int nj = half * 16 + j;
                uint32_t off = SWZ512((ks2 * 16 + (lane & 15)) * 512 + nj * 16);
                uint32_t vh0, vh1, vl0, vl1;
                asm volatile("ldmatrix.sync.aligned.m8n8.x2.trans.shared.b16 {%0,%1}, [%2];"
                    : "=r"(vh0), "=r"(vh1) : "r"(vbh + off));
                asm volatile("ldmatrix.sync.aligned.m8n8.x2.trans.shared.b16 {%0,%1}, [%2];"
                    : "=r"(vl0), "=r"(vl1) : "r"(vbl + off));
                asm volatile(
                    "mma.sync.aligned.m16n8k16.row.col.f32.bf16.bf16.f32 "
                    "{%0,%1,%2,%3}, {%4,%5,%6,%7}, {%8,%9}, {%0,%1,%2,%3};"
                    : "+f"(oAcc[j][0]), "+f"(oAcc[j][1]), "+f"(oAcc[j][2]), "+f"(oAcc[j][3])
                    : "r"(phi[ks2][0]), "r"(phi[ks2][1]), "r"(phi[ks2][2]), "r"(phi[ks2][3]),
                      "r"(vh0), "r"(vh1));
                asm volatile(
                    "mma.sync.aligned.m16n8k16.row.col.f32.bf16.bf16.f32 "
                    "{%0,%1,%2,%3}, {%4,%5,%6,%7}, {%8,%9}, {%0,%1,%2,%3};"
                    : "+f"(oAcc[j][0]), "+f"(oAcc[j][1]), "+f"(oAcc[j][2]), "+f"(oAcc[j][3])
                    : "r"(plo[ks2][0]), "r"(plo[ks2][1]), "r"(plo[ks2][2]), "r"(plo[ks2][3]),
                      "r"(vh0), "r"(vh1));
                asm volatile(
                    "mma.sync.aligned.m16n8k16.row.col.f32.bf16.bf16.f32 "
                    "{%0,%1,%2,%3}, {%4,%5,%6,%7}, {%8,%9}, {%0,%1,%2,%3};"
                    : "+f"(oAcc[j][0]), "+f"(oAcc[j][1]), "+f"(oAcc[j][2]), "+f"(oAcc[j][3])
                    : "r"(phi[ks2][0]), "r"(phi[ks2][1]), "r"(phi[ks2][2]), "r"(phi[ks2][3]),
                      "r"(vl0), "r"(vl1));
            }
        }
        __syncthreads();
    }

    float il0 = 1.0f / l0, il1 = 1.0f / l1;
    int hoff = head * HD;
    int r0 = qi * 64 + pair * 16 + tq;
    float* outp = (half == 0) ? outr : outi;
#pragma unroll
    for (int j = 0; j < 16; j++) {
        int col = j * 8 + tr * 2;
        float2 a = make_float2(oAcc[j][0] * il0, oAcc[j][1] * il0);
        float2 b = make_float2(oAcc[j][2] * il1, oAcc[j][3] * il1);
        *(float2*)(outp + (size_t)r0 * HH + hoff + col) = a;
        *(float2*)(outp + (size_t)(r0 + 8) * HH + hoff + col) = b;
    }
}

// ======================= launch =======================
extern "C" void kernel_launch(void* const* d_in, const int* in_sizes, int n_in,
                              void* d_out, int out_size) {
    const float* hr   = (const float*)d_in[0];
    const float* hi   = (const float*)d_in[1];
    const int*   pos  = (const int*)d_in[2];
    float* out = (float*)d_out;

    __nv_bfloat16 *nr, *ni, *wsp, *qhi, *qlo, *khi, *klo, *vhi, *vlo;
    float *is1, *is2, *is3, *is4, *ar, *ai;
    cudaGetSymbolAddress((void**)&nr,  g_nr);
    cudaGetSymbolAddress((void**)&ni,  g_ni);
    cudaGetSymbolAddress((void**)&is1, g_invs1);
    cudaGetSymbolAddress((void**)&is2, g_invs2);
    cudaGetSymbolAddress((void**)&is3, g_invs3);
    cudaGetSymbolAddress((void**)&is4, g_invs4);
    cudaGetSymbolAddress((void**)&wsp, g_wsp);
    cudaGetSymbolAddress((void**)&ar,  g_ar);
    cudaGetSymbolAddress((void**)&ai,  g_ai);
    cudaGetSymbolAddress((void**)&qhi, g_qhi);
    cudaGetSymbolAddress((void**)&qlo, g_qlo);
    cudaGetSymbolAddress((void**)&khi, g_khi);
    cudaGetSymbolAddress((void**)&klo, g_klo);
    cudaGetSymbolAddress((void**)&vhi, g_vhi);
    cudaGetSymbolAddress((void**)&vlo, g_vlo);
    __nv_bfloat16* ws[16];
    for (int i = 0; i < 16; i++) ws[i] = wsp + (size_t)i * HH * HH;

    // ---- prep
    QuantArgs qa;
    qa.x[0] = hr; qa.x[1] = hi;
    qa.q[0] = nr; qa.q[1] = ni;
    qa.invs[0] = is1; qa.invs[1] = is2;
    rowquant_bf16_kernel<<<dim3(TT, 2), 256>>>(qa);

    cossin_kernel<<<(TT * HD) / 256, 256>>>(pos);

    SplitArgs sa;
    for (int w = 0; w < 8; w++) sa.w[w] = (const float*)d_in[3 + w];
    sa.base = wsp;
    split_kernel<<<dim3((HH * HH) / 2048, 8), 256>>>(sa);

    // ---- QKV: 3 complex-paired tasks, fused rope+split epilogue
    cudaFuncSetAttribute(gemm_cplx, cudaFuncAttributeMaxDynamicSharedMemorySize, GSM);
    CTasks tq;
    tq.t[0] = {ws[0], ws[1], ws[2],  ws[3],  is1, is2, qhi, qlo, nullptr, nullptr, 1};
    tq.t[1] = {ws[4], ws[5], ws[6],  ws[7],  is1, is2, khi, klo, nullptr, nullptr, 1};
    tq.t[2] = {ws[8], ws[9], ws[10], ws[11], is1, is2, vhi, vlo, nullptr, nullptr, 0};
    gemm_cplx<<<dim3(HH / 128, TT / 128, 3), 256, GSM>>>(nr, ni, tq);

    // ---- flash attention (8 warps)
    cudaFuncSetAttribute(flash_mma, cudaFuncAttributeMaxDynamicSharedMemorySize, FSMEM);
    flash_mma<<<dim3(TT / 64, NHEAD), 256, FSMEM>>>(qhi, qlo, khi, klo, vhi, vlo, ar, ai);

    // ---- output projection: one paired task, fp32 epilogue
    QuantArgs qb;
    qb.x[0] = ar; qb.x[1] = ai;
    qb.q[0] = nr; qb.q[1] = ni;
    qb.invs[0] = is3; qb.invs[1] = is4;
    rowquant_bf16_kernel<<<dim3(TT, 2), 256>>>(qb);

    CTasks to;
    to.t[0] = {ws[12], ws[13], ws[14], ws[15], is3, is4, nullptr, nullptr,
               out, out + (size_t)TT * HH, -1};
    to.t[1] = to.t[0];
    to.t[2] = to.t[0];
    gemm_cplx<<<dim3(HH / 128, TT / 128, 1), 256, GSM>>>(nr, ni, to);
}

// round 15
// speedup vs baseline: 1.1815x; 1.0579x over previous
#include <cuda_runtime.h>
#include <cuda_bf16.h>
#include <math_constants.h>
#include <cstdint>

#define TT 2048
#define HH 2048
#define NHEAD 16
#define HD 128
#define D2 256

// ======================= scratch (static device globals) =======================
__device__ __nv_bfloat16 g_nr[TT*HH];
__device__ __nv_bfloat16 g_ni[TT*HH];
__device__ float g_invs1[TT];
__device__ float g_invs2[TT];
__device__ float g_invs3[TT];
__device__ float g_invs4[TT];
__device__ __nv_bfloat16 g_wsp[16][HH*HH];
__device__ float g_ar[TT*HH];
__device__ float g_ai[TT*HH];
__device__ float g_cos[TT*HD];
__device__ float g_sin[TT*HD];
__device__ __nv_bfloat16 g_qhi[NHEAD*TT*D2];
__device__ __nv_bfloat16 g_qlo[NHEAD*TT*D2];
__device__ __nv_bfloat16 g_khi[NHEAD*TT*D2];
__device__ __nv_bfloat16 g_klo[NHEAD*TT*D2];
__device__ __nv_bfloat16 g_vhi[NHEAD*TT*D2];
__device__ __nv_bfloat16 g_vlo[NHEAD*TT*D2];

// ======================= helpers =======================
__device__ __forceinline__ uint32_t smem_u32(const void* p) {
    uint32_t a;
    asm("{ .reg .u64 t; cvta.to.shared.u64 t, %1; cvt.u32.u64 %0, t; }" : "=r"(a) : "l"(p));
    return a;
}
#define SWZ128(b) ((b) ^ (((b) >> 3) & 0x70))
#define SWZ512(b) ((b) ^ (((b) >> 5) & 0x70))

__device__ __forceinline__ uint32_t packbf(float a, float b) {
    __nv_bfloat162 t = __floats2bfloat162_rn(a, b);
    return *(uint32_t*)&t;
}

// ======================= prep kernels =======================
struct QuantArgs {
    const float* x[2];
    __nv_bfloat16* q[2];
    float* invs[2];
};

__global__ void rowquant_bf16_kernel(QuantArgs a) {
    __shared__ float red[256];
    int sel = blockIdx.y;
    int row = blockIdx.x;
    int tid = threadIdx.x;
    const float* xr = a.x[sel] + (size_t)row * HH + tid * 8;
    float4 v0 = *(const float4*)xr;
    float4 v1 = *(const float4*)(xr + 4);
    float e[8] = {v0.x, v0.y, v0.z, v0.w, v1.x, v1.y, v1.z, v1.w};
    float m = 0.f;
#pragma unroll
    for (int j = 0; j < 8; j++) m = fmaxf(m, fabsf(e[j]));
    red[tid] = m;
    __syncthreads();
    for (int s = 128; s > 0; s >>= 1) {
        if (tid < s) red[tid] = fmaxf(red[tid], red[tid + s]);
        __syncthreads();
    }
    float scale = 127.0f / fmaxf(red[0], 1e-5f);
    if (tid == 0) a.invs[sel][row] = 1.0f / scale;
    __nv_bfloat16 q[8];
#pragma unroll
    for (int j = 0; j < 8; j++) {
        float v = rintf(e[j] * scale);
        v = fminf(fmaxf(v, -128.f), 127.f);
        q[j] = __float2bfloat16_rn(v);
    }
    *(uint4*)(a.q[sel] + (size_t)row * HH + tid * 8) = *(uint4*)q;
}

struct SplitArgs { const float* w[8]; __nv_bfloat16* base; };

__global__ void split_kernel(SplitArgs a) {
    int wsel = blockIdx.y;
    size_t i = ((size_t)blockIdx.x * 256 + threadIdx.x) * 8;
    const float* w = a.w[wsel] + i;
    float4 v0 = *(const float4*)w;
    float4 v1 = *(const float4*)(w + 4);
    float vv[8] = {v0.x, v0.y, v0.z, v0.w, v1.x, v1.y, v1.z, v1.w};
    __nv_bfloat16 h[8], l[8];
#pragma unroll
    for (int j = 0; j < 8; j++) {
        h[j] = __float2bfloat16_rn(vv[j]);
        l[j] = __float2bfloat16_rn(vv[j] - __bfloat162float(h[j]));
    }
    __nv_bfloat16* hi = a.base + (size_t)(2 * wsel) * HH * HH + i;
    __nv_bfloat16* lo = a.base + (size_t)(2 * wsel + 1) * HH * HH + i;
    *(uint4*)hi = *(uint4*)h;
    *(uint4*)lo = *(uint4*)l;
}

// fp32 chain — matches XLA's fp32-rounded angle + cos/sin (proven; do NOT "improve")
__global__ void cossin_kernel(const int* __restrict__ pos) {
    int idx = blockIdx.x * 256 + threadIdx.x;
    if (idx >= TT * HD) return;
    int t = idx / HD, d = idx % HD;
    float invf = 1.0f / powf(10000.0f, (float)d / (float)HD);
    float f = (float)pos[t] * invf;
    g_cos[idx] = __bfloat162float(__float2bfloat16(cosf(f)));
    g_sin[idx] = __bfloat162float(__float2bfloat16(sinf(f)));
}

// ======================= complex-paired GEMM, merged-level 80K chunks =======================
// acc_r = nr@Wr^T + ni@Wi^T ; acc_i = nr@Wi^T - ni@Wr^T (sign via rescale trick)
// CTA 128x128, 8 warps (2m x 4n), warp tile 64x32, TWO accumulators.
// chunk: A(16K) + W0..W3(64K) = 80K; per ks: 4 A-ldm + 8 B-ldm + 64 MMA. 2-stage ring.
#define STAGES 2
#define NCHUNK 64          // 2 A-parts x 32 K-chunks of 64 (both W-levels per chunk)
#define STG_SZ 81920
#define GSM    (STAGES * STG_SZ)   // 163840

struct CTask {
    const __nv_bfloat16 *Wrhi, *Wrlo, *Wihi, *Wilo;
    const float *invs1, *invs2;
    __nv_bfloat16 *ghi, *glo;
    float *fr, *fi;
    int mode;   // 1 = rope+split, 0 = split, -1 = fp32 pair write
};
struct CTasks { CTask t[3]; };

__device__ __forceinline__ void load_chunk5(uint32_t st,
                                            const __nv_bfloat16* Aseg,
                                            const __nv_bfloat16* W0,
                                            const __nv_bfloat16* W1,
                                            const __nv_bfloat16* W2,
                                            const __nv_bfloat16* W3,
                                            int m0, int n0, int kc, int tid) {
    const char* ag = (const char*)(Aseg + (size_t)m0 * HH + kc * 64);
    const char* wg[4] = {
        (const char*)(W0 + (size_t)n0 * HH + kc * 64),
        (const char*)(W1 + (size_t)n0 * HH + kc * 64),
        (const char*)(W2 + (size_t)n0 * HH + kc * 64),
        (const char*)(W3 + (size_t)n0 * HH + kc * 64)};
#pragma unroll
    for (int i = 0; i < 4; i++) {   // A: 128 rows x 8 x 16B
        int idx = tid + i * 256;
        int r = idx >> 3, g = idx & 7;
        uint32_t so = st + SWZ128(r * 128 + g * 16);
        asm volatile("cp.async.cg.shared.global [%0], [%1], 16;"
                     :: "r"(so), "l"(ag + (size_t)r * 4096 + g * 16));
    }
#pragma unroll
    for (int w = 0; w < 4; w++) {
        uint32_t base = st + 16384 * (w + 1);
#pragma unroll
        for (int i = 0; i < 4; i++) {
            int idx = tid + i * 256;
            int r = idx >> 3, g = idx & 7;
            uint32_t so = base + SWZ128(r * 128 + g * 16);
            asm volatile("cp.async.cg.shared.global [%0], [%1], 16;"
                         :: "r"(so), "l"(wg[w] + (size_t)r * 4096 + g * 16));
        }
    }
}

// one K=64 chunk: A frags loaded once; 4 W matrices (r-hi, r-lo, i-hi, i-lo) consumed
__device__ __forceinline__ void compute_chunk5(uint32_t st,
                                               int warp_m, int warp_n, int lane,
                                               float (&accr)[4][4][4], float (&acci)[4][4][4]) {
#pragma unroll
    for (int ks = 0; ks < 4; ks++) {
        uint32_t af[4][4];
#pragma unroll
        for (int mi = 0; mi < 4; mi++) {
            int r = warp_m * 64 + mi * 16 + (lane & 15);
            int cb = ks * 32 + (lane >> 4) * 16;
            uint32_t ad = st + SWZ128(r * 128 + cb);
            asm volatile("ldmatrix.sync.aligned.m8n8.x4.shared.b16 {%0,%1,%2,%3}, [%4];"
                : "=r"(af[mi][0]), "=r"(af[mi][1]), "=r"(af[mi][2]), "=r"(af[mi][3])
                : "r"(ad));
        }
#pragma unroll
        for (int lvl = 0; lvl < 2; lvl++) {
            // acc_r matrix at slot lvl, acc_i matrix at slot 2+lvl
#pragma unroll
            for (int which = 0; which < 2; which++) {
                uint32_t sb = st + 16384 * (1 + which * 2 + lvl);
                uint32_t bf[4][2];
#pragma unroll
                for (int p = 0; p < 2; p++) {
                    int nr_ = warp_n * 32 + p * 16 + (lane & 7) + ((lane >> 4) << 3);
                    int cb = ks * 32 + ((lane >> 3) & 1) * 16;
                    uint32_t bd = sb + SWZ128(nr_ * 128 + cb);
                    asm volatile("ldmatrix.sync.aligned.m8n8.x4.shared.b16 {%0,%1,%2,%3}, [%4];"
                        : "=r"(bf[2*p][0]), "=r"(bf[2*p][1]),
                          "=r"(bf[2*p+1][0]), "=r"(bf[2*p+1][1])
                        : "r"(bd));
                }
                if (which == 0) {
#pragma unroll
                    for (int mi = 0; mi < 4; mi++)
#pragma unroll
                        for (int nj = 0; nj < 4; nj++)
                            asm volatile(
                                "mma.sync.aligned.m16n8k16.row.col.f32.bf16.bf16.f32 "
                                "{%0,%1,%2,%3}, {%4,%5,%6,%7}, {%8,%9}, {%0,%1,%2,%3};"
                                : "+f"(accr[mi][nj][0]), "+f"(accr[mi][nj][1]),
                                  "+f"(accr[mi][nj][2]), "+f"(accr[mi][nj][3])
                                : "r"(af[mi][0]), "r"(af[mi][1]), "r"(af[mi][2]), "r"(af[mi][3]),
                                  "r"(bf[nj][0]), "r"(bf[nj][1]));
                } else {
#pragma unroll
                    for (int mi = 0; mi < 4; mi++)
#pragma unroll
                        for (int nj = 0; nj < 4; nj++)
                            asm volatile(
                                "mma.sync.aligned.m16n8k16.row.col.f32.bf16.bf16.f32 "
                                "{%0,%1,%2,%3}, {%4,%5,%6,%7}, {%8,%9}, {%0,%1,%2,%3};"
                                : "+f"(acci[mi][nj][0]), "+f"(acci[mi][nj][1]),
                                  "+f"(acci[mi][nj][2]), "+f"(acci[mi][nj][3])
                                : "r"(af[mi][0]), "r"(af[mi][1]), "r"(af[mi][2]), "r"(af[mi][3]),
                                  "r"(bf[nj][0]), "r"(bf[nj][1]));
                }
            }
        }
    }
}

__global__ __launch_bounds__(256, 1) void gemm_cplx(
    const __nv_bfloat16* __restrict__ A1, const __nv_bfloat16* __restrict__ A2,
    CTasks tasks) {
    extern __shared__ char smem[];
    uint32_t sbase = smem_u32(smem);
    const CTask tk = tasks.t[blockIdx.z];
    int tid = threadIdx.x;
    int wid = tid >> 5, lane = tid & 31;
    int warp_m = wid >> 2, warp_n = wid & 3;
    int m0 = blockIdx.y * 128, n0 = blockIdx.x * 128;
    int tq = lane >> 2, tr = lane & 3;

    float accr[4][4][4], acci[4][4][4];
#pragma unroll
    for (int a = 0; a < 4; a++)
#pragma unroll
        for (int b = 0; b < 4; b++)
#pragma unroll
            for (int c = 0; c < 4; c++) { accr[a][b][c] = 0.f; acci[a][b][c] = 0.f; }

    // chunk c: c<32 -> A1, r-slots=Wr(hi,lo), i-slots=Wi(hi,lo); c>=32 -> A2, roles swap
    auto segload = [&](int cn, uint32_t st) {
        if (cn < 32)
            load_chunk5(st, A1, tk.Wrhi, tk.Wrlo, tk.Wihi, tk.Wilo, m0, n0, cn & 31, tid);
        else
            load_chunk5(st, A2, tk.Wihi, tk.Wilo, tk.Wrhi, tk.Wrlo, m0, n0, cn & 31, tid);
        asm volatile("cp.async.commit_group;");
    };

    segload(0, sbase);
    segload(1, sbase + STG_SZ);

    for (int c = 0; c < NCHUNK; c++) {
        uint32_t st = sbase + (c & 1) * STG_SZ;
        if (c < NCHUNK - 1) asm volatile("cp.async.wait_group 1;");
        else                asm volatile("cp.async.wait_group 0;");
        __syncthreads();

        compute_chunk5(st, warp_m, warp_n, lane, accr, acci);

        if (c == 31) {
            // acc_r holds nr@(Wrhi+Wrlo): *= +invs1/invs2 ; acc_i holds nr@(Wihi+Wilo): *= -invs1/invs2
#pragma unroll
            for (int mi = 0; mi < 4; mi++)
#pragma unroll
                for (int h = 0; h < 2; h++) {
                    int row = m0 + warp_m * 64 + mi * 16 + tq + h * 8;
                    float ratio = tk.invs1[row] / tk.invs2[row];
#pragma unroll
                    for (int nj = 0; nj < 4; nj++) {
                        accr[mi][nj][2*h]     *=  ratio;
                        accr[mi][nj][2*h + 1] *=  ratio;
                        acci[mi][nj][2*h]     *= -ratio;
                        acci[mi][nj][2*h + 1] *= -ratio;
                    }
                }
        }
        __syncthreads();

        int cn = c + STAGES;
        if (cn < NCHUNK) segload(cn, st);
    }

    int head = n0 >> 7;
#pragma unroll
    for (int mi = 0; mi < 4; mi++) {
#pragma unroll
        for (int h = 0; h < 2; h++) {
            int row = m0 + warp_m * 64 + mi * 16 + tq + h * 8;
            float fsr = tk.invs2[row];
            float fsi = -fsr;
            if (tk.mode < 0) {
                float* fr = tk.fr + (size_t)row * HH + n0 + warp_n * 32;
                float* fi = tk.fi + (size_t)row * HH + n0 + warp_n * 32;
#pragma unroll
                for (int nj = 0; nj < 4; nj++) {
                    float2 o1, o2;
                    o1.x = fsr * accr[mi][nj][2*h];
                    o1.y = fsr * accr[mi][nj][2*h + 1];
                    o2.x = fsi * acci[mi][nj][2*h];
                    o2.y = fsi * acci[mi][nj][2*h + 1];
                    *(float2*)(fr + nj * 8 + 2 * tr) = o1;
                    *(float2*)(fi + nj * 8 + 2 * tr) = o2;
                }
            } else {
                size_t base = ((size_t)head * TT + row) * D2;
#pragma unroll
                for (int nj = 0; nj < 4; nj++) {
                    int d = warp_n * 32 + nj * 8 + 2 * tr;
                    float rx = fsr * accr[mi][nj][2*h];
                    float ry = fsr * accr[mi][nj][2*h + 1];
                    float ix = fsi * acci[mi][nj][2*h];
                    float iy = fsi * acci[mi][nj][2*h + 1];
                    if (tk.mode == 1) {
                        float2 c2 = *(const float2*)&g_cos[row * HD + d];
                        float2 s2 = *(const float2*)&g_sin[row * HD + d];
                        float rr0 = rx * c2.x - ix * s2.x;
                        float ii0 = ix * c2.x + rx * s2.x;
                        float rr1 = ry * c2.y - iy * s2.y;
                        float ii1 = iy * c2.y + ry * s2.y;
                        rx = rr0; ry = rr1; ix = ii0; iy = ii1;
                    }
                    __nv_bfloat16 rh0 = __float2bfloat16_rn(rx);
                    __nv_bfloat16 rh1 = __float2bfloat16_rn(ry);
                    __nv_bfloat16 ih0 = __float2bfloat16_rn(ix);
                    __nv_bfloat16 ih1 = __float2bfloat16_rn(iy);
                    *(uint32_t*)(tk.ghi + base + d) =
                        (uint32_t)*(uint16_t*)&rh0 | ((uint32_t)*(uint16_t*)&rh1 << 16);
                    *(uint32_t*)(tk.glo + base + d) =
                        packbf(rx - __bfloat162float(rh0), ry - __bfloat162float(rh1));
                    *(uint32_t*)(tk.ghi + base + 128 + d) =
                        (uint32_t)*(uint16_t*)&ih0 | ((uint32_t)*(uint16_t*)&ih1 << 16);
                    *(uint32_t*)(tk.glo + base + 128 + d) =
                        packbf(ix - __bfloat162float(ih0), iy - __bfloat162float(ih1));
                }
            }
        }
    }
}

// ======================= HMMA flash attention — 8 warps, pair-split (R10-proven) =======================
#define SB_OFF   196608
#define SB_HALF  576
#define SB_PAIR  1152
#define FSMEM    (196608 + 4 * SB_PAIR * 4)   // 215040

__global__ __launch_bounds__(256, 1) void flash_mma(
    const __nv_bfloat16* __restrict__ qhi, const __nv_bfloat16* __restrict__ qlo,
    const __nv_bfloat16* __restrict__ khi, const __nv_bfloat16* __restrict__ klo,
    const __nv_bfloat16* __restrict__ vhi, const __nv_bfloat16* __restrict__ vlo,
    float* __restrict__ outr, float* __restrict__ outi) {
    extern __shared__ char sm[];
    uint32_t sb = smem_u32(sm);
    float* Sbuf = (float*)(sm + SB_OFF);
    int head = blockIdx.y;
    int qi = (int)gridDim.x - 1 - (int)blockIdx.x;
    int tid = threadIdx.x;
    int warp = tid >> 5, lane = tid & 31;
    int pair = warp >> 1, half = warp & 1;
    int tq = lane >> 2, tr = lane & 3;
    size_t hbase = (size_t)head * TT * D2;

    {
        const char* s0 = (const char*)(qhi + hbase + (size_t)qi * 64 * D2);
        const char* s1 = (const char*)(qlo + hbase + (size_t)qi * 64 * D2);
#pragma unroll
        for (int i = 0; i < 16; i++) {
            int idx = tid + i * 256;
            int mat = idx >> 11, r = (idx >> 5) & 63, g = idx & 31;
            const char* src = (mat == 0 ? s0 : s1) + (size_t)r * 512 + g * 16;
            uint32_t dst = sb + mat * 32768 + SWZ512(r * 512 + g * 16);
            asm volatile("cp.async.cg.shared.global [%0], [%1], 16;" :: "r"(dst), "l"(src));
        }
    }

    int nkb = 2 * (qi + 1);
    const char* kvsrc[4] = {(const char*)(khi + hbase), (const char*)(klo + hbase),
                            (const char*)(vhi + hbase), (const char*)(vlo + hbase)};
    auto loadKV = [&](int kb, int buf) {
        uint32_t base = sb + 65536 + buf * 65536;
#pragma unroll
        for (int i = 0; i < 16; i++) {
            int idx = tid + i * 256;
            int mat = idx >> 10, r = (idx >> 5) & 31, g = idx & 31;
            const char* src = kvsrc[mat] + (size_t)(kb * 32 + r) * 512 + g * 16;
            uint32_t dst = base + mat * 16384 + SWZ512(r * 512 + g * 16);
            asm volatile("cp.async.cg.shared.global [%0], [%1], 16;" :: "r"(dst), "l"(src));
        }
    };
    loadKV(0, 0);
    asm volatile("cp.async.commit_group;");

    float oAcc[16][4];
#pragma unroll
    for (int j = 0; j < 16; j++)
#pragma unroll
        for (int c = 0; c < 4; c++) oAcc[j][c] = 0.f;
    float m0 = -CUDART_INF_F, m1 = -CUDART_INF_F, l0 = 0.f, l1 = 0.f;
    int rowg0 = qi * 64 + pair * 16 + tq;

    for (int kb = 0; kb < nkb; kb++) {
        if (kb + 1 < nkb) {
            loadKV(kb + 1, (kb + 1) & 1);
            asm volatile("cp.async.commit_group;");
            asm volatile("cp.async.wait_group 1;");
        } else {
            asm volatile("cp.async.wait_group 0;");
        }
        __syncthreads();
        uint32_t kv = sb + 65536 + (kb & 1) * 65536;

        float sAcc[4][4];
#pragma unroll
        for (int j = 0; j < 4; j++)
#pragma unroll
            for (int c = 0; c < 4; c++) sAcc[j][c] = 0.f;
#pragma unroll
        for (int pass = 0; pass < 3; pass++) {
            uint32_t qb_ = sb + (pass == 2 ? 32768 : 0);
            uint32_t kb_ = kv + (pass == 1 ? 16384 : 0);
#pragma unroll
            for (int ks0 = 0; ks0 < 8; ks0++) {
                int ks = half * 8 + ks0;
                uint32_t qa[4];
                uint32_t qaddr = qb_ + SWZ512((pair * 16 + (lane & 15)) * 512
                                              + ks * 32 + (lane >> 4) * 16);
                asm volatile("ldmatrix.sync.aligned.m8n8.x4.shared.b16 {%0,%1,%2,%3}, [%4];"
                    : "=r"(qa[0]), "=r"(qa[1]), "=r"(qa[2]), "=r"(qa[3]) : "r"(qaddr));
                uint32_t bfr[4][2];
#pragma unroll
                for (int p = 0; p < 2; p++) {
                    int nr = p * 16 + (lane & 7) + ((lane >> 4) << 3);
                    uint32_t kaddr = kb_ + SWZ512(nr * 512 + ks * 32 + ((lane >> 3) & 1) * 16);
                    asm volatile("ldmatrix.sync.aligned.m8n8.x4.shared.b16 {%0,%1,%2,%3}, [%4];"
                        : "=r"(bfr[2*p][0]), "=r"(bfr[2*p][1]),
                          "=r"(bfr[2*p+1][0]), "=r"(bfr[2*p+1][1]) : "r"(kaddr));
                }
#pragma unroll
                for (int nj = 0; nj < 4; nj++)
                    asm volatile(
                        "mma.sync.aligned.m16n8k16.row.col.f32.bf16.bf16.f32 "
                        "{%0,%1,%2,%3}, {%4,%5,%6,%7}, {%8,%9}, {%0,%1,%2,%3};"
                        : "+f"(sAcc[nj][0]), "+f"(sAcc[nj][1]),
                          "+f"(sAcc[nj][2]), "+f"(sAcc[nj][3])
                        : "r"(qa[0]), "r"(qa[1]), "r"(qa[2]), "r"(qa[3]),
                          "r"(bfr[nj][0]), "r"(bfr[nj][1]));
            }
        }

        {
            float* my = Sbuf + pair * SB_PAIR + half * SB_HALF;
#pragma unroll
            for (int nj = 0; nj < 4; nj++)
#pragma unroll
                for (int c = 0; c < 4; c++)
                    my[(tq + (c >> 1) * 8) * 36 + nj * 8 + tr * 2 + (c & 1)] = sAcc[nj][c];
        }
        __syncthreads();
        {
            const float* b0 = Sbuf + pair * SB_PAIR;
            const float* b1 = b0 + SB_HALF;
#pragma unroll
            for (int nj = 0; nj < 4; nj++)
#pragma unroll
                for (int c = 0; c < 4; c++) {
                    int ix = (tq + (c >> 1) * 8) * 36 + nj * 8 + tr * 2 + (c & 1);
                    sAcc[nj][c] = b0[ix] + b1[ix];
                }
        }

        float mloc0 = -CUDART_INF_F, mloc1 = -CUDART_INF_F;
#pragma unroll
        for (int nj = 0; nj < 4; nj++)
#pragma unroll
            for (int c = 0; c < 4; c++) {
                float sv = sAcc[nj][c] * 0.0625f;
                int col = kb * 32 + nj * 8 + tr * 2 + (c & 1);
                int rg = rowg0 + ((c >> 1) << 3);
                if (col > rg) sv = -1e9f;
                sAcc[nj][c] = sv;
                if (c < 2) mloc0 = fmaxf(mloc0, sv);
                else       mloc1 = fmaxf(mloc1, sv);
            }
        mloc0 = fmaxf(mloc0, __shfl_xor_sync(0xffffffffu, mloc0, 1));
        mloc0 = fmaxf(mloc0, __shfl_xor_sync(0xffffffffu, mloc0, 2));
        mloc1 = fmaxf(mloc1, __shfl_xor_sync(0xffffffffu, mloc1, 1));
        mloc1 = fmaxf(mloc1, __shfl_xor_sync(0xffffffffu, mloc1, 2));
        float mn0 = fmaxf(m0, mloc0), mn1 = fmaxf(m1, mloc1);
        float f0 = __expf(m0 - mn0), f1 = __expf(m1 - mn1);
        m0 = mn0; m1 = mn1;
        float rs0 = 0.f, rs1 = 0.f;
#pragma unroll
        for (int nj = 0; nj < 4; nj++)
#pragma unroll
            for (int c = 0; c < 4; c++) {
                float p = __expf(sAcc[nj][c] - (c < 2 ? mn0 : mn1));
                sAcc[nj][c] = p;
                if (c < 2) rs0 += p; else rs1 += p;
            }
        rs0 += __shfl_xor_sync(0xffffffffu, rs0, 1);
        rs0 += __shfl_xor_sync(0xffffffffu, rs0, 2);
        rs1 += __shfl_xor_sync(0xffffffffu, rs1, 1);
        rs1 += __shfl_xor_sync(0xffffffffu, rs1, 2);
        l0 = l0 * f0 + rs0;
        l1 = l1 * f1 + rs1;
#pragma unroll
        for (int j = 0; j < 16; j++) {
            oAcc[j][0] *= f0; oAcc[j][1] *= f0;
            oAcc[j][2] *= f1; oAcc[j][3] *= f1;
        }

        uint32_t phi[2][4], plo[2][4];
#pragma unroll
        for (int ks2 = 0; ks2 < 2; ks2++) {
            int nb = ks2 * 2;
#pragma unroll
            for (int q = 0; q < 2; q++) {
                float a0 = sAcc[nb][2*q], a1 = sAcc[nb][2*q+1];
                float b0 = sAcc[nb+1][2*q], b1 = sAcc[nb+1][2*q+1];
                phi[ks2][q]     = packbf(a0, a1);
                phi[ks2][q + 2] = packbf(b0, b1);
                float a0h = __bfloat162float(__float2bfloat16_rn(a0));
                float a1h = __bfloat162float(__float2bfloat16_rn(a1));
                float b0h = __bfloat162float(__float2bfloat16_rn(b0));
                float b1h = __bfloat162float(__float2bfloat16_rn(b1));
                plo[ks2][q]     = packbf(a0 - a0h, a1 - a1h);
                plo[ks2][q + 2] = packbf(b0 - b0h, b1 - b1h);
            }
        }

        uint32_t vbh = kv + 32768, vbl = kv + 49152;
#pragma unroll
        for (int ks2 = 0; ks2 < 2; ks2++) {
#pragma unroll
            for (int j = 0; j < 16; j++) {
                int nj = half * 16 + j;
                uint32_t off = SWZ512((ks2 * 16 + (lane & 15)) * 512 + nj * 16);
                uint32_t vh0, vh1, vl0, vl1;
                asm volatile("ldmatrix.sync.aligned.m8n8.x2.trans.shared.b16 {%0,%1}, [%2];"
                    : "=r"(vh0), "=r"(vh1) : "r"(vbh + off));
                asm volatile("ldmatrix.sync.aligned.m8n8.x2.trans.shared.b16 {%0,%1}, [%2];"
                    : "=r"(vl0), "=r"(vl1) : "r"(vbl + off));
                asm volatile(
                    "mma.sync.aligned.m16n8k16.row.col.f32.bf16.bf16.f32 "
                    "{%0,%1,%2,%3}, {%4,%5,%6,%7}, {%8,%9}, {%0,%1,%2,%3};"
                    : "+f"(oAcc[j][0]), "+f"(oAcc[j][1]), "+f"(oAcc[j][2]), "+f"(oAcc[j][3])
                    : "r"(phi[ks2][0]), "r"(phi[ks2][1]), "r"(phi[ks2][2]), "r"(phi[ks2][3]),
                      "r"(vh0), "r"(vh1));
                asm volatile(
                    "mma.sync.aligned.m16n8k16.row.col.f32.bf16.bf16.f32 "
                    "{%0,%1,%2,%3}, {%4,%5,%6,%7}, {%8,%9}, {%0,%1,%2,%3};"
                    : "+f"(oAcc[j][0]), "+f"(oAcc[j][1]), "+f"(oAcc[j][2]), "+f"(oAcc[j][3])
                    : "r"(plo[ks2][0]), "r"(plo[ks2][1]), "r"(plo[ks2][2]), "r"(plo[ks2][3]),
                      "r"(vh0), "r"(vh1));
                asm volatile(
                    "mma.sync.aligned.m16n8k16.row.col.f32.bf16.bf16.f32 "
                    "{%0,%1,%2,%3}, {%4,%5,%6,%7}, {%8,%9}, {%0,%1,%2,%3};"
                    : "+f"(oAcc[j][0]), "+f"(oAcc[j][1]), "+f"(oAcc[j][2]), "+f"(oAcc[j][3])
                    : "r"(phi[ks2][0]), "r"(phi[ks2][1]), "r"(phi[ks2][2]), "r"(phi[ks2][3]),
                      "r"(vl0), "r"(vl1));
            }
        }
        __syncthreads();
    }

    float il0 = 1.0f / l0, il1 = 1.0f / l1;
    int hoff = head * HD;
    int r0 = qi * 64 + pair * 16 + tq;
    float* outp = (half == 0) ? outr : outi;
#pragma unroll
    for (int j = 0; j < 16; j++) {
        int col = j * 8 + tr * 2;
        float2 a = make_float2(oAcc[j][0] * il0, oAcc[j][1] * il0);
        float2 b = make_float2(oAcc[j][2] * il1, oAcc[j][3] * il1);
        *(float2*)(outp + (size_t)r0 * HH + hoff + col) = a;
        *(float2*)(outp + (size_t)(r0 + 8) * HH + hoff + col) = b;
    }
}

// ======================= launch =======================
extern "C" void kernel_launch(void* const* d_in, const int* in_sizes, int n_in,
                              void* d_out, int out_size) {
    const float* hr   = (const float*)d_in[0];
    const float* hi   = (const float*)d_in[1];
    const int*   pos  = (const int*)d_in[2];
    float* out = (float*)d_out;

    __nv_bfloat16 *nr, *ni, *wsp, *qhi, *qlo, *khi, *klo, *vhi, *vlo;
    float *is1, *is2, *is3, *is4, *ar, *ai;
    cudaGetSymbolAddress((void**)&nr,  g_nr);
    cudaGetSymbolAddress((void**)&ni,  g_ni);
    cudaGetSymbolAddress((void**)&is1, g_invs1);
    cudaGetSymbolAddress((void**)&is2, g_invs2);
    cudaGetSymbolAddress((void**)&is3, g_invs3);
    cudaGetSymbolAddress((void**)&is4, g_invs4);
    cudaGetSymbolAddress((void**)&wsp, g_wsp);
    cudaGetSymbolAddress((void**)&ar,  g_ar);
    cudaGetSymbolAddress((void**)&ai,  g_ai);
    cudaGetSymbolAddress((void**)&qhi, g_qhi);
    cudaGetSymbolAddress((void**)&qlo, g_qlo);
    cudaGetSymbolAddress((void**)&khi, g_khi);
    cudaGetSymbolAddress((void**)&klo, g_klo);
    cudaGetSymbolAddress((void**)&vhi, g_vhi);
    cudaGetSymbolAddress((void**)&vlo, g_vlo);
    __nv_bfloat16* ws[16];
    for (int i = 0; i < 16; i++) ws[i] = wsp + (size_t)i * HH * HH;

    // ---- prep
    QuantArgs qa;
    qa.x[0] = hr; qa.x[1] = hi;
    qa.q[0] = nr; qa.q[1] = ni;
    qa.invs[0] = is1; qa.invs[1] = is2;
    rowquant_bf16_kernel<<<dim3(TT, 2), 256>>>(qa);

    cossin_kernel<<<(TT * HD) / 256, 256>>>(pos);

    SplitArgs sa;
    for (int w = 0; w < 8; w++) sa.w[w] = (const float*)d_in[3 + w];
    sa.base = wsp;
    split_kernel<<<dim3((HH * HH) / 2048, 8), 256>>>(sa);

    // ---- QKV: 3 complex-paired tasks, merged-level chunks, fused rope+split epilogue
    cudaFuncSetAttribute(gemm_cplx, cudaFuncAttributeMaxDynamicSharedMemorySize, GSM);
    CTasks tq;
    tq.t[0] = {ws[0], ws[1], ws[2],  ws[3],  is1, is2, qhi, qlo, nullptr, nullptr, 1};
    tq.t[1] = {ws[4], ws[5], ws[6],  ws[7],  is1, is2, khi, klo, nullptr, nullptr, 1};
    tq.t[2] = {ws[8], ws[9], ws[10], ws[11], is1, is2, vhi, vlo, nullptr, nullptr, 0};
    gemm_cplx<<<dim3(HH / 128, TT / 128, 3), 256, GSM>>>(nr, ni, tq);

    // ---- flash attention (8 warps)
    cudaFuncSetAttribute(flash_mma, cudaFuncAttributeMaxDynamicSharedMemorySize, FSMEM);
    flash_mma<<<dim3(TT / 64, NHEAD), 256, FSMEM>>>(qhi, qlo, khi, klo, vhi, vlo, ar, ai);

    // ---- output projection: one paired task, fp32 epilogue
    QuantArgs qb;
    qb.x[0] = ar; qb.x[1] = ai;
    qb.q[0] = nr; qb.q[1] = ni;
    qb.invs[0] = is3; qb.invs[1] = is4;
    rowquant_bf16_kernel<<<dim3(TT, 2), 256>>>(qb);

    CTasks to;
    to.t[0] = {ws[12], ws[13], ws[14], ws[15], is3, is4, nullptr, nullptr,
               out, out + (size_t)TT * HH, -1};
    to.t[1] = to.t[0];
    to.t[2] = to.t[0];
    gemm_cplx<<<dim3(HH / 128, TT / 128, 1), 256, GSM>>>(nr, ni, to);
}

// round 16
// speedup vs baseline: 1.2013x; 1.0167x over previous
#include <cuda_runtime.h>
#include <cuda_bf16.h>
#include <math_constants.h>
#include <cstdint>

#define TT 2048
#define HH 2048
#define NHEAD 16
#define HD 128
#define D2 256

// ======================= scratch (static device globals) =======================
__device__ __nv_bfloat16 g_nr[TT*HH];
__device__ __nv_bfloat16 g_ni[TT*HH];
__device__ float g_invs1[TT];
__device__ float g_invs2[TT];
__device__ float g_invs3[TT];
__device__ float g_invs4[TT];
__device__ __nv_bfloat16 g_wsp[16][HH*HH];
__device__ float g_ar[TT*HH];
__device__ float g_ai[TT*HH];
__device__ float g_cos[TT*HD];
__device__ float g_sin[TT*HD];
__device__ __nv_bfloat16 g_qhi[NHEAD*TT*D2];
__device__ __nv_bfloat16 g_qlo[NHEAD*TT*D2];
__device__ __nv_bfloat16 g_khi[NHEAD*TT*D2];
__device__ __nv_bfloat16 g_klo[NHEAD*TT*D2];
__device__ __nv_bfloat16 g_vhi[NHEAD*TT*D2];
__device__ __nv_bfloat16 g_vlo[NHEAD*TT*D2];

// ======================= helpers =======================
__device__ __forceinline__ uint32_t smem_u32(const void* p) {
    uint32_t a;
    asm("{ .reg .u64 t; cvta.to.shared.u64 t, %1; cvt.u32.u64 %0, t; }" : "=r"(a) : "l"(p));
    return a;
}
#define SWZ128(b) ((b) ^ (((b) >> 3) & 0x70))
#define SWZ512(b) ((b) ^ (((b) >> 5) & 0x70))

__device__ __forceinline__ uint32_t packbf(float a, float b) {
    __nv_bfloat162 t = __floats2bfloat162_rn(a, b);
    return *(uint32_t*)&t;
}

// ======================= prep kernels =======================
struct QuantArgs {
    const float* x[2];
    __nv_bfloat16* q[2];
    float* invs[2];
};

__global__ void rowquant_bf16_kernel(QuantArgs a) {
    __shared__ float red[256];
    int sel = blockIdx.y;
    int row = blockIdx.x;
    int tid = threadIdx.x;
    const float* xr = a.x[sel] + (size_t)row * HH + tid * 8;
    float4 v0 = *(const float4*)xr;
    float4 v1 = *(const float4*)(xr + 4);
    float e[8] = {v0.x, v0.y, v0.z, v0.w, v1.x, v1.y, v1.z, v1.w};
    float m = 0.f;
#pragma unroll
    for (int j = 0; j < 8; j++) m = fmaxf(m, fabsf(e[j]));
    red[tid] = m;
    __syncthreads();
    for (int s = 128; s > 0; s >>= 1) {
        if (tid < s) red[tid] = fmaxf(red[tid], red[tid + s]);
        __syncthreads();
    }
    float scale = 127.0f / fmaxf(red[0], 1e-5f);
    if (tid == 0) a.invs[sel][row] = 1.0f / scale;
    __nv_bfloat16 q[8];
#pragma unroll
    for (int j = 0; j < 8; j++) {
        float v = rintf(e[j] * scale);
        v = fminf(fmaxf(v, -128.f), 127.f);
        q[j] = __float2bfloat16_rn(v);
    }
    *(uint4*)(a.q[sel] + (size_t)row * HH + tid * 8) = *(uint4*)q;
}

struct SplitArgs { const float* w[8]; __nv_bfloat16* base; };

__global__ void split_kernel(SplitArgs a) {
    int wsel = blockIdx.y;
    size_t i = ((size_t)blockIdx.x * 256 + threadIdx.x) * 8;
    const float* w = a.w[wsel] + i;
    float4 v0 = *(const float4*)w;
    float4 v1 = *(const float4*)(w + 4);
    float vv[8] = {v0.x, v0.y, v0.z, v0.w, v1.x, v1.y, v1.z, v1.w};
    __nv_bfloat16 h[8], l[8];
#pragma unroll
    for (int j = 0; j < 8; j++) {
        h[j] = __float2bfloat16_rn(vv[j]);
        l[j] = __float2bfloat16_rn(vv[j] - __bfloat162float(h[j]));
    }
    __nv_bfloat16* hi = a.base + (size_t)(2 * wsel) * HH * HH + i;
    __nv_bfloat16* lo = a.base + (size_t)(2 * wsel + 1) * HH * HH + i;
    *(uint4*)hi = *(uint4*)h;
    *(uint4*)lo = *(uint4*)l;
}

// fp32 chain — matches XLA's fp32-rounded angle + cos/sin (proven; do NOT "improve")
__global__ void cossin_kernel(const int* __restrict__ pos) {
    int idx = blockIdx.x * 256 + threadIdx.x;
    if (idx >= TT * HD) return;
    int t = idx / HD, d = idx % HD;
    float invf = 1.0f / powf(10000.0f, (float)d / (float)HD);
    float f = (float)pos[t] * invf;
    g_cos[idx] = __bfloat162float(__float2bfloat16(cosf(f)));
    g_sin[idx] = __bfloat162float(__float2bfloat16(sinf(f)));
}

// ======================= complex-paired GEMM, merged-level 80K chunks (R15-proven) =======================
#define STAGES 2
#define NCHUNK 64
#define STG_SZ 81920
#define GSM    (STAGES * STG_SZ)   // 163840

struct CTask {
    const __nv_bfloat16 *Wrhi, *Wrlo, *Wihi, *Wilo;
    const float *invs1, *invs2;
    __nv_bfloat16 *ghi, *glo;
    float *fr, *fi;
    int mode;   // 1 = rope+split, 0 = split, -1 = fp32 pair write
};
struct CTasks { CTask t[3]; };

__device__ __forceinline__ void load_chunk5(uint32_t st,
                                            const __nv_bfloat16* Aseg,
                                            const __nv_bfloat16* W0,
                                            const __nv_bfloat16* W1,
                                            const __nv_bfloat16* W2,
                                            const __nv_bfloat16* W3,
                                            int m0, int n0, int kc, int tid) {
    const char* ag = (const char*)(Aseg + (size_t)m0 * HH + kc * 64);
    const char* wg[4] = {
        (const char*)(W0 + (size_t)n0 * HH + kc * 64),
        (const char*)(W1 + (size_t)n0 * HH + kc * 64),
        (const char*)(W2 + (size_t)n0 * HH + kc * 64),
        (const char*)(W3 + (size_t)n0 * HH + kc * 64)};
#pragma unroll
    for (int i = 0; i < 4; i++) {
        int idx = tid + i * 256;
        int r = idx >> 3, g = idx & 7;
        uint32_t so = st + SWZ128(r * 128 + g * 16);
        asm volatile("cp.async.cg.shared.global [%0], [%1], 16;"
                     :: "r"(so), "l"(ag + (size_t)r * 4096 + g * 16));
    }
#pragma unroll
    for (int w = 0; w < 4; w++) {
        uint32_t base = st + 16384 * (w + 1);
#pragma unroll
        for (int i = 0; i < 4; i++) {
            int idx = tid + i * 256;
            int r = idx >> 3, g = idx & 7;
            uint32_t so = base + SWZ128(r * 128 + g * 16);
            asm volatile("cp.async.cg.shared.global [%0], [%1], 16;"
                         :: "r"(so), "l"(wg[w] + (size_t)r * 4096 + g * 16));
        }
    }
}

__device__ __forceinline__ void compute_chunk5(uint32_t st,
                                               int warp_m, int warp_n, int lane,
                                               float (&accr)[4][4][4], float (&acci)[4][4][4]) {
#pragma unroll
    for (int ks = 0; ks < 4; ks++) {
        uint32_t af[4][4];
#pragma unroll
        for (int mi = 0; mi < 4; mi++) {
            int r = warp_m * 64 + mi * 16 + (lane & 15);
            int cb = ks * 32 + (lane >> 4) * 16;
            uint32_t ad = st + SWZ128(r * 128 + cb);
            asm volatile("ldmatrix.sync.aligned.m8n8.x4.shared.b16 {%0,%1,%2,%3}, [%4];"
                : "=r"(af[mi][0]), "=r"(af[mi][1]), "=r"(af[mi][2]), "=r"(af[mi][3])
                : "r"(ad));
        }
#pragma unroll
        for (int lvl = 0; lvl < 2; lvl++) {
#pragma unroll
            for (int which = 0; which < 2; which++) {
                uint32_t sb = st + 16384 * (1 + which * 2 + lvl);
                uint32_t bf[4][2];
#pragma unroll
                for (int p = 0; p < 2; p++) {
                    int nr_ = warp_n * 32 + p * 16 + (lane & 7) + ((lane >> 4) << 3);
                    int cb = ks * 32 + ((lane >> 3) & 1) * 16;
                    uint32_t bd = sb + SWZ128(nr_ * 128 + cb);
                    asm volatile("ldmatrix.sync.aligned.m8n8.x4.shared.b16 {%0,%1,%2,%3}, [%4];"
                        : "=r"(bf[2*p][0]), "=r"(bf[2*p][1]),
                          "=r"(bf[2*p+1][0]), "=r"(bf[2*p+1][1])
                        : "r"(bd));
                }
                if (which == 0) {
#pragma unroll
                    for (int mi = 0; mi < 4; mi++)
#pragma unroll
                        for (int nj = 0; nj < 4; nj++)
                            asm volatile(
                                "mma.sync.aligned.m16n8k16.row.col.f32.bf16.bf16.f32 "
                                "{%0,%1,%2,%3}, {%4,%5,%6,%7}, {%8,%9}, {%0,%1,%2,%3};"
                                : "+f"(accr[mi][nj][0]), "+f"(accr[mi][nj][1]),
                                  "+f"(accr[mi][nj][2]), "+f"(accr[mi][nj][3])
                                : "r"(af[mi][0]), "r"(af[mi][1]), "r"(af[mi][2]), "r"(af[mi][3]),
                                  "r"(bf[nj][0]), "r"(bf[nj][1]));
                } else {
#pragma unroll
                    for (int mi = 0; mi < 4; mi++)
#pragma unroll
                        for (int nj = 0; nj < 4; nj++)
                            asm volatile(
                                "mma.sync.aligned.m16n8k16.row.col.f32.bf16.bf16.f32 "
                                "{%0,%1,%2,%3}, {%4,%5,%6,%7}, {%8,%9}, {%0,%1,%2,%3};"
                                : "+f"(acci[mi][nj][0]), "+f"(acci[mi][nj][1]),
                                  "+f"(acci[mi][nj][2]), "+f"(acci[mi][nj][3])
                                : "r"(af[mi][0]), "r"(af[mi][1]), "r"(af[mi][2]), "r"(af[mi][3]),
                                  "r"(bf[nj][0]), "r"(bf[nj][1]));
                }
            }
        }
    }
}

__global__ __launch_bounds__(256, 1) void gemm_cplx(
    const __nv_bfloat16* __restrict__ A1, const __nv_bfloat16* __restrict__ A2,
    CTasks tasks) {
    extern __shared__ char smem[];
    uint32_t sbase = smem_u32(smem);
    const CTask tk = tasks.t[blockIdx.z];
    int tid = threadIdx.x;
    int wid = tid >> 5, lane = tid & 31;
    int warp_m = wid >> 2, warp_n = wid & 3;
    int m0 = blockIdx.y * 128, n0 = blockIdx.x * 128;
    int tq = lane >> 2, tr = lane & 3;

    float accr[4][4][4], acci[4][4][4];
#pragma unroll
    for (int a = 0; a < 4; a++)
#pragma unroll
        for (int b = 0; b < 4; b++)
#pragma unroll
            for (int c = 0; c < 4; c++) { accr[a][b][c] = 0.f; acci[a][b][c] = 0.f; }

    auto segload = [&](int cn, uint32_t st) {
        if (cn < 32)
            load_chunk5(st, A1, tk.Wrhi, tk.Wrlo, tk.Wihi, tk.Wilo, m0, n0, cn & 31, tid);
        else
            load_chunk5(st, A2, tk.Wihi, tk.Wilo, tk.Wrhi, tk.Wrlo, m0, n0, cn & 31, tid);
        asm volatile("cp.async.commit_group;");
    };

    segload(0, sbase);
    segload(1, sbase + STG_SZ);

    for (int c = 0; c < NCHUNK; c++) {
        uint32_t st = sbase + (c & 1) * STG_SZ;
        if (c < NCHUNK - 1) asm volatile("cp.async.wait_group 1;");
        else                asm volatile("cp.async.wait_group 0;");
        __syncthreads();

        compute_chunk5(st, warp_m, warp_n, lane, accr, acci);

        if (c == 31) {
#pragma unroll
            for (int mi = 0; mi < 4; mi++)
#pragma unroll
                for (int h = 0; h < 2; h++) {
                    int row = m0 + warp_m * 64 + mi * 16 + tq + h * 8;
                    float ratio = tk.invs1[row] / tk.invs2[row];
#pragma unroll
                    for (int nj = 0; nj < 4; nj++) {
                        accr[mi][nj][2*h]     *=  ratio;
                        accr[mi][nj][2*h + 1] *=  ratio;
                        acci[mi][nj][2*h]     *= -ratio;
                        acci[mi][nj][2*h + 1] *= -ratio;
                    }
                }
        }
        __syncthreads();

        int cn = c + STAGES;
        if (cn < NCHUNK) segload(cn, st);
    }

    int head = n0 >> 7;
#pragma unroll
    for (int mi = 0; mi < 4; mi++) {
#pragma unroll
        for (int h = 0; h < 2; h++) {
            int row = m0 + warp_m * 64 + mi * 16 + tq + h * 8;
            float fsr = tk.invs2[row];
            float fsi = -fsr;
            if (tk.mode < 0) {
                float* fr = tk.fr + (size_t)row * HH + n0 + warp_n * 32;
                float* fi = tk.fi + (size_t)row * HH + n0 + warp_n * 32;
#pragma unroll
                for (int nj = 0; nj < 4; nj++) {
                    float2 o1, o2;
                    o1.x = fsr * accr[mi][nj][2*h];
                    o1.y = fsr * accr[mi][nj][2*h + 1];
                    o2.x = fsi * acci[mi][nj][2*h];
                    o2.y = fsi * acci[mi][nj][2*h + 1];
                    *(float2*)(fr + nj * 8 + 2 * tr) = o1;
                    *(float2*)(fi + nj * 8 + 2 * tr) = o2;
                }
            } else {
                size_t base = ((size_t)head * TT + row) * D2;
#pragma unroll
                for (int nj = 0; nj < 4; nj++) {
                    int d = warp_n * 32 + nj * 8 + 2 * tr;
                    float rx = fsr * accr[mi][nj][2*h];
                    float ry = fsr * accr[mi][nj][2*h + 1];
                    float ix = fsi * acci[mi][nj][2*h];
                    float iy = fsi * acci[mi][nj][2*h + 1];
                    if (tk.mode == 1) {
                        float2 c2 = *(const float2*)&g_cos[row * HD + d];
                        float2 s2 = *(const float2*)&g_sin[row * HD + d];
                        float rr0 = rx * c2.x - ix * s2.x;
                        float ii0 = ix * c2.x + rx * s2.x;
                        float rr1 = ry * c2.y - iy * s2.y;
                        float ii1 = iy * c2.y + ry * s2.y;
                        rx = rr0; ry = rr1; ix = ii0; iy = ii1;
                    }
                    __nv_bfloat16 rh0 = __float2bfloat16_rn(rx);
                    __nv_bfloat16 rh1 = __float2bfloat16_rn(ry);
                    __nv_bfloat16 ih0 = __float2bfloat16_rn(ix);
                    __nv_bfloat16 ih1 = __float2bfloat16_rn(iy);
                    *(uint32_t*)(tk.ghi + base + d) =
                        (uint32_t)*(uint16_t*)&rh0 | ((uint32_t)*(uint16_t*)&rh1 << 16);
                    *(uint32_t*)(tk.glo + base + d) =
                        packbf(rx - __bfloat162float(rh0), ry - __bfloat162float(rh1));
                    *(uint32_t*)(tk.ghi + base + 128 + d) =
                        (uint32_t)*(uint16_t*)&ih0 | ((uint32_t)*(uint16_t*)&ih1 << 16);
                    *(uint32_t*)(tk.glo + base + 128 + d) =
                        packbf(ix - __bfloat162float(ih0), iy - __bfloat162float(ih1));
                }
            }
        }
    }
}

// ======================= HMMA flash attention — Q fragments register-resident =======================
#define SB_OFF   196608
#define SB_HALF  576
#define SB_PAIR  1152
#define FSMEM    (196608 + 4 * SB_PAIR * 4)   // 215040

__global__ __launch_bounds__(256, 1) void flash_mma(
    const __nv_bfloat16* __restrict__ qhi, const __nv_bfloat16* __restrict__ qlo,
    const __nv_bfloat16* __restrict__ khi, const __nv_bfloat16* __restrict__ klo,
    const __nv_bfloat16* __restrict__ vhi, const __nv_bfloat16* __restrict__ vlo,
    float* __restrict__ outr, float* __restrict__ outi) {
    extern __shared__ char sm[];
    uint32_t sb = smem_u32(sm);
    float* Sbuf = (float*)(sm + SB_OFF);
    int head = blockIdx.y;
    int qi = (int)gridDim.x - 1 - (int)blockIdx.x;
    int tid = threadIdx.x;
    int warp = tid >> 5, lane = tid & 31;
    int pair = warp >> 1, half = warp & 1;
    int tq = lane >> 2, tr = lane & 3;
    size_t hbase = (size_t)head * TT * D2;

    // Q tile load (hi+lo) — committed with KV0 in group 0
    {
        const char* s0 = (const char*)(qhi + hbase + (size_t)qi * 64 * D2);
        const char* s1 = (const char*)(qlo + hbase + (size_t)qi * 64 * D2);
#pragma unroll
        for (int i = 0; i < 16; i++) {
            int idx = tid + i * 256;
            int mat = idx >> 11, r = (idx >> 5) & 63, g = idx & 31;
            const char* src = (mat == 0 ? s0 : s1) + (size_t)r * 512 + g * 16;
            uint32_t dst = sb + mat * 32768 + SWZ512(r * 512 + g * 16);
            asm volatile("cp.async.cg.shared.global [%0], [%1], 16;" :: "r"(dst), "l"(src));
        }
    }

    int nkb = 2 * (qi + 1);
    const char* kvsrc[4] = {(const char*)(khi + hbase), (const char*)(klo + hbase),
                            (const char*)(vhi + hbase), (const char*)(vlo + hbase)};
    auto loadKV = [&](int kb, int buf) {
        uint32_t base = sb + 65536 + buf * 65536;
#pragma unroll
        for (int i = 0; i < 16; i++) {
            int idx = tid + i * 256;
            int mat = idx >> 10, r = (idx >> 5) & 31, g = idx & 31;
            const char* src = kvsrc[mat] + (size_t)(kb * 32 + r) * 512 + g * 16;
            uint32_t dst = base + mat * 16384 + SWZ512(r * 512 + g * 16);
            asm volatile("cp.async.cg.shared.global [%0], [%1], 16;" :: "r"(dst), "l"(src));
        }
    };
    loadKV(0, 0);
    asm volatile("cp.async.commit_group;");

    // wait for Q + KV0, then hoist Q fragments into registers (fixed all kernel)
    asm volatile("cp.async.wait_group 0;");
    __syncthreads();
    uint32_t qhiF[8][4], qloF[8][4];
#pragma unroll
    for (int ks0 = 0; ks0 < 8; ks0++) {
        int ks = half * 8 + ks0;
        uint32_t off = SWZ512((pair * 16 + (lane & 15)) * 512 + ks * 32 + (lane >> 4) * 16);
        asm volatile("ldmatrix.sync.aligned.m8n8.x4.shared.b16 {%0,%1,%2,%3}, [%4];"
            : "=r"(qhiF[ks0][0]), "=r"(qhiF[ks0][1]), "=r"(qhiF[ks0][2]), "=r"(qhiF[ks0][3])
            : "r"(sb + off));
        asm volatile("ldmatrix.sync.aligned.m8n8.x4.shared.b16 {%0,%1,%2,%3}, [%4];"
            : "=r"(qloF[ks0][0]), "=r"(qloF[ks0][1]), "=r"(qloF[ks0][2]), "=r"(qloF[ks0][3])
            : "r"(sb + 32768 + off));
    }

    float oAcc[16][4];
#pragma unroll
    for (int j = 0; j < 16; j++)
#pragma unroll
        for (int c = 0; c < 4; c++) oAcc[j][c] = 0.f;
    float m0 = -CUDART_INF_F, m1 = -CUDART_INF_F, l0 = 0.f, l1 = 0.f;
    int rowg0 = qi * 64 + pair * 16 + tq;

    for (int kb = 0; kb < nkb; kb++) {
        if (kb + 1 < nkb) {
            loadKV(kb + 1, (kb + 1) & 1);
            asm volatile("cp.async.commit_group;");
        }
        if (kb > 0) {
            if (kb + 1 < nkb) asm volatile("cp.async.wait_group 1;");
            else              asm volatile("cp.async.wait_group 0;");
            __syncthreads();
        }
        uint32_t kv = sb + 65536 + (kb & 1) * 65536;

        // ---- S: per ks, share K-hi between qhi and qlo passes
        float sAcc[4][4];
#pragma unroll
        for (int j = 0; j < 4; j++)
#pragma unroll
            for (int c = 0; c < 4; c++) sAcc[j][c] = 0.f;
#pragma unroll
        for (int ks0 = 0; ks0 < 8; ks0++) {
            int ks = half * 8 + ks0;
            uint32_t bh[4][2], bl[4][2];
#pragma unroll
            for (int p = 0; p < 2; p++) {
                int nr = p * 16 + (lane & 7) + ((lane >> 4) << 3);
                uint32_t ko = SWZ512(nr * 512 + ks * 32 + ((lane >> 3) & 1) * 16);
                asm volatile("ldmatrix.sync.aligned.m8n8.x4.shared.b16 {%0,%1,%2,%3}, [%4];"
                    : "=r"(bh[2*p][0]), "=r"(bh[2*p][1]), "=r"(bh[2*p+1][0]), "=r"(bh[2*p+1][1])
                    : "r"(kv + ko));
                asm volatile("ldmatrix.sync.aligned.m8n8.x4.shared.b16 {%0,%1,%2,%3}, [%4];"
                    : "=r"(bl[2*p][0]), "=r"(bl[2*p][1]), "=r"(bl[2*p+1][0]), "=r"(bl[2*p+1][1])
                    : "r"(kv + 16384 + ko));
            }
#pragma unroll
            for (int nj = 0; nj < 4; nj++) {
                asm volatile(
                    "mma.sync.aligned.m16n8k16.row.col.f32.bf16.bf16.f32 "
                    "{%0,%1,%2,%3}, {%4,%5,%6,%7}, {%8,%9}, {%0,%1,%2,%3};"
                    : "+f"(sAcc[nj][0]), "+f"(sAcc[nj][1]), "+f"(sAcc[nj][2]), "+f"(sAcc[nj][3])
                    : "r"(qhiF[ks0][0]), "r"(qhiF[ks0][1]), "r"(qhiF[ks0][2]), "r"(qhiF[ks0][3]),
                      "r"(bh[nj][0]), "r"(bh[nj][1]));
                asm volatile(
                    "mma.sync.aligned.m16n8k16.row.col.f32.bf16.bf16.f32 "
                    "{%0,%1,%2,%3}, {%4,%5,%6,%7}, {%8,%9}, {%0,%1,%2,%3};"
                    : "+f"(sAcc[nj][0]), "+f"(sAcc[nj][1]), "+f"(sAcc[nj][2]), "+f"(sAcc[nj][3])
                    : "r"(qloF[ks0][0]), "r"(qloF[ks0][1]), "r"(qloF[ks0][2]), "r"(qloF[ks0][3]),
                      "r"(bh[nj][0]), "r"(bh[nj][1]));
                asm volatile(
                    "mma.sync.aligned.m16n8k16.row.col.f32.bf16.bf16.f32 "
                    "{%0,%1,%2,%3}, {%4,%5,%6,%7}, {%8,%9}, {%0,%1,%2,%3};"
                    : "+f"(sAcc[nj][0]), "+f"(sAcc[nj][1]), "+f"(sAcc[nj][2]), "+f"(sAcc[nj][3])
                    : "r"(qhiF[ks0][0]), "r"(qhiF[ks0][1]), "r"(qhiF[ks0][2]), "r"(qhiF[ks0][3]),
                      "r"(bl[nj][0]), "r"(bl[nj][1]));
            }
        }

        // exchange partial S through smem, sum the pair's halves
        {
            float* my = Sbuf + pair * SB_PAIR + half * SB_HALF;
#pragma unroll
            for (int nj = 0; nj < 4; nj++)
#pragma unroll
                for (int c = 0; c < 4; c++)
                    my[(tq + (c >> 1) * 8) * 36 + nj * 8 + tr * 2 + (c & 1)] = sAcc[nj][c];
        }
        __syncthreads();
        {
            const float* b0 = Sbuf + pair * SB_PAIR;
            const float* b1 = b0 + SB_HALF;
#pragma unroll
            for (int nj = 0; nj < 4; nj++)
#pragma unroll
                for (int c = 0; c < 4; c++) {
                    int ix = (tq + (c >> 1) * 8) * 36 + nj * 8 + tr * 2 + (c & 1);
                    sAcc[nj][c] = b0[ix] + b1[ix];
                }
        }

        float mloc0 = -CUDART_INF_F, mloc1 = -CUDART_INF_F;
#pragma unroll
        for (int nj = 0; nj < 4; nj++)
#pragma unroll
            for (int c = 0; c < 4; c++) {
                float sv = sAcc[nj][c] * 0.0625f;
                int col = kb * 32 + nj * 8 + tr * 2 + (c & 1);
                int rg = rowg0 + ((c >> 1) << 3);
                if (col > rg) sv = -1e9f;
                sAcc[nj][c] = sv;
                if (c < 2) mloc0 = fmaxf(mloc0, sv);
                else       mloc1 = fmaxf(mloc1, sv);
            }
        mloc0 = fmaxf(mloc0, __shfl_xor_sync(0xffffffffu, mloc0, 1));
        mloc0 = fmaxf(mloc0, __shfl_xor_sync(0xffffffffu, mloc0, 2));
        mloc1 = fmaxf(mloc1, __shfl_xor_sync(0xffffffffu, mloc1, 1));
        mloc1 = fmaxf(mloc1, __shfl_xor_sync(0xffffffffu, mloc1, 2));
        float mn0 = fmaxf(m0, mloc0), mn1 = fmaxf(m1, mloc1);
        float f0 = __expf(m0 - mn0), f1 = __expf(m1 - mn1);
        m0 = mn0; m1 = mn1;
        float rs0 = 0.f, rs1 = 0.f;
#pragma unroll
        for (int nj = 0; nj < 4; nj++)
#pragma unroll
            for (int c = 0; c < 4; c++) {
                float p = __expf(sAcc[nj][c] - (c < 2 ? mn0 : mn1));
                sAcc[nj][c] = p;
                if (c < 2) rs0 += p; else rs1 += p;
            }
        rs0 += __shfl_xor_sync(0xffffffffu, rs0, 1);
        rs0 += __shfl_xor_sync(0xffffffffu, rs0, 2);
        rs1 += __shfl_xor_sync(0xffffffffu, rs1, 1);
        rs1 += __shfl_xor_sync(0xffffffffu, rs1, 2);
        l0 = l0 * f0 + rs0;
        l1 = l1 * f1 + rs1;
#pragma unroll
        for (int j = 0; j < 16; j++) {
            oAcc[j][0] *= f0; oAcc[j][1] *= f0;
            oAcc[j][2] *= f1; oAcc[j][3] *= f1;
        }

        uint32_t phi[2][4], plo[2][4];
#pragma unroll
        for (int ks2 = 0; ks2 < 2; ks2++) {
            int nb = ks2 * 2;
#pragma unroll
            for (int q = 0; q < 2; q++) {
                float a0 = sAcc[nb][2*q], a1 = sAcc[nb][2*q+1];
                float b0 = sAcc[nb+1][2*q], b1 = sAcc[nb+1][2*q+1];
                phi[ks2][q]     = packbf(a0, a1);
                phi[ks2][q + 2] = packbf(b0, b1);
                float a0h = __bfloat162float(__float2bfloat16_rn(a0));
                float a1h = __bfloat162float(__float2bfloat16_rn(a1));
                float b0h = __bfloat162float(__float2bfloat16_rn(b0));
                float b1h = __bfloat162float(__float2bfloat16_rn(b1));
                plo[ks2][q]     = packbf(a0 - a0h, a1 - a1h);
                plo[ks2][q + 2] = packbf(b0 - b0h, b1 - b1h);
            }
        }

        uint32_t vbh = kv + 32768, vbl = kv + 49152;
#pragma unroll
        for (int ks2 = 0; ks2 < 2; ks2++) {
#pragma unroll
            for (int j = 0; j < 16; j++) {
                int nj = half * 16 + j;
                uint32_t off = SWZ512((ks2 * 16 + (lane & 15)) * 512 + nj * 16);
                uint32_t vh0, vh1, vl0, vl1;
                asm volatile("ldmatrix.sync.aligned.m8n8.x2.trans.shared.b16 {%0,%1}, [%2];"
                    : "=r"(vh0), "=r"(vh1) : "r"(vbh + off));
                asm volatile("ldmatrix.sync.aligned.m8n8.x2.trans.shared.b16 {%0,%1}, [%2];"
                    : "=r"(vl0), "=r"(vl1) : "r"(vbl + off));
                asm volatile(
                    "mma.sync.aligned.m16n8k16.row.col.f32.bf16.bf16.f32 "
                    "{%0,%1,%2,%3}, {%4,%5,%6,%7}, {%8,%9}, {%0,%1,%2,%3};"
                    : "+f"(oAcc[j][0]), "+f"(oAcc[j][1]), "+f"(oAcc[j][2]), "+f"(oAcc[j][3])
                    : "r"(phi[ks2][0]), "r"(phi[ks2][1]), "r"(phi[ks2][2]), "r"(phi[ks2][3]),
                      "r"(vh0), "r"(vh1));
                asm volatile(
                    "mma.sync.aligned.m16n8k16.row.col.f32.bf16.bf16.f32 "
                    "{%0,%1,%2,%3}, {%4,%5,%6,%7}, {%8,%9}, {%0,%1,%2,%3};"
                    : "+f"(oAcc[j][0]), "+f"(oAcc[j][1]), "+f"(oAcc[j][2]), "+f"(oAcc[j][3])
                    : "r"(plo[ks2][0]), "r"(plo[ks2][1]), "r"(plo[ks2][2]), "r"(plo[ks2][3]),
                      "r"(vh0), "r"(vh1));
                asm volatile(
                    "mma.sync.aligned.m16n8k16.row.col.f32.bf16.bf16.f32 "
                    "{%0,%1,%2,%3}, {%4,%5,%6,%7}, {%8,%9}, {%0,%1,%2,%3};"
                    : "+f"(oAcc[j][0]), "+f"(oAcc[j][1]), "+f"(oAcc[j][2]), "+f"(oAcc[j][3])
                    : "r"(phi[ks2][0]), "r"(phi[ks2][1]), "r"(phi[ks2][2]), "r"(phi[ks2][3]),
                      "r"(vl0), "r"(vl1));
            }
        }
        __syncthreads();
    }

    float il0 = 1.0f / l0, il1 = 1.0f / l1;
    int hoff = head * HD;
    int r0 = qi * 64 + pair * 16 + tq;
    float* outp = (half == 0) ? outr : outi;
#pragma unroll
    for (int j = 0; j < 16; j++) {
        int col = j * 8 + tr * 2;
        float2 a = make_float2(oAcc[j][0] * il0, oAcc[j][1] * il0);
        float2 b = make_float2(oAcc[j][2] * il1, oAcc[j][3] * il1);
        *(float2*)(outp + (size_t)r0 * HH + hoff + col) = a;
        *(float2*)(outp + (size_t)(r0 + 8) * HH + hoff + col) = b;
    }
}

// ======================= launch =======================
extern "C" void kernel_launch(void* const* d_in, const int* in_sizes, int n_in,
                              void* d_out, int out_size) {
    const float* hr   = (const float*)d_in[0];
    const float* hi   = (const float*)d_in[1];
    const int*   pos  = (const int*)d_in[2];
    float* out = (float*)d_out;

    __nv_bfloat16 *nr, *ni, *wsp, *qhi, *qlo, *khi, *klo, *vhi, *vlo;
    float *is1, *is2, *is3, *is4, *ar, *ai;
    cudaGetSymbolAddress((void**)&nr,  g_nr);
    cudaGetSymbolAddress((void**)&ni,  g_ni);
    cudaGetSymbolAddress((void**)&is1, g_invs1);
    cudaGetSymbolAddress((void**)&is2, g_invs2);
    cudaGetSymbolAddress((void**)&is3, g_invs3);
    cudaGetSymbolAddress((void**)&is4, g_invs4);
    cudaGetSymbolAddress((void**)&wsp, g_wsp);
    cudaGetSymbolAddress((void**)&ar,  g_ar);
    cudaGetSymbolAddress((void**)&ai,  g_ai);
    cudaGetSymbolAddress((void**)&qhi, g_qhi);
    cudaGetSymbolAddress((void**)&qlo, g_qlo);
    cudaGetSymbolAddress((void**)&khi, g_khi);
    cudaGetSymbolAddress((void**)&klo, g_klo);
    cudaGetSymbolAddress((void**)&vhi, g_vhi);
    cudaGetSymbolAddress((void**)&vlo, g_vlo);
    __nv_bfloat16* ws[16];
    for (int i = 0; i < 16; i++) ws[i] = wsp + (size_t)i * HH * HH;

    // ---- prep
    QuantArgs qa;
    qa.x[0] = hr; qa.x[1] = hi;
    qa.q[0] = nr; qa.q[1] = ni;
    qa.invs[0] = is1; qa.invs[1] = is2;
    rowquant_bf16_kernel<<<dim3(TT, 2), 256>>>(qa);

    cossin_kernel<<<(TT * HD) / 256, 256>>>(pos);

    SplitArgs sa;
    for (int w = 0; w < 8; w++) sa.w[w] = (const float*)d_in[3 + w];
    sa.base = wsp;
    split_kernel<<<dim3((HH * HH) / 2048, 8), 256>>>(sa);

    // ---- QKV: 3 complex-paired tasks, merged-level chunks, fused rope+split epilogue
    cudaFuncSetAttribute(gemm_cplx, cudaFuncAttributeMaxDynamicSharedMemorySize, GSM);
    CTasks tq;
    tq.t[0] = {ws[0], ws[1], ws[2],  ws[3],  is1, is2, qhi, qlo, nullptr, nullptr, 1};
    tq.t[1] = {ws[4], ws[5], ws[6],  ws[7],  is1, is2, khi, klo, nullptr, nullptr, 1};
    tq.t[2] = {ws[8], ws[9], ws[10], ws[11], is1, is2, vhi, vlo, nullptr, nullptr, 0};
    gemm_cplx<<<dim3(HH / 128, TT / 128, 3), 256, GSM>>>(nr, ni, tq);

    // ---- flash attention (8 warps, Q register-resident)
    cudaFuncSetAttribute(flash_mma, cudaFuncAttributeMaxDynamicSharedMemorySize, FSMEM);
    flash_mma<<<dim3(TT / 64, NHEAD), 256, FSMEM>>>(qhi, qlo, khi, klo, vhi, vlo, ar, ai);

    // ---- output projection: one paired task, fp32 epilogue
    QuantArgs qb;
    qb.x[0] = ar; qb.x[1] = ai;
    qb.q[0] = nr; qb.q[1] = ni;
    qb.invs[0] = is3; qb.invs[1] = is4;
    rowquant_bf16_kernel<<<dim3(TT, 2), 256>>>(qb);

    CTasks to;
    to.t[0] = {ws[12], ws[13], ws[14], ws[15], is3, is4, nullptr, nullptr,
               out, out + (size_t)TT * HH, -1};
    to.t[1] = to.t[0];
    to.t[2] = to.t[0];
    gemm_cplx<<<dim3(HH / 128, TT / 128, 1), 256, GSM>>>(nr, ni, to);
}